// round 2
// baseline (speedup 1.0000x reference)
#include <cuda_runtime.h>
#include <cstdint>

// ---------------- shapes ----------------
#define BZ 64
#define LL 2048
#define DD 512
#define UU 512
#define AA 512
#define KK 64
#define VV 32000
#define EE 256
#define QW 7

// output layout in d_out: [out (64*32000)][ht (64*512)][attn (64*2048)]
#define OUT_OFF 0
#define HT_OFF  (BZ*VV)
#define ATTN_OFF (BZ*VV + BZ*UU)

// ---------------- scratch (device globals; no allocation allowed) ----------------
__device__ float g_F[BZ*LL*KK];          // conv output (64,2048,64)
__device__ float g_ha[BZ*AA];            // prev_hidden @ Wa
__device__ float g_logit[BZ*LL];         // attention logits
__device__ float g_ctxpart[8*BZ*DD];     // context split-L partials
__device__ float g_context[BZ*DD];
__device__ float g_eypart[32*BZ*EE];     // Ey split-K partials
__device__ float g_Ey[BZ*EE];
__device__ float g_ccz[BZ*UU];
__device__ float g_zt[BZ*UU];
__device__ float g_rt[BZ*UU];
__device__ float g_rh[BZ*UU];
__device__ float g_hcand[BZ*UU];
__device__ float g_ht[BZ*UU];
__device__ float g_oute[BZ*EE];
__device__ float g_vlogits[BZ*VV];       // pre-softmax vocab logits

// ---------------- conv1d SAME width-7 ----------------
__global__ void conv_kernel(const float* __restrict__ B, const float* __restrict__ Qk) {
    int idx = blockIdx.x * blockDim.x + threadIdx.x;
    if (idx >= BZ*LL*KK) return;
    int k = idx & (KK-1);
    int l = (idx >> 6) & (LL-1);
    int b = idx >> 17;
    float s = 0.f;
#pragma unroll
    for (int w = 0; w < QW; w++) {
        int ll2 = l + w - 3;
        if (ll2 >= 0 && ll2 < LL) s += B[b*LL + ll2] * Qk[w*KK + k];
    }
    g_F[idx] = s;
}

// ---------------- generic small GEMM: C(64xN) = act( sum_p A_p(64xK_p) @ B_p(K_p x N) + biases + addm ) ----------------
// grid.x = N/64, block = 256 threads. K_p multiples of 32.
__global__ void sgemm3_kernel(const float* __restrict__ A0, const float* __restrict__ B0, int K0, int ldb0,
                              const float* __restrict__ A1, const float* __restrict__ B1, int K1, int ldb1,
                              const float* __restrict__ A2, const float* __restrict__ B2, int K2, int ldb2,
                              const float* __restrict__ bias1, const float* __restrict__ bias2,
                              const float* __restrict__ addm,
                              float* __restrict__ C, int N, int act)
{
    __shared__ float As[64][33];
    __shared__ float Bs[32][64];
    int t = threadIdx.x;
    int tx = t & 15, ty = t >> 4;
    int n0 = blockIdx.x * 64;

    float acc[4][4];
#pragma unroll
    for (int i = 0; i < 4; i++)
#pragma unroll
        for (int j = 0; j < 4; j++) acc[i][j] = 0.f;

    const float* Aps[3] = {A0, A1, A2};
    const float* Bps[3] = {B0, B1, B2};
    int Ks[3]  = {K0, K1, K2};
    int lds[3] = {ldb0, ldb1, ldb2};

    for (int p = 0; p < 3; p++) {
        const float* A = Aps[p];
        if (A == nullptr) continue;
        const float* Bm = Bps[p];
        int K = Ks[p], ldb = lds[p];
        for (int kc = 0; kc < K; kc += 32) {
            __syncthreads();
#pragma unroll
            for (int e = t; e < 2048; e += 256) { int m = e >> 5, k = e & 31; As[m][k] = A[m*K + kc + k]; }
#pragma unroll
            for (int e = t; e < 2048; e += 256) { int k = e >> 6, n = e & 63; Bs[k][n] = Bm[(size_t)(kc + k)*ldb + n0 + n]; }
            __syncthreads();
#pragma unroll
            for (int k = 0; k < 32; k++) {
                float a[4];
#pragma unroll
                for (int i = 0; i < 4; i++) a[i] = As[ty*4 + i][k];
                float4 bv = *(const float4*)&Bs[k][tx*4];
                float bj[4] = {bv.x, bv.y, bv.z, bv.w};
#pragma unroll
                for (int i = 0; i < 4; i++)
#pragma unroll
                    for (int j = 0; j < 4; j++) acc[i][j] = fmaf(a[i], bj[j], acc[i][j]);
            }
        }
    }

#pragma unroll
    for (int i = 0; i < 4; i++) {
        int m = ty*4 + i;
#pragma unroll
        for (int j = 0; j < 4; j++) {
            int n = n0 + tx*4 + j;
            float v = acc[i][j];
            if (bias1) v += bias1[n];
            if (bias2) v += bias2[n];
            if (addm)  v += addm[m*N + n];
            if (act == 1) v = 1.f / (1.f + __expf(-v));
            else if (act == 2) v = tanhf(v);
            C[m*N + n] = v;
        }
    }
}

// ---------------- fused attention logits: logit[b,l] = sum_a Va[a]*tanh(ha[b,a] + feat@Ua + F@Uf) ----------------
// grid = 64*32 blocks (b, l-tile of 64), 256 threads
__global__ void attn_logits_kernel(const float* __restrict__ feat,
                                   const float* __restrict__ Ua,
                                   const float* __restrict__ Uf,
                                   const float* __restrict__ Va)
{
    __shared__ float As[64][33];
    __shared__ float Bs[32][64];
    __shared__ float has[AA];
    __shared__ float vas[AA];
    __shared__ float red[64][17];

    int t = threadIdx.x;
    int tx = t & 15, ty = t >> 4;
    int b  = blockIdx.x >> 5;
    int l0 = (blockIdx.x & 31) << 6;

    for (int i = t; i < AA; i += 256) { has[i] = g_ha[b*AA + i]; vas[i] = Va[i]; }

    const float* fb = feat + (size_t)(b*LL + l0) * DD;
    const float* Fb = g_F  + (size_t)(b*LL + l0) * KK;

    float part[4] = {0.f, 0.f, 0.f, 0.f};

    for (int n0 = 0; n0 < AA; n0 += 64) {
        float acc[4][4];
#pragma unroll
        for (int i = 0; i < 4; i++)
#pragma unroll
            for (int j = 0; j < 4; j++) acc[i][j] = 0.f;

        // features @ Ua (K = 512)
        for (int kc = 0; kc < DD; kc += 32) {
            __syncthreads();
#pragma unroll
            for (int e = t; e < 2048; e += 256) { int m = e >> 5, k = e & 31; As[m][k] = fb[m*DD + kc + k]; }
#pragma unroll
            for (int e = t; e < 2048; e += 256) { int k = e >> 6, n = e & 63; Bs[k][n] = Ua[(kc + k)*AA + n0 + n]; }
            __syncthreads();
#pragma unroll
            for (int k = 0; k < 32; k++) {
                float a[4];
#pragma unroll
                for (int i = 0; i < 4; i++) a[i] = As[ty*4 + i][k];
                float4 bv = *(const float4*)&Bs[k][tx*4];
                float bj[4] = {bv.x, bv.y, bv.z, bv.w};
#pragma unroll
                for (int i = 0; i < 4; i++)
#pragma unroll
                    for (int j = 0; j < 4; j++) acc[i][j] = fmaf(a[i], bj[j], acc[i][j]);
            }
        }
        // F @ Uf (K = 64)
        for (int kc = 0; kc < KK; kc += 32) {
            __syncthreads();
#pragma unroll
            for (int e = t; e < 2048; e += 256) { int m = e >> 5, k = e & 31; As[m][k] = Fb[m*KK + kc + k]; }
#pragma unroll
            for (int e = t; e < 2048; e += 256) { int k = e >> 6, n = e & 63; Bs[k][n] = Uf[(kc + k)*AA + n0 + n]; }
            __syncthreads();
#pragma unroll
            for (int k = 0; k < 32; k++) {
                float a[4];
#pragma unroll
                for (int i = 0; i < 4; i++) a[i] = As[ty*4 + i][k];
                float4 bv = *(const float4*)&Bs[k][tx*4];
                float bj[4] = {bv.x, bv.y, bv.z, bv.w};
#pragma unroll
                for (int i = 0; i < 4; i++)
#pragma unroll
                    for (int j = 0; j < 4; j++) acc[i][j] = fmaf(a[i], bj[j], acc[i][j]);
            }
        }
        // epilogue for this n-chunk: tanh, dot with Va
#pragma unroll
        for (int i = 0; i < 4; i++)
#pragma unroll
            for (int j = 0; j < 4; j++) {
                int n = n0 + tx*4 + j;
                part[i] += tanhf(acc[i][j] + has[n]) * vas[n];
            }
    }

    __syncthreads();
#pragma unroll
    for (int i = 0; i < 4; i++) red[ty*4 + i][tx] = part[i];
    __syncthreads();
    if (t < 64) {
        float s = 0.f;
#pragma unroll
        for (int x = 0; x < 16; x++) s += red[t][x];
        g_logit[b*LL + l0 + t] = s;
    }
}

// ---------------- softmax over L (writes attn into d_out attn region) ----------------
__global__ void softmaxL_kernel(float* __restrict__ attn) {
    int b = blockIdx.x, t = threadIdx.x;
    __shared__ float sred[256];
    const float* lg = g_logit + b*LL;
    float mx = -1e30f;
    for (int l = t; l < LL; l += 256) mx = fmaxf(mx, lg[l]);
    sred[t] = mx; __syncthreads();
    for (int s = 128; s > 0; s >>= 1) { if (t < s) sred[t] = fmaxf(sred[t], sred[t+s]); __syncthreads(); }
    mx = sred[0]; __syncthreads();
    float sum = 0.f;
    for (int l = t; l < LL; l += 256) sum += __expf(lg[l] - mx);
    sred[t] = sum; __syncthreads();
    for (int s = 128; s > 0; s >>= 1) { if (t < s) sred[t] += sred[t+s]; __syncthreads(); }
    sum = sred[0]; __syncthreads();
    float inv = 1.f / sum;
    for (int l = t; l < LL; l += 256) attn[b*LL + l] = __expf(lg[l] - mx) * inv;
}

// ---------------- context: sum_l attn*features, split over L (deterministic, no atomics) ----------------
__global__ void ctx_part_kernel(const float* __restrict__ feat, const float* __restrict__ attn) {
    int b = blockIdx.x >> 3, lc = blockIdx.x & 7;
    int d = threadIdx.x;
    const float* fb = feat + (size_t)(b*LL + lc*256) * DD;
    const float* ab = attn + b*LL + lc*256;
    float s = 0.f;
    for (int l = 0; l < 256; l++) s = fmaf(ab[l], fb[(size_t)l*DD + d], s);
    g_ctxpart[lc*(BZ*DD) + b*DD + d] = s;
}
__global__ void ctx_reduce_kernel() {
    int i = blockIdx.x * blockDim.x + threadIdx.x;
    if (i >= BZ*DD) return;
    float s = 0.f;
#pragma unroll
    for (int lc = 0; lc < 8; lc++) s += g_ctxpart[lc*(BZ*DD) + i];
    g_context[i] = s;
}

// ---------------- Ey = prev_target @ We, split-K (no atomics) ----------------
// grid (4 n-chunks of 64, 32 k-chunks of 1000), 256 threads
__global__ void ey_part_kernel(const float* __restrict__ pt, const float* __restrict__ We) {
    int n0 = blockIdx.x * 64;
    int kc = blockIdx.y;
    int k0 = kc * 1000;
    int t = threadIdx.x;
    int tx = t & 63, tg = t >> 6;
    float acc[16];
#pragma unroll
    for (int mm = 0; mm < 16; mm++) acc[mm] = 0.f;
    for (int k = 0; k < 1000; k++) {
        float w = We[(size_t)(k0 + k)*EE + n0 + tx];
#pragma unroll
        for (int mm = 0; mm < 16; mm++)
            acc[mm] = fmaf(pt[(size_t)(mm*4 + tg)*VV + k0 + k], w, acc[mm]);
    }
#pragma unroll
    for (int mm = 0; mm < 16; mm++)
        g_eypart[kc*(BZ*EE) + (mm*4 + tg)*EE + n0 + tx] = acc[mm];
}
__global__ void ey_reduce_kernel() {
    int i = blockIdx.x * blockDim.x + threadIdx.x;
    if (i >= BZ*EE) return;
    float s = 0.f;
    for (int kc = 0; kc < 32; kc++) s += g_eypart[kc*(BZ*EE) + i];
    g_Ey[i] = s;
}

// ---------------- elementwise ----------------
__global__ void rh_kernel(const float* __restrict__ h) {
    int i = blockIdx.x * blockDim.x + threadIdx.x;
    if (i >= BZ*UU) return;
    g_rh[i] = g_rt[i] * h[i];
}
__global__ void ht_kernel(const float* __restrict__ h, float* __restrict__ out_ht) {
    int i = blockIdx.x * blockDim.x + threadIdx.x;
    if (i >= BZ*UU) return;
    float z = g_zt[i];
    float v = (1.f - z) * h[i] + z * g_hcand[i];
    g_ht[i] = v;
    out_ht[i] = v;
}

// ---------------- softmax over V ----------------
__global__ void softmaxV_kernel(float* __restrict__ out) {
    int b = blockIdx.x, t = threadIdx.x;
    __shared__ float sred[1024];
    const float* lg = g_vlogits + (size_t)b*VV;
    float mx = -1e30f;
    for (int v = t; v < VV; v += 1024) mx = fmaxf(mx, lg[v]);
    sred[t] = mx; __syncthreads();
    for (int s = 512; s > 0; s >>= 1) { if (t < s) sred[t] = fmaxf(sred[t], sred[t+s]); __syncthreads(); }
    mx = sred[0]; __syncthreads();
    float sum = 0.f;
    for (int v = t; v < VV; v += 1024) sum += __expf(lg[v] - mx);
    sred[t] = sum; __syncthreads();
    for (int s = 512; s > 0; s >>= 1) { if (t < s) sred[t] += sred[t+s]; __syncthreads(); }
    sum = sred[0]; __syncthreads();
    float inv = 1.f / sum;
    for (int v = t; v < VV; v += 1024) out[(size_t)b*VV + v] = __expf(lg[v] - mx) * inv;
}

// ---------------- launch ----------------
extern "C" void kernel_launch(void* const* d_in, const int* in_sizes, int n_in,
                              void* d_out, int out_size)
{
    const float* prev_target = (const float*)d_in[0];
    const float* prev_hidden = (const float*)d_in[1];
    const float* features    = (const float*)d_in[2];
    const float* Bmat        = (const float*)d_in[3];
    const float* Wa          = (const float*)d_in[4];
    const float* Ua          = (const float*)d_in[5];
    const float* Va          = (const float*)d_in[6];
    const float* Uf          = (const float*)d_in[7];
    const float* Qk          = (const float*)d_in[8];
    const float* We          = (const float*)d_in[9];
    const float* Wccz        = (const float*)d_in[10];
    const float* Wyz         = (const float*)d_in[11];
    const float* Uhz         = (const float*)d_in[12];
    const float* Wyr         = (const float*)d_in[13];
    const float* Uhr         = (const float*)d_in[14];
    const float* Ccr         = (const float*)d_in[15];
    const float* Wyh         = (const float*)d_in[16];
    const float* b_wyh       = (const float*)d_in[17];
    const float* Urh         = (const float*)d_in[18];
    const float* b_urh       = (const float*)d_in[19];
    const float* Wo          = (const float*)d_in[20];
    const float* Wh          = (const float*)d_in[21];
    const float* Wc          = (const float*)d_in[22];

    float* out      = (float*)d_out;               // (64, 32000)
    float* out_ht   = (float*)d_out + HT_OFF;      // (64, 512)
    float* out_attn = (float*)d_out + ATTN_OFF;    // (64, 2048)

    float* pF;       cudaGetSymbolAddress((void**)&pF, g_F); (void)pF; // not needed; kernels use globals
    float* pha;      cudaGetSymbolAddress((void**)&pha, g_ha);
    float* pccz;     cudaGetSymbolAddress((void**)&pccz, g_ccz);
    float* pzt;      cudaGetSymbolAddress((void**)&pzt, g_zt);
    float* prt;      cudaGetSymbolAddress((void**)&prt, g_rt);
    float* prh;      cudaGetSymbolAddress((void**)&prh, g_rh);
    float* phc;      cudaGetSymbolAddress((void**)&phc, g_hcand);
    float* pht;      cudaGetSymbolAddress((void**)&pht, g_ht);
    float* pctx;     cudaGetSymbolAddress((void**)&pctx, g_context);
    float* pEy;      cudaGetSymbolAddress((void**)&pEy, g_Ey);
    float* poute;    cudaGetSymbolAddress((void**)&poute, g_oute);
    float* pvlog;    cudaGetSymbolAddress((void**)&pvlog, g_vlogits);

    // 1. conv -> F
    conv_kernel<<<(BZ*LL*KK + 255)/256, 256>>>(Bmat, Qk);

    // 2. ha = prev_hidden @ Wa
    sgemm3_kernel<<<AA/64, 256>>>(prev_hidden, Wa, UU, AA,
                                  nullptr, nullptr, 0, 0,
                                  nullptr, nullptr, 0, 0,
                                  nullptr, nullptr, nullptr, pha, AA, 0);

    // 3. attention logits (the big one)
    attn_logits_kernel<<<BZ*32, 256>>>(features, Ua, Uf, Va);

    // 4. softmax over L -> attn (d_out)
    softmaxL_kernel<<<BZ, 256>>>(out_attn);

    // 5. context
    ctx_part_kernel<<<BZ*8, 512>>>(features, out_attn);
    ctx_reduce_kernel<<<(BZ*DD + 255)/256, 256>>>();

    // 6. Ey = prev_target @ We (split-K)
    { dim3 g(4, 32); ey_part_kernel<<<g, 256>>>(prev_target, We); }
    ey_reduce_kernel<<<(BZ*EE + 255)/256, 256>>>();

    // 7. ccz = context @ Wccz
    sgemm3_kernel<<<UU/64, 256>>>(pctx, Wccz, DD, UU,
                                  nullptr, nullptr, 0, 0,
                                  nullptr, nullptr, 0, 0,
                                  nullptr, nullptr, nullptr, pccz, UU, 0);

    // 8. zt = sigmoid(Ey@Wyz + h@Uhz + ccz)
    sgemm3_kernel<<<UU/64, 256>>>(pEy, Wyz, EE, UU,
                                  prev_hidden, Uhz, UU, UU,
                                  nullptr, nullptr, 0, 0,
                                  nullptr, nullptr, pccz, pzt, UU, 1);

    // 9. rt = sigmoid(Ey@Wyr + h@Uhr + context@Ccr)
    sgemm3_kernel<<<UU/64, 256>>>(pEy, Wyr, EE, UU,
                                  prev_hidden, Uhr, UU, UU,
                                  pctx, Ccr, DD, UU,
                                  nullptr, nullptr, nullptr, prt, UU, 1);

    // 10. rh = rt * h
    rh_kernel<<<(BZ*UU + 255)/256, 256>>>(prev_hidden);

    // 11. hcand = tanh(Ey@Wyh + b_wyh + rh@Urh + b_urh + ccz)
    sgemm3_kernel<<<UU/64, 256>>>(pEy, Wyh, EE, UU,
                                  prh, Urh, UU, UU,
                                  nullptr, nullptr, 0, 0,
                                  b_wyh, b_urh, pccz, phc, UU, 2);

    // 12. ht = (1-zt)*h + zt*hcand  (also writes d_out ht region)
    ht_kernel<<<(BZ*UU + 255)/256, 256>>>(prev_hidden, out_ht);

    // 13. out_e = Ey + ht@Wh + context@Wc
    sgemm3_kernel<<<EE/64, 256>>>(pht, Wh, UU, EE,
                                  pctx, Wc, DD, EE,
                                  nullptr, nullptr, 0, 0,
                                  nullptr, nullptr, pEy, poute, EE, 0);

    // 14. vlogits = out_e @ Wo
    sgemm3_kernel<<<VV/64, 256>>>(poute, Wo, EE, VV,
                                  nullptr, nullptr, 0, 0,
                                  nullptr, nullptr, 0, 0,
                                  nullptr, nullptr, nullptr, pvlog, VV, 0);

    // 15. softmax over V -> out (d_out)
    softmaxV_kernel<<<BZ, 1024>>>(out);
}

// round 4
// speedup vs baseline: 1.7728x; 1.7728x over previous
#include <cuda_runtime.h>
#include <cstdint>

// ---------------- shapes ----------------
#define BZ 64
#define LL 2048
#define DD 512
#define UU 512
#define AA 512
#define KK 64
#define VV 32000
#define EE 256
#define QW 7

#define HT_OFF  (BZ*VV)
#define ATTN_OFF (BZ*VV + BZ*UU)

// ---------------- scratch ----------------
__device__ float g_F[BZ*LL*KK];
__device__ float g_ha[BZ*AA];
__device__ float g_logit[BZ*LL];
__device__ float g_ctxpart[8*BZ*DD];
__device__ float g_context[BZ*DD];
__device__ float g_eypart[32*BZ*EE];
__device__ float g_Ey[BZ*EE];
__device__ float g_ccz[BZ*UU];
__device__ float g_zt[BZ*UU];
__device__ float g_rt[BZ*UU];
__device__ float g_rh[BZ*UU];
__device__ float g_hcand[BZ*UU];
__device__ float g_ht[BZ*UU];
__device__ float g_oute[BZ*EE];
__device__ float g_vlogits[BZ*VV];

// ---------------- conv1d SAME width-7 ----------------
__global__ void conv_kernel(const float* __restrict__ B, const float* __restrict__ Qk) {
    int idx = blockIdx.x * blockDim.x + threadIdx.x;
    if (idx >= BZ*LL*KK) return;
    int k = idx & (KK-1);
    int l = (idx >> 6) & (LL-1);
    int b = idx >> 17;
    float s = 0.f;
#pragma unroll
    for (int w = 0; w < QW; w++) {
        int ll2 = l + w - 3;
        if (ll2 >= 0 && ll2 < LL) s += B[b*LL + ll2] * Qk[w*KK + k];
    }
    g_F[idx] = s;
}

// ---------------- generic small GEMM (fp32; used for the small ops) ----------------
__global__ void sgemm3_kernel(const float* __restrict__ A0, const float* __restrict__ B0, int K0, int ldb0,
                              const float* __restrict__ A1, const float* __restrict__ B1, int K1, int ldb1,
                              const float* __restrict__ A2, const float* __restrict__ B2, int K2, int ldb2,
                              const float* __restrict__ bias1, const float* __restrict__ bias2,
                              const float* __restrict__ addm,
                              float* __restrict__ C, int N, int act)
{
    __shared__ float As[64][33];
    __shared__ float Bs[32][64];
    int t = threadIdx.x;
    int tx = t & 15, ty = t >> 4;
    int n0 = blockIdx.x * 64;

    float acc[4][4];
#pragma unroll
    for (int i = 0; i < 4; i++)
#pragma unroll
        for (int j = 0; j < 4; j++) acc[i][j] = 0.f;

    const float* Aps[3] = {A0, A1, A2};
    const float* Bps[3] = {B0, B1, B2};
    int Ks[3]  = {K0, K1, K2};
    int lds[3] = {ldb0, ldb1, ldb2};

    for (int p = 0; p < 3; p++) {
        const float* A = Aps[p];
        if (A == nullptr) continue;
        const float* Bm = Bps[p];
        int K = Ks[p], ldb = lds[p];
        for (int kc = 0; kc < K; kc += 32) {
            __syncthreads();
#pragma unroll
            for (int e = t; e < 2048; e += 256) { int m = e >> 5, k = e & 31; As[m][k] = A[m*K + kc + k]; }
#pragma unroll
            for (int e = t; e < 2048; e += 256) { int k = e >> 6, n = e & 63; Bs[k][n] = Bm[(size_t)(kc + k)*ldb + n0 + n]; }
            __syncthreads();
#pragma unroll
            for (int k = 0; k < 32; k++) {
                float a[4];
#pragma unroll
                for (int i = 0; i < 4; i++) a[i] = As[ty*4 + i][k];
                float4 bv = *(const float4*)&Bs[k][tx*4];
                float bj[4] = {bv.x, bv.y, bv.z, bv.w};
#pragma unroll
                for (int i = 0; i < 4; i++)
#pragma unroll
                    for (int j = 0; j < 4; j++) acc[i][j] = fmaf(a[i], bj[j], acc[i][j]);
            }
        }
    }

#pragma unroll
    for (int i = 0; i < 4; i++) {
        int m = ty*4 + i;
#pragma unroll
        for (int j = 0; j < 4; j++) {
            int n = n0 + tx*4 + j;
            float v = acc[i][j];
            if (bias1) v += bias1[n];
            if (bias2) v += bias2[n];
            if (addm)  v += addm[m*N + n];
            if (act == 1) v = 1.f / (1.f + __expf(-v));
            else if (act == 2) v = tanhf(v);
            C[m*N + n] = v;
        }
    }
}

// ---------------- tf32 helpers ----------------
__device__ __forceinline__ float to_tf32(float x) {
    float r;
    asm("cvt.rna.tf32.f32 %0, %1;" : "=f"(r) : "f"(x));
    return r;
}
__device__ __forceinline__ void mma_tf32(float* c, const uint32_t* a, const uint32_t* b) {
    asm volatile(
        "mma.sync.aligned.m16n8k8.row.col.f32.tf32.tf32.f32 "
        "{%0,%1,%2,%3}, {%4,%5,%6,%7}, {%8,%9}, {%0,%1,%2,%3};"
        : "+f"(c[0]), "+f"(c[1]), "+f"(c[2]), "+f"(c[3])
        : "r"(a[0]), "r"(a[1]), "r"(a[2]), "r"(a[3]), "r"(b[0]), "r"(b[1]));
}

// ---------------- attention logits via tf32 HMMA ----------------
// logit[b,l] = sum_a Va[a] * tanh( ha[b,a] + feat[b,l,:]@Ua[:,a] + F[b,l,:]@Uf[:,a] )
// Block tile: 128 rows (l) x 128 cols (a) per pass, 4 passes over A=512.
// grid = 64 batches * 16 l-tiles = 1024 blocks, 512 threads (16 warps; 4x4 warp grid).
#define ALD 36
#define BLD 136
__global__ __launch_bounds__(512, 1)
void attn_logits_mma_kernel(const float* __restrict__ feat,
                            const float* __restrict__ Ua,
                            const float* __restrict__ Uf,
                            const float* __restrict__ Va)
{
    __shared__ float As[128][ALD];     // 18432 B  [m][k]
    __shared__ float Bs[32][BLD];      // 17408 B  [k][n]
    __shared__ float has[AA];          //  2048 B
    __shared__ float vas[AA];          //  2048 B
    __shared__ float red[128][17];     //  8704 B

    int t = threadIdx.x;
    int lane = t & 31;
    int wid  = t >> 5;
    int wm = wid & 3;        // warp row group: 32 rows each
    int wn = wid >> 2;       // warp col group: 32 cols each
    int qid = lane >> 2;     // 0..7
    int tq  = lane & 3;      // 0..3

    int b  = blockIdx.x >> 4;
    int l0 = (blockIdx.x & 15) << 7;   // *128

    for (int i = t; i < AA; i += 512) { has[i] = g_ha[b*AA + i]; vas[i] = Va[i]; }

    const float* fb = feat + (size_t)(b*LL + l0) * DD;
    const float* Fb = g_F  + (size_t)(b*LL + l0) * KK;

    float part[4] = {0.f, 0.f, 0.f, 0.f};   // [fm*2 + half]

    for (int n0 = 0; n0 < AA; n0 += 128) {
        float acc[2][4][4];   // [fm][fn][4]
#pragma unroll
        for (int i = 0; i < 2; i++)
#pragma unroll
            for (int j = 0; j < 4; j++)
#pragma unroll
                for (int r = 0; r < 4; r++) acc[i][j][r] = 0.f;

#pragma unroll 1
        for (int seg = 0; seg < 2; seg++) {
            const float* A  = seg ? Fb : fb;
            const float* Bm = seg ? Uf : Ua;
            int K   = seg ? KK : DD;
            int lda = seg ? KK : DD;

            for (int kc = 0; kc < K; kc += 32) {
                // load A tile 128x32 (1024 float4), B tile 32x128 (1024 float4)
                float4 av[2], bv[2];
#pragma unroll
                for (int r = 0; r < 2; r++) {
                    int e = t + r*512;
                    int m = e >> 3, k4 = (e & 7) << 2;
                    av[r] = *(const float4*)&A[(size_t)m*lda + kc + k4];
                    int kr = e >> 5, n4 = (e & 31) << 2;
                    bv[r] = *(const float4*)&Bm[(size_t)(kc + kr)*AA + n0 + n4];
                }
                __syncthreads();
#pragma unroll
                for (int r = 0; r < 2; r++) {
                    int e = t + r*512;
                    int m = e >> 3, k4 = (e & 7) << 2;
                    As[m][k4+0] = to_tf32(av[r].x);
                    As[m][k4+1] = to_tf32(av[r].y);
                    As[m][k4+2] = to_tf32(av[r].z);
                    As[m][k4+3] = to_tf32(av[r].w);
                    int kr = e >> 5, n4 = (e & 31) << 2;
                    Bs[kr][n4+0] = to_tf32(bv[r].x);
                    Bs[kr][n4+1] = to_tf32(bv[r].y);
                    Bs[kr][n4+2] = to_tf32(bv[r].z);
                    Bs[kr][n4+3] = to_tf32(bv[r].w);
                }
                __syncthreads();

#pragma unroll
                for (int kk = 0; kk < 4; kk++) {
                    uint32_t af[2][4], bf[4][2];
#pragma unroll
                    for (int fm = 0; fm < 2; fm++) {
                        int m0 = wm*32 + fm*16 + qid;
                        af[fm][0] = __float_as_uint(As[m0    ][kk*8 + tq    ]);
                        af[fm][1] = __float_as_uint(As[m0 + 8][kk*8 + tq    ]);
                        af[fm][2] = __float_as_uint(As[m0    ][kk*8 + tq + 4]);
                        af[fm][3] = __float_as_uint(As[m0 + 8][kk*8 + tq + 4]);
                    }
#pragma unroll
                    for (int fn = 0; fn < 4; fn++) {
                        int nb = wn*32 + fn*8 + qid;
                        bf[fn][0] = __float_as_uint(Bs[kk*8 + tq    ][nb]);
                        bf[fn][1] = __float_as_uint(Bs[kk*8 + tq + 4][nb]);
                    }
#pragma unroll
                    for (int fm = 0; fm < 2; fm++)
#pragma unroll
                        for (int fn = 0; fn < 4; fn++)
                            mma_tf32(acc[fm][fn], af[fm], bf[fn]);
                }
            }
        }

        // epilogue: tanh + dot with Va, accumulate per-row partials
#pragma unroll
        for (int fm = 0; fm < 2; fm++)
#pragma unroll
            for (int fn = 0; fn < 4; fn++)
#pragma unroll
                for (int r = 0; r < 4; r++) {
                    int half = r >> 1;               // c2,c3 are rows +8
                    int j    = r & 1;
                    int n = n0 + wn*32 + fn*8 + 2*tq + j;
                    part[fm*2 + half] += tanhf(acc[fm][fn][r] + has[n]) * vas[n];
                }
    }

    __syncthreads();
    int slot = wn*4 + tq;
#pragma unroll
    for (int fm = 0; fm < 2; fm++)
#pragma unroll
        for (int half = 0; half < 2; half++) {
            int rl = wm*32 + fm*16 + qid + 8*half;
            red[rl][slot] = part[fm*2 + half];
        }
    __syncthreads();
    if (t < 128) {
        float s = 0.f;
#pragma unroll
        for (int x = 0; x < 16; x++) s += red[t][x];
        g_logit[b*LL + l0 + t] = s;
    }
}

// ---------------- softmax over L ----------------
__global__ void softmaxL_kernel(float* __restrict__ attn) {
    int b = blockIdx.x, t = threadIdx.x;
    __shared__ float sred[256];
    const float* lg = g_logit + b*LL;
    float mx = -1e30f;
    for (int l = t; l < LL; l += 256) mx = fmaxf(mx, lg[l]);
    sred[t] = mx; __syncthreads();
    for (int s = 128; s > 0; s >>= 1) { if (t < s) sred[t] = fmaxf(sred[t], sred[t+s]); __syncthreads(); }
    mx = sred[0]; __syncthreads();
    float sum = 0.f;
    for (int l = t; l < LL; l += 256) sum += __expf(lg[l] - mx);
    sred[t] = sum; __syncthreads();
    for (int s = 128; s > 0; s >>= 1) { if (t < s) sred[t] += sred[t+s]; __syncthreads(); }
    sum = sred[0]; __syncthreads();
    float inv = 1.f / sum;
    for (int l = t; l < LL; l += 256) attn[b*LL + l] = __expf(lg[l] - mx) * inv;
}

// ---------------- context ----------------
__global__ void ctx_part_kernel(const float* __restrict__ feat, const float* __restrict__ attn) {
    int b = blockIdx.x >> 3, lc = blockIdx.x & 7;
    int d = threadIdx.x;
    const float* fb = feat + (size_t)(b*LL + lc*256) * DD;
    const float* ab = attn + b*LL + lc*256;
    float s = 0.f;
    for (int l = 0; l < 256; l++) s = fmaf(ab[l], fb[(size_t)l*DD + d], s);
    g_ctxpart[lc*(BZ*DD) + b*DD + d] = s;
}
__global__ void ctx_reduce_kernel() {
    int i = blockIdx.x * blockDim.x + threadIdx.x;
    if (i >= BZ*DD) return;
    float s = 0.f;
#pragma unroll
    for (int lc = 0; lc < 8; lc++) s += g_ctxpart[lc*(BZ*DD) + i];
    g_context[i] = s;
}

// ---------------- Ey split-K ----------------
__global__ void ey_part_kernel(const float* __restrict__ pt, const float* __restrict__ We) {
    int n0 = blockIdx.x * 64;
    int kc = blockIdx.y;
    int k0 = kc * 1000;
    int t = threadIdx.x;
    int tx = t & 63, tg = t >> 6;
    float acc[16];
#pragma unroll
    for (int mm = 0; mm < 16; mm++) acc[mm] = 0.f;
    for (int k = 0; k < 1000; k++) {
        float w = We[(size_t)(k0 + k)*EE + n0 + tx];
#pragma unroll
        for (int mm = 0; mm < 16; mm++)
            acc[mm] = fmaf(pt[(size_t)(mm*4 + tg)*VV + k0 + k], w, acc[mm]);
    }
#pragma unroll
    for (int mm = 0; mm < 16; mm++)
        g_eypart[kc*(BZ*EE) + (mm*4 + tg)*EE + n0 + tx] = acc[mm];
}
__global__ void ey_reduce_kernel() {
    int i = blockIdx.x * blockDim.x + threadIdx.x;
    if (i >= BZ*EE) return;
    float s = 0.f;
    for (int kc = 0; kc < 32; kc++) s += g_eypart[kc*(BZ*EE) + i];
    g_Ey[i] = s;
}

// ---------------- elementwise ----------------
__global__ void rh_kernel(const float* __restrict__ h) {
    int i = blockIdx.x * blockDim.x + threadIdx.x;
    if (i >= BZ*UU) return;
    g_rh[i] = g_rt[i] * h[i];
}
__global__ void ht_kernel(const float* __restrict__ h, float* __restrict__ out_ht) {
    int i = blockIdx.x * blockDim.x + threadIdx.x;
    if (i >= BZ*UU) return;
    float z = g_zt[i];
    float v = (1.f - z) * h[i] + z * g_hcand[i];
    g_ht[i] = v;
    out_ht[i] = v;
}

// ---------------- softmax over V ----------------
__global__ void softmaxV_kernel(float* __restrict__ out) {
    int b = blockIdx.x, t = threadIdx.x;
    __shared__ float sred[1024];
    const float* lg = g_vlogits + (size_t)b*VV;
    float mx = -1e30f;
    for (int v = t; v < VV; v += 1024) mx = fmaxf(mx, lg[v]);
    sred[t] = mx; __syncthreads();
    for (int s = 512; s > 0; s >>= 1) { if (t < s) sred[t] = fmaxf(sred[t], sred[t+s]); __syncthreads(); }
    mx = sred[0]; __syncthreads();
    float sum = 0.f;
    for (int v = t; v < VV; v += 1024) sum += __expf(lg[v] - mx);
    sred[t] = sum; __syncthreads();
    for (int s = 512; s > 0; s >>= 1) { if (t < s) sred[t] += sred[t+s]; __syncthreads(); }
    sum = sred[0]; __syncthreads();
    float inv = 1.f / sum;
    for (int v = t; v < VV; v += 1024) out[(size_t)b*VV + v] = __expf(lg[v] - mx) * inv;
}

// ---------------- launch ----------------
extern "C" void kernel_launch(void* const* d_in, const int* in_sizes, int n_in,
                              void* d_out, int out_size)
{
    const float* prev_target = (const float*)d_in[0];
    const float* prev_hidden = (const float*)d_in[1];
    const float* features    = (const float*)d_in[2];
    const float* Bmat        = (const float*)d_in[3];
    const float* Wa          = (const float*)d_in[4];
    const float* Ua          = (const float*)d_in[5];
    const float* Va          = (const float*)d_in[6];
    const float* Uf          = (const float*)d_in[7];
    const float* Qk          = (const float*)d_in[8];
    const float* We          = (const float*)d_in[9];
    const float* Wccz        = (const float*)d_in[10];
    const float* Wyz         = (const float*)d_in[11];
    const float* Uhz         = (const float*)d_in[12];
    const float* Wyr         = (const float*)d_in[13];
    const float* Uhr         = (const float*)d_in[14];
    const float* Ccr         = (const float*)d_in[15];
    const float* Wyh         = (const float*)d_in[16];
    const float* b_wyh       = (const float*)d_in[17];
    const float* Urh         = (const float*)d_in[18];
    const float* b_urh       = (const float*)d_in[19];
    const float* Wo          = (const float*)d_in[20];
    const float* Wh          = (const float*)d_in[21];
    const float* Wc          = (const float*)d_in[22];

    float* out      = (float*)d_out;
    float* out_ht   = (float*)d_out + HT_OFF;
    float* out_attn = (float*)d_out + ATTN_OFF;

    float* pha;   cudaGetSymbolAddress((void**)&pha, g_ha);
    float* pccz;  cudaGetSymbolAddress((void**)&pccz, g_ccz);
    float* pzt;   cudaGetSymbolAddress((void**)&pzt, g_zt);
    float* prt;   cudaGetSymbolAddress((void**)&prt, g_rt);
    float* prh;   cudaGetSymbolAddress((void**)&prh, g_rh);
    float* phc;   cudaGetSymbolAddress((void**)&phc, g_hcand);
    float* pht;   cudaGetSymbolAddress((void**)&pht, g_ht);
    float* pctx;  cudaGetSymbolAddress((void**)&pctx, g_context);
    float* pEy;   cudaGetSymbolAddress((void**)&pEy, g_Ey);
    float* poute; cudaGetSymbolAddress((void**)&poute, g_oute);
    float* pvlog; cudaGetSymbolAddress((void**)&pvlog, g_vlogits);

    conv_kernel<<<(BZ*LL*KK + 255)/256, 256>>>(Bmat, Qk);

    sgemm3_kernel<<<AA/64, 256>>>(prev_hidden, Wa, UU, AA,
                                  nullptr, nullptr, 0, 0,
                                  nullptr, nullptr, 0, 0,
                                  nullptr, nullptr, nullptr, pha, AA, 0);

    attn_logits_mma_kernel<<<BZ*16, 512>>>(features, Ua, Uf, Va);

    softmaxL_kernel<<<BZ, 256>>>(out_attn);

    ctx_part_kernel<<<BZ*8, 512>>>(features, out_attn);
    ctx_reduce_kernel<<<(BZ*DD + 255)/256, 256>>>();

    { dim3 g(4, 32); ey_part_kernel<<<g, 256>>>(prev_target, We); }
    ey_reduce_kernel<<<(BZ*EE + 255)/256, 256>>>();

    sgemm3_kernel<<<UU/64, 256>>>(pctx, Wccz, DD, UU,
                                  nullptr, nullptr, 0, 0,
                                  nullptr, nullptr, 0, 0,
                                  nullptr, nullptr, nullptr, pccz, UU, 0);

    sgemm3_kernel<<<UU/64, 256>>>(pEy, Wyz, EE, UU,
                                  prev_hidden, Uhz, UU, UU,
                                  nullptr, nullptr, 0, 0,
                                  nullptr, nullptr, pccz, pzt, UU, 1);

    sgemm3_kernel<<<UU/64, 256>>>(pEy, Wyr, EE, UU,
                                  prev_hidden, Uhr, UU, UU,
                                  pctx, Ccr, DD, UU,
                                  nullptr, nullptr, nullptr, prt, UU, 1);

    rh_kernel<<<(BZ*UU + 255)/256, 256>>>(prev_hidden);

    sgemm3_kernel<<<UU/64, 256>>>(pEy, Wyh, EE, UU,
                                  prh, Urh, UU, UU,
                                  nullptr, nullptr, 0, 0,
                                  b_wyh, b_urh, pccz, phc, UU, 2);

    ht_kernel<<<(BZ*UU + 255)/256, 256>>>(prev_hidden, out_ht);

    sgemm3_kernel<<<EE/64, 256>>>(pht, Wh, UU, EE,
                                  pctx, Wc, DD, EE,
                                  nullptr, nullptr, 0, 0,
                                  nullptr, nullptr, pEy, poute, EE, 0);

    sgemm3_kernel<<<VV/64, 256>>>(poute, Wo, EE, VV,
                                  nullptr, nullptr, 0, 0,
                                  nullptr, nullptr, 0, 0,
                                  nullptr, nullptr, nullptr, pvlog, VV, 0);

    softmaxV_kernel<<<BZ, 1024>>>(out);
}

// round 5
// speedup vs baseline: 1.9116x; 1.0783x over previous
#include <cuda_runtime.h>
#include <cstdint>

// ---------------- shapes ----------------
#define BZ 64
#define LL 2048
#define DD 512
#define UU 512
#define AA 512
#define KK 64
#define VV 32000
#define EE 256
#define QW 7

#define HT_OFF  (BZ*VV)
#define ATTN_OFF (BZ*VV + BZ*UU)

// ---------------- scratch ----------------
__device__ float g_Bext[BZ*LL*32];   // shifted-B extension tile [b][l][32] (cols 0..6 used)
__device__ float g_Qext[32*512];     // rows 0..6 = Qk@Uf, rest zero
__device__ float g_ha[BZ*AA];
__device__ float g_logit[BZ*LL];
__device__ float g_ctxpart[8*BZ*DD];
__device__ float g_context[BZ*DD];
__device__ float g_eypart[32*BZ*EE];
__device__ float g_Ey[BZ*EE];
__device__ float g_zt[BZ*UU];
__device__ float g_rt[BZ*UU];
__device__ float g_hcand[BZ*UU];
__device__ float g_ht[BZ*UU];
__device__ float g_oute[BZ*EE];
__device__ float g_vlogits[BZ*VV];

// ---------------- cp.async helpers ----------------
__device__ __forceinline__ void cp_async16(void* smem, const void* gmem) {
    unsigned sa = (unsigned)__cvta_generic_to_shared(smem);
    asm volatile("cp.async.cg.shared.global [%0], [%1], 16;" :: "r"(sa), "l"(gmem));
}
__device__ __forceinline__ void cp_commit() { asm volatile("cp.async.commit_group;"); }
template<int N> __device__ __forceinline__ void cp_wait() {
    asm volatile("cp.async.wait_group %0;" :: "n"(N));
}

// ---------------- prep: QU = Qk@Uf into padded 32x512; shifted-B ext tiles ----------------
__global__ void prep_qext_kernel(const float* __restrict__ Qk, const float* __restrict__ Uf) {
    int i = blockIdx.x * blockDim.x + threadIdx.x;
    if (i >= 32*512) return;
    int w = i >> 9, a = i & 511;
    float s = 0.f;
    if (w < QW) {
        for (int k = 0; k < KK; k++) s = fmaf(Qk[w*KK + k], Uf[k*AA + a], s);
    }
    g_Qext[i] = s;
}
__global__ void prep_bext_kernel(const float* __restrict__ Bm) {
    int i = blockIdx.x * blockDim.x + threadIdx.x;
    if (i >= BZ*LL*32) return;
    int j = i & 31;
    int l = (i >> 5) & (LL-1);
    int b = i >> 16;
    int ls = l + j - 3;
    g_Bext[i] = (j < QW && ls >= 0 && ls < LL) ? Bm[b*LL + ls] : 0.f;
}

// ---------------- generic small GEMM (fp32) ----------------
// C(64xN) = act( A0@B0 + A1*? @B1 + A2@B2 + biases + addm ), A1 optionally elementwise-multiplied by Amul1.
__global__ void sgemm3_kernel(const float* __restrict__ A0, const float* __restrict__ B0, int K0,
                              const float* __restrict__ A1, const float* __restrict__ B1, int K1,
                              const float* __restrict__ Amul1,
                              const float* __restrict__ A2, const float* __restrict__ B2, int K2,
                              const float* __restrict__ bias1, const float* __restrict__ bias2,
                              const float* __restrict__ addm,
                              float* __restrict__ C, int N, int act)
{
    __shared__ float As[64][33];
    __shared__ float Bs[32][64];
    int t = threadIdx.x;
    int tx = t & 15, ty = t >> 4;
    int n0 = blockIdx.x * 64;

    float acc[4][4];
#pragma unroll
    for (int i = 0; i < 4; i++)
#pragma unroll
        for (int j = 0; j < 4; j++) acc[i][j] = 0.f;

    const float* Aps[3] = {A0, A1, A2};
    const float* Bps[3] = {B0, B1, B2};
    const float* Mps[3] = {nullptr, Amul1, nullptr};
    int Ks[3] = {K0, K1, K2};

    for (int p = 0; p < 3; p++) {
        const float* A = Aps[p];
        if (A == nullptr) continue;
        const float* Bm = Bps[p];
        const float* Mu = Mps[p];
        int K = Ks[p];
        for (int kc = 0; kc < K; kc += 32) {
            __syncthreads();
#pragma unroll
            for (int e = t; e < 2048; e += 256) {
                int m = e >> 5, k = e & 31;
                float v = A[m*K + kc + k];
                if (Mu) v *= Mu[m*K + kc + k];
                As[m][k] = v;
            }
#pragma unroll
            for (int e = t; e < 2048; e += 256) { int k = e >> 6, n = e & 63; Bs[k][n] = Bm[(size_t)(kc + k)*N + n0 + n]; }
            __syncthreads();
#pragma unroll
            for (int k = 0; k < 32; k++) {
                float a[4];
#pragma unroll
                for (int i = 0; i < 4; i++) a[i] = As[ty*4 + i][k];
                float4 bv = *(const float4*)&Bs[k][tx*4];
                float bj[4] = {bv.x, bv.y, bv.z, bv.w};
#pragma unroll
                for (int i = 0; i < 4; i++)
#pragma unroll
                    for (int j = 0; j < 4; j++) acc[i][j] = fmaf(a[i], bj[j], acc[i][j]);
            }
        }
    }

#pragma unroll
    for (int i = 0; i < 4; i++) {
        int m = ty*4 + i;
#pragma unroll
        for (int j = 0; j < 4; j++) {
            int n = n0 + tx*4 + j;
            float v = acc[i][j];
            if (bias1) v += bias1[n];
            if (bias2) v += bias2[n];
            if (addm)  v += addm[m*N + n];
            if (act == 1) v = 1.f / (1.f + __expf(-v));
            else if (act == 2) v = tanhf(v);
            C[m*N + n] = v;
        }
    }
}

// ---------------- tf32 mma ----------------
__device__ __forceinline__ void mma_tf32(float* c, const uint32_t* a, const uint32_t* b) {
    asm volatile(
        "mma.sync.aligned.m16n8k8.row.col.f32.tf32.tf32.f32 "
        "{%0,%1,%2,%3}, {%4,%5,%6,%7}, {%8,%9}, {%0,%1,%2,%3};"
        : "+f"(c[0]), "+f"(c[1]), "+f"(c[2]), "+f"(c[3])
        : "r"(a[0]), "r"(a[1]), "r"(a[2]), "r"(a[3]), "r"(b[0]), "r"(b[1]));
}

__device__ __forceinline__ float fast_tanh(float x) {
    x = fminf(fmaxf(x, -15.f), 15.f);
    float e = __expf(2.f * x);
    return (e - 1.f) / (e + 1.f);
}

// ---------------- attention logits: pipelined tf32 HMMA ----------------
// K = 544 total (512 feat@Ua + 32 ext cols for the conv fold). 17 chunks of 32.
// Block: 128 l-rows, 4 passes of 128 a-cols. 256 threads = 8 warps (4 x 2),
// warp tile 32x64. 2-stage cp.async pipeline, 2 blocks/SM.
#define NCHUNK 17
#define SM_AS0 0
#define SM_AS1 4608
#define SM_BS0 9216
#define SM_BS1 13568
#define SM_HAS 17920
#define SM_VAS 18432
#define SM_RED 18944
#define SM_TOTF 20096   // floats -> 80384 bytes

__global__ __launch_bounds__(256, 2)
void attn_mma_kernel(const float* __restrict__ feat,
                     const float* __restrict__ Ua,
                     const float* __restrict__ Va)
{
    extern __shared__ float sm[];
    float* AsS[2] = {sm + SM_AS0, sm + SM_AS1};   // [128][36]
    float* BsS[2] = {sm + SM_BS0, sm + SM_BS1};   // [32][136]
    float* has = sm + SM_HAS;
    float* vas = sm + SM_VAS;
    float* red = sm + SM_RED;                     // [128][9]

    int t = threadIdx.x;
    int lane = t & 31, wid = t >> 5;
    int wm = wid & 3, wn = wid >> 2;   // 4 x 2 warp grid
    int qid = lane >> 2, tq = lane & 3;

    int b  = blockIdx.x >> 4;
    int l0 = (blockIdx.x & 15) << 7;

    for (int i = t; i < AA; i += 256) { has[i] = g_ha[b*AA + i]; vas[i] = Va[i]; }

    const float* fb   = feat  + (size_t)(b*LL + l0) * DD;
    const float* bext = g_Bext + (size_t)(b*LL + l0) * 32;

    float part[4] = {0.f, 0.f, 0.f, 0.f};

    for (int n0 = 0; n0 < AA; n0 += 128) {
        float acc[2][8][4];
#pragma unroll
        for (int i = 0; i < 2; i++)
#pragma unroll
            for (int j = 0; j < 8; j++)
#pragma unroll
                for (int r = 0; r < 4; r++) acc[i][j][r] = 0.f;

        // ---- async load of chunk c into stage c&1 ----
        auto issue = [&](int c) {
            int s = c & 1;
            const float* Ap; int lda; const float* Bp;
            if (c < 16) { Ap = fb + c*32; lda = DD; Bp = Ua + (size_t)c*32*AA + n0; }
            else        { Ap = bext;      lda = 32; Bp = g_Qext + n0; }
#pragma unroll
            for (int r = 0; r < 4; r++) {
                int i = t + 256*r;
                int m = i >> 3, k4 = (i & 7) << 2;
                cp_async16(&AsS[s][m*36 + k4], Ap + (size_t)m*lda + k4);
                int kr = i >> 5, n4 = (i & 31) << 2;
                cp_async16(&BsS[s][kr*136 + n4], Bp + (size_t)kr*AA + n4);
            }
            cp_commit();
        };

        issue(0);
        for (int c = 0; c < NCHUNK; c++) {
            if (c + 1 < NCHUNK) { issue(c + 1); cp_wait<1>(); }
            else                { cp_wait<0>(); }
            __syncthreads();
            const float* As_ = AsS[c & 1];
            const float* Bs_ = BsS[c & 1];
#pragma unroll
            for (int kk = 0; kk < 4; kk++) {
                uint32_t af[2][4], bf[8][2];
#pragma unroll
                for (int fm = 0; fm < 2; fm++) {
                    int m0 = wm*32 + fm*16 + qid;
                    af[fm][0] = __float_as_uint(As_[(m0    )*36 + kk*8 + tq    ]);
                    af[fm][1] = __float_as_uint(As_[(m0 + 8)*36 + kk*8 + tq    ]);
                    af[fm][2] = __float_as_uint(As_[(m0    )*36 + kk*8 + tq + 4]);
                    af[fm][3] = __float_as_uint(As_[(m0 + 8)*36 + kk*8 + tq + 4]);
                }
#pragma unroll
                for (int fn = 0; fn < 8; fn++) {
                    int nb = wn*64 + fn*8 + qid;
                    bf[fn][0] = __float_as_uint(Bs_[(kk*8 + tq    )*136 + nb]);
                    bf[fn][1] = __float_as_uint(Bs_[(kk*8 + tq + 4)*136 + nb]);
                }
#pragma unroll
                for (int fm = 0; fm < 2; fm++)
#pragma unroll
                    for (int fn = 0; fn < 8; fn++)
                        mma_tf32(acc[fm][fn], af[fm], bf[fn]);
            }
            __syncthreads();
        }

        // ---- epilogue: tanh + dot with Va ----
#pragma unroll
        for (int fm = 0; fm < 2; fm++)
#pragma unroll
            for (int fn = 0; fn < 8; fn++)
#pragma unroll
                for (int r = 0; r < 4; r++) {
                    int half = r >> 1, j = r & 1;
                    int n = n0 + wn*64 + fn*8 + 2*tq + j;
                    part[fm*2 + half] += fast_tanh(acc[fm][fn][r] + has[n]) * vas[n];
                }
    }

    // ---- cross-warp row reduction ----
    __syncthreads();
#pragma unroll
    for (int p = 0; p < 4; p++) {
        int fm = p >> 1, half = p & 1;
        int rl = wm*32 + fm*16 + half*8 + qid;
        red[rl*9 + wn*4 + tq] = part[p];
    }
    __syncthreads();
    if (t < 128) {
        float s = 0.f;
#pragma unroll
        for (int x = 0; x < 8; x++) s += red[t*9 + x];
        g_logit[b*LL + l0 + t] = s;
    }
}

// ---------------- softmax over L ----------------
__global__ void softmaxL_kernel(float* __restrict__ attn) {
    int b = blockIdx.x, t = threadIdx.x;
    __shared__ float sred[256];
    const float* lg = g_logit + b*LL;
    float mx = -1e30f;
    for (int l = t; l < LL; l += 256) mx = fmaxf(mx, lg[l]);
    sred[t] = mx; __syncthreads();
    for (int s = 128; s > 0; s >>= 1) { if (t < s) sred[t] = fmaxf(sred[t], sred[t+s]); __syncthreads(); }
    mx = sred[0]; __syncthreads();
    float sum = 0.f;
    for (int l = t; l < LL; l += 256) sum += __expf(lg[l] - mx);
    sred[t] = sum; __syncthreads();
    for (int s = 128; s > 0; s >>= 1) { if (t < s) sred[t] += sred[t+s]; __syncthreads(); }
    sum = sred[0]; __syncthreads();
    float inv = 1.f / sum;
    for (int l = t; l < LL; l += 256) attn[b*LL + l] = __expf(lg[l] - mx) * inv;
}

// ---------------- context ----------------
__global__ void ctx_part_kernel(const float* __restrict__ feat, const float* __restrict__ attn) {
    int b = blockIdx.x >> 3, lc = blockIdx.x & 7;
    int d = threadIdx.x;
    const float* fb = feat + (size_t)(b*LL + lc*256) * DD;
    const float* ab = attn + b*LL + lc*256;
    float s = 0.f;
    for (int l = 0; l < 256; l++) s = fmaf(ab[l], fb[(size_t)l*DD + d], s);
    g_ctxpart[lc*(BZ*DD) + b*DD + d] = s;
}
__global__ void ctx_reduce_kernel() {
    int i = blockIdx.x * blockDim.x + threadIdx.x;
    if (i >= BZ*DD) return;
    float s = 0.f;
#pragma unroll
    for (int lc = 0; lc < 8; lc++) s += g_ctxpart[lc*(BZ*DD) + i];
    g_context[i] = s;
}

// ---------------- Ey split-K ----------------
__global__ void ey_part_kernel(const float* __restrict__ pt, const float* __restrict__ We) {
    int n0 = blockIdx.x * 64;
    int kc = blockIdx.y;
    int k0 = kc * 1000;
    int t = threadIdx.x;
    int tx = t & 63, tg = t >> 6;
    float acc[16];
#pragma unroll
    for (int mm = 0; mm < 16; mm++) acc[mm] = 0.f;
    for (int k = 0; k < 1000; k++) {
        float w = We[(size_t)(k0 + k)*EE + n0 + tx];
#pragma unroll
        for (int mm = 0; mm < 16; mm++)
            acc[mm] = fmaf(pt[(size_t)(mm*4 + tg)*VV + k0 + k], w, acc[mm]);
    }
#pragma unroll
    for (int mm = 0; mm < 16; mm++)
        g_eypart[kc*(BZ*EE) + (mm*4 + tg)*EE + n0 + tx] = acc[mm];
}
__global__ void ey_reduce_kernel() {
    int i = blockIdx.x * blockDim.x + threadIdx.x;
    if (i >= BZ*EE) return;
    float s = 0.f;
    for (int kc = 0; kc < 32; kc++) s += g_eypart[kc*(BZ*EE) + i];
    g_Ey[i] = s;
}

// ---------------- elementwise ----------------
__global__ void ht_kernel(const float* __restrict__ h, float* __restrict__ out_ht) {
    int i = blockIdx.x * blockDim.x + threadIdx.x;
    if (i >= BZ*UU) return;
    float z = g_zt[i];
    float v = (1.f - z) * h[i] + z * g_hcand[i];
    g_ht[i] = v;
    out_ht[i] = v;
}

// ---------------- softmax over V ----------------
__global__ void softmaxV_kernel(float* __restrict__ out) {
    int b = blockIdx.x, t = threadIdx.x;
    __shared__ float sred[1024];
    const float* lg = g_vlogits + (size_t)b*VV;
    float mx = -1e30f;
    for (int v = t; v < VV; v += 1024) mx = fmaxf(mx, lg[v]);
    sred[t] = mx; __syncthreads();
    for (int s = 512; s > 0; s >>= 1) { if (t < s) sred[t] = fmaxf(sred[t], sred[t+s]); __syncthreads(); }
    mx = sred[0]; __syncthreads();
    float sum = 0.f;
    for (int v = t; v < VV; v += 1024) sum += __expf(lg[v] - mx);
    sred[t] = sum; __syncthreads();
    for (int s = 512; s > 0; s >>= 1) { if (t < s) sred[t] += sred[t+s]; __syncthreads(); }
    sum = sred[0]; __syncthreads();
    float inv = 1.f / sum;
    for (int v = t; v < VV; v += 1024) out[(size_t)b*VV + v] = __expf(lg[v] - mx) * inv;
}

// ---------------- launch ----------------
extern "C" void kernel_launch(void* const* d_in, const int* in_sizes, int n_in,
                              void* d_out, int out_size)
{
    const float* prev_target = (const float*)d_in[0];
    const float* prev_hidden = (const float*)d_in[1];
    const float* features    = (const float*)d_in[2];
    const float* Bmat        = (const float*)d_in[3];
    const float* Wa          = (const float*)d_in[4];
    const float* Ua          = (const float*)d_in[5];
    const float* Va          = (const float*)d_in[6];
    const float* Uf          = (const float*)d_in[7];
    const float* Qk          = (const float*)d_in[8];
    const float* We          = (const float*)d_in[9];
    const float* Wccz        = (const float*)d_in[10];
    const float* Wyz         = (const float*)d_in[11];
    const float* Uhz         = (const float*)d_in[12];
    const float* Wyr         = (const float*)d_in[13];
    const float* Uhr         = (const float*)d_in[14];
    const float* Ccr         = (const float*)d_in[15];
    const float* Wyh         = (const float*)d_in[16];
    const float* b_wyh       = (const float*)d_in[17];
    const float* Urh         = (const float*)d_in[18];
    const float* b_urh       = (const float*)d_in[19];
    const float* Wo          = (const float*)d_in[20];
    const float* Wh          = (const float*)d_in[21];
    const float* Wc          = (const float*)d_in[22];

    float* out      = (float*)d_out;
    float* out_ht   = (float*)d_out + HT_OFF;
    float* out_attn = (float*)d_out + ATTN_OFF;

    float* pha;   cudaGetSymbolAddress((void**)&pha, g_ha);
    float* pzt;   cudaGetSymbolAddress((void**)&pzt, g_zt);
    float* prt;   cudaGetSymbolAddress((void**)&prt, g_rt);
    float* phc;   cudaGetSymbolAddress((void**)&phc, g_hcand);
    float* pht;   cudaGetSymbolAddress((void**)&pht, g_ht);
    float* pctx;  cudaGetSymbolAddress((void**)&pctx, g_context);
    float* pEy;   cudaGetSymbolAddress((void**)&pEy, g_Ey);
    float* poute; cudaGetSymbolAddress((void**)&poute, g_oute);
    float* pvlog; cudaGetSymbolAddress((void**)&pvlog, g_vlogits);

    cudaFuncSetAttribute(attn_mma_kernel, cudaFuncAttributeMaxDynamicSharedMemorySize, SM_TOTF*4);

    // prep: conv fold
    prep_qext_kernel<<<(32*512 + 255)/256, 256>>>(Qk, Uf);
    prep_bext_kernel<<<(BZ*LL*32 + 255)/256, 256>>>(Bmat);

    // ha = prev_hidden @ Wa
    sgemm3_kernel<<<AA/64, 256>>>(prev_hidden, Wa, UU,
                                  nullptr, nullptr, 0, nullptr,
                                  nullptr, nullptr, 0,
                                  nullptr, nullptr, nullptr, pha, AA, 0);

    // attention logits (pipelined tf32 mma)
    attn_mma_kernel<<<BZ*16, 256, SM_TOTF*4>>>(features, Ua, Va);

    softmaxL_kernel<<<BZ, 256>>>(out_attn);

    ctx_part_kernel<<<BZ*8, 512>>>(features, out_attn);
    ctx_reduce_kernel<<<(BZ*DD + 255)/256, 256>>>();

    { dim3 g(4, 32); ey_part_kernel<<<g, 256>>>(prev_target, We); }
    ey_reduce_kernel<<<(BZ*EE + 255)/256, 256>>>();

    // zt = sigmoid(Ey@Wyz + h@Uhz + ctx@Wccz)
    sgemm3_kernel<<<UU/64, 256>>>(pEy, Wyz, EE,
                                  prev_hidden, Uhz, UU, nullptr,
                                  pctx, Wccz, DD,
                                  nullptr, nullptr, nullptr, pzt, UU, 1);

    // rt = sigmoid(Ey@Wyr + h@Uhr + ctx@Ccr)
    sgemm3_kernel<<<UU/64, 256>>>(pEy, Wyr, EE,
                                  prev_hidden, Uhr, UU, nullptr,
                                  pctx, Ccr, DD,
                                  nullptr, nullptr, nullptr, prt, UU, 1);

    // hcand = tanh(Ey@Wyh + (rt*h)@Urh + ctx@Wccz + b_wyh + b_urh)
    sgemm3_kernel<<<UU/64, 256>>>(pEy, Wyh, EE,
                                  prev_hidden, Urh, UU, prt,
                                  pctx, Wccz, DD,
                                  b_wyh, b_urh, nullptr, phc, UU, 2);

    ht_kernel<<<(BZ*UU + 255)/256, 256>>>(prev_hidden, out_ht);

    // out_e = Ey + ht@Wh + ctx@Wc
    sgemm3_kernel<<<EE/64, 256>>>(pht, Wh, UU,
                                  pctx, Wc, DD, nullptr,
                                  nullptr, nullptr, 0,
                                  nullptr, nullptr, pEy, poute, EE, 0);

    // vlogits = out_e @ Wo
    sgemm3_kernel<<<VV/64, 256>>>(poute, Wo, EE,
                                  nullptr, nullptr, 0, nullptr,
                                  nullptr, nullptr, 0,
                                  nullptr, nullptr, nullptr, pvlog, VV, 0);

    softmaxV_kernel<<<BZ, 1024>>>(out);
}

// round 6
// speedup vs baseline: 4.5113x; 2.3599x over previous
#include <cuda_runtime.h>
#include <cstdint>

// ---------------- shapes ----------------
#define BZ 64
#define LL 2048
#define DD 512
#define UU 512
#define AA 512
#define KK 64
#define VV 32000
#define EE 256
#define QW 7

#define HT_OFF  (BZ*VV)
#define ATTN_OFF (BZ*VV + BZ*UU)

#define EY_SPLIT 125   // 32000 / 256
#define CTX_SPLIT 16

// ---------------- scratch ----------------
__device__ float g_Bext[BZ*LL*32];
__device__ float g_Qext[32*512];
__device__ float g_ha[BZ*AA];
__device__ float g_logit[BZ*LL];
__device__ float g_ctxpart[CTX_SPLIT*BZ*DD];
__device__ float g_context[BZ*DD];
__device__ float g_eypart[EY_SPLIT*BZ*EE];
__device__ float g_Ey[BZ*EE];
__device__ float g_zt[BZ*UU];
__device__ float g_rt[BZ*UU];
__device__ float g_ht[BZ*UU];
__device__ float g_oute[BZ*EE];
__device__ float g_vlogits[BZ*VV];

// ---------------- cp.async helpers ----------------
__device__ __forceinline__ void cp_async16(void* smem, const void* gmem) {
    unsigned sa = (unsigned)__cvta_generic_to_shared(smem);
    asm volatile("cp.async.cg.shared.global [%0], [%1], 16;" :: "r"(sa), "l"(gmem));
}
__device__ __forceinline__ void cp_commit() { asm volatile("cp.async.commit_group;"); }
template<int N> __device__ __forceinline__ void cp_wait() {
    asm volatile("cp.async.wait_group %0;" :: "n"(N));
}

// ---------------- merged prep: Qext | Bext | ha ----------------
// blocks [0,64): Qext.  [64, 64+16384): Bext.  [16448, 16512): ha (one per b).
__global__ void prep_all_kernel(const float* __restrict__ Qk, const float* __restrict__ Uf,
                                const float* __restrict__ Bm,
                                const float* __restrict__ h,  const float* __restrict__ Wa)
{
    __shared__ float hs[UU];
    int bx = blockIdx.x, t = threadIdx.x;
    if (bx < 64) {
        int i = bx*256 + t;                 // 16384 elems of g_Qext
        int w = i >> 9, a = i & 511;
        float s = 0.f;
        if (w < QW)
            for (int k = 0; k < KK; k++) s = fmaf(Qk[w*KK + k], Uf[k*AA + a], s);
        g_Qext[i] = s;
    } else if (bx < 64 + 16384) {
        int i = (bx - 64)*256 + t;          // BZ*LL*32 elems
        int j = i & 31;
        int l = (i >> 5) & (LL-1);
        int b = i >> 16;
        int ls = l + j - 3;
        g_Bext[i] = (j < QW && ls >= 0 && ls < LL) ? Bm[b*LL + ls] : 0.f;
    } else {
        int b = bx - 16448;
        for (int i = t; i < UU; i += 256) hs[i] = h[b*UU + i];
        __syncthreads();
        float a0 = 0.f, a1 = 0.f;
        for (int k = 0; k < UU; k++) {
            float hv = hs[k];
            a0 = fmaf(hv, Wa[k*AA + t],       a0);
            a1 = fmaf(hv, Wa[k*AA + t + 256], a1);
        }
        g_ha[b*AA + t]       = a0;
        g_ha[b*AA + t + 256] = a1;
    }
}

// ---------------- generic small GEMM with register double-buffering ----------------
// C(64xN) = act( A0@B0 + (A1.*Amul1)@B1 + A2@B2 + biases + addm )
__global__ void sgemm3v2_kernel(const float* __restrict__ A0, const float* __restrict__ B0, int K0,
                                const float* __restrict__ A1, const float* __restrict__ B1, int K1,
                                const float* __restrict__ Amul1,
                                const float* __restrict__ A2, const float* __restrict__ B2, int K2,
                                const float* __restrict__ bias1, const float* __restrict__ bias2,
                                const float* __restrict__ addm,
                                float* __restrict__ C, int N, int act)
{
    __shared__ float As[64][33];
    __shared__ float Bs[32][64];
    int t = threadIdx.x;
    int tx = t & 15, ty = t >> 4;
    int n0 = blockIdx.x * 64;

    float acc[4][4];
#pragma unroll
    for (int i = 0; i < 4; i++)
#pragma unroll
        for (int j = 0; j < 4; j++) acc[i][j] = 0.f;

    const float* Aps[3] = {A0, A1, A2};
    const float* Bps[3] = {B0, B1, B2};
    const float* Mps[3] = {nullptr, Amul1, nullptr};
    int Ks[3] = {K0, K1, K2};

    for (int p = 0; p < 3; p++) {
        const float* A = Aps[p];
        if (A == nullptr) continue;
        const float* Bm = Bps[p];
        const float* Mu = Mps[p];
        int K = Ks[p];

        float ar[8], br[8];
#pragma unroll
        for (int r = 0; r < 8; r++) {
            int e = t + 256*r;
            int m = e >> 5, k = e & 31;
            float v = A[m*K + k];
            if (Mu) v *= Mu[m*K + k];
            ar[r] = v;
            int kb = e >> 6, n = e & 63;
            br[r] = Bm[(size_t)kb*N + n0 + n];
        }
        for (int kc = 0; kc < K; kc += 32) {
            __syncthreads();
#pragma unroll
            for (int r = 0; r < 8; r++) {
                int e = t + 256*r;
                As[e >> 5][e & 31] = ar[r];
                Bs[e >> 6][e & 63] = br[r];
            }
            __syncthreads();
            if (kc + 32 < K) {
#pragma unroll
                for (int r = 0; r < 8; r++) {
                    int e = t + 256*r;
                    int m = e >> 5, k = e & 31;
                    float v = A[m*K + kc + 32 + k];
                    if (Mu) v *= Mu[m*K + kc + 32 + k];
                    ar[r] = v;
                    int kb = e >> 6, n = e & 63;
                    br[r] = Bm[(size_t)(kc + 32 + kb)*N + n0 + n];
                }
            }
#pragma unroll
            for (int k = 0; k < 32; k++) {
                float a[4];
#pragma unroll
                for (int i = 0; i < 4; i++) a[i] = As[ty*4 + i][k];
                float4 bv = *(const float4*)&Bs[k][tx*4];
                float bj[4] = {bv.x, bv.y, bv.z, bv.w};
#pragma unroll
                for (int i = 0; i < 4; i++)
#pragma unroll
                    for (int j = 0; j < 4; j++) acc[i][j] = fmaf(a[i], bj[j], acc[i][j]);
            }
        }
    }

#pragma unroll
    for (int i = 0; i < 4; i++) {
        int m = ty*4 + i;
#pragma unroll
        for (int j = 0; j < 4; j++) {
            int n = n0 + tx*4 + j;
            float v = acc[i][j];
            if (bias1) v += bias1[n];
            if (bias2) v += bias2[n];
            if (addm)  v += addm[m*N + n];
            if (act == 1) v = 1.f / (1.f + __expf(-v));
            else if (act == 2) v = tanhf(v);
            C[m*N + n] = v;
        }
    }
}

// ---------------- fused zt & rt: grid (8, 2) ----------------
__global__ void gates_zr_kernel(const float* __restrict__ Ey, const float* __restrict__ h,
                                const float* __restrict__ ctx,
                                const float* __restrict__ Wyz, const float* __restrict__ Uhz,
                                const float* __restrict__ Wccz,
                                const float* __restrict__ Wyr, const float* __restrict__ Uhr,
                                const float* __restrict__ Ccr)
{
    __shared__ float As[64][33];
    __shared__ float Bs[32][64];
    int t = threadIdx.x;
    int tx = t & 15, ty = t >> 4;
    int n0 = blockIdx.x * 64;
    int gate = blockIdx.y;

    const float* Aps[3] = {Ey, h, ctx};
    const float* Bps[3];
    if (gate == 0) { Bps[0] = Wyz; Bps[1] = Uhz; Bps[2] = Wccz; }
    else           { Bps[0] = Wyr; Bps[1] = Uhr; Bps[2] = Ccr; }
    int Ks[3] = {EE, UU, DD};
    float* C = gate ? g_rt : g_zt;

    float acc[4][4];
#pragma unroll
    for (int i = 0; i < 4; i++)
#pragma unroll
        for (int j = 0; j < 4; j++) acc[i][j] = 0.f;

    for (int p = 0; p < 3; p++) {
        const float* A = Aps[p];
        const float* Bm = Bps[p];
        int K = Ks[p];
        float ar[8], br[8];
#pragma unroll
        for (int r = 0; r < 8; r++) {
            int e = t + 256*r;
            ar[r] = A[(e >> 5)*K + (e & 31)];
            br[r] = Bm[(size_t)(e >> 6)*UU + n0 + (e & 63)];
        }
        for (int kc = 0; kc < K; kc += 32) {
            __syncthreads();
#pragma unroll
            for (int r = 0; r < 8; r++) {
                int e = t + 256*r;
                As[e >> 5][e & 31] = ar[r];
                Bs[e >> 6][e & 63] = br[r];
            }
            __syncthreads();
            if (kc + 32 < K) {
#pragma unroll
                for (int r = 0; r < 8; r++) {
                    int e = t + 256*r;
                    ar[r] = A[(e >> 5)*K + kc + 32 + (e & 31)];
                    br[r] = Bm[(size_t)(kc + 32 + (e >> 6))*UU + n0 + (e & 63)];
                }
            }
#pragma unroll
            for (int k = 0; k < 32; k++) {
                float a[4];
#pragma unroll
                for (int i = 0; i < 4; i++) a[i] = As[ty*4 + i][k];
                float4 bv = *(const float4*)&Bs[k][tx*4];
                float bj[4] = {bv.x, bv.y, bv.z, bv.w};
#pragma unroll
                for (int i = 0; i < 4; i++)
#pragma unroll
                    for (int j = 0; j < 4; j++) acc[i][j] = fmaf(a[i], bj[j], acc[i][j]);
            }
        }
    }
#pragma unroll
    for (int i = 0; i < 4; i++) {
        int m = ty*4 + i;
#pragma unroll
        for (int j = 0; j < 4; j++) {
            int n = n0 + tx*4 + j;
            C[m*UU + n] = 1.f / (1.f + __expf(-acc[i][j]));
        }
    }
}

// ---------------- hcand + ht fused ----------------
__global__ void hcand_ht_kernel(const float* __restrict__ Ey, const float* __restrict__ h,
                                const float* __restrict__ ctx,
                                const float* __restrict__ Wyh, const float* __restrict__ Urh,
                                const float* __restrict__ Wccz,
                                const float* __restrict__ b_wyh, const float* __restrict__ b_urh,
                                float* __restrict__ out_ht)
{
    __shared__ float As[64][33];
    __shared__ float Bs[32][64];
    int t = threadIdx.x;
    int tx = t & 15, ty = t >> 4;
    int n0 = blockIdx.x * 64;

    const float* Aps[3] = {Ey, h, ctx};
    const float* Bps[3] = {Wyh, Urh, Wccz};
    int Ks[3] = {EE, UU, DD};

    float acc[4][4];
#pragma unroll
    for (int i = 0; i < 4; i++)
#pragma unroll
        for (int j = 0; j < 4; j++) acc[i][j] = 0.f;

    for (int p = 0; p < 3; p++) {
        const float* A = Aps[p];
        const float* Bm = Bps[p];
        int K = Ks[p];
        bool mul = (p == 1);
        float ar[8], br[8];
#pragma unroll
        for (int r = 0; r < 8; r++) {
            int e = t + 256*r;
            int m = e >> 5, k = e & 31;
            float v = A[m*K + k];
            if (mul) v *= g_rt[m*UU + k];
            ar[r] = v;
            br[r] = Bm[(size_t)(e >> 6)*UU + n0 + (e & 63)];
        }
        for (int kc = 0; kc < K; kc += 32) {
            __syncthreads();
#pragma unroll
            for (int r = 0; r < 8; r++) {
                int e = t + 256*r;
                As[e >> 5][e & 31] = ar[r];
                Bs[e >> 6][e & 63] = br[r];
            }
            __syncthreads();
            if (kc + 32 < K) {
#pragma unroll
                for (int r = 0; r < 8; r++) {
                    int e = t + 256*r;
                    int m = e >> 5, k = kc + 32 + (e & 31);
                    float v = A[m*K + k];
                    if (mul) v *= g_rt[m*UU + k];
                    ar[r] = v;
                    br[r] = Bm[(size_t)(kc + 32 + (e >> 6))*UU + n0 + (e & 63)];
                }
            }
#pragma unroll
            for (int k = 0; k < 32; k++) {
                float a[4];
#pragma unroll
                for (int i = 0; i < 4; i++) a[i] = As[ty*4 + i][k];
                float4 bv = *(const float4*)&Bs[k][tx*4];
                float bj[4] = {bv.x, bv.y, bv.z, bv.w};
#pragma unroll
                for (int i = 0; i < 4; i++)
#pragma unroll
                    for (int j = 0; j < 4; j++) acc[i][j] = fmaf(a[i], bj[j], acc[i][j]);
            }
        }
    }
#pragma unroll
    for (int i = 0; i < 4; i++) {
        int m = ty*4 + i;
#pragma unroll
        for (int j = 0; j < 4; j++) {
            int n = n0 + tx*4 + j;
            float hc = tanhf(acc[i][j] + b_wyh[n] + b_urh[n]);
            float z  = g_zt[m*UU + n];
            float v  = (1.f - z) * h[m*UU + n] + z * hc;
            g_ht[m*UU + n] = v;
            out_ht[m*UU + n] = v;
        }
    }
}

// ---------------- tf32 mma ----------------
__device__ __forceinline__ void mma_tf32(float* c, const uint32_t* a, const uint32_t* b) {
    asm volatile(
        "mma.sync.aligned.m16n8k8.row.col.f32.tf32.tf32.f32 "
        "{%0,%1,%2,%3}, {%4,%5,%6,%7}, {%8,%9}, {%0,%1,%2,%3};"
        : "+f"(c[0]), "+f"(c[1]), "+f"(c[2]), "+f"(c[3])
        : "r"(a[0]), "r"(a[1]), "r"(a[2]), "r"(a[3]), "r"(b[0]), "r"(b[1]));
}
__device__ __forceinline__ float fast_tanh(float x) {
    x = fminf(fmaxf(x, -15.f), 15.f);
    float e = __expf(2.f * x);
    return (e - 1.f) / (e + 1.f);
}

// ---------------- attention logits: 3-stage pipelined tf32 HMMA ----------------
#define NCHUNK 17
#define STGF 8960            // floats per stage: As 128x36 + Bs 32x136
#define SM_HAS (3*STGF)      // 26880
#define SM_VAS (SM_HAS+512)
#define SM_TOTF (SM_VAS+512) // 27904 floats = 111616 B

__global__ __launch_bounds__(256, 2)
void attn_mma_kernel(const float* __restrict__ feat,
                     const float* __restrict__ Ua,
                     const float* __restrict__ Va)
{
    extern __shared__ float sm[];
    float* has = sm + SM_HAS;
    float* vas = sm + SM_VAS;

    int t = threadIdx.x;
    int lane = t & 31, wid = t >> 5;
    int wm = wid & 3, wn = wid >> 2;
    int qid = lane >> 2, tq = lane & 3;

    int b  = blockIdx.x >> 4;
    int l0 = (blockIdx.x & 15) << 7;

    for (int i = t; i < AA; i += 256) { has[i] = g_ha[b*AA + i]; vas[i] = Va[i]; }

    const float* fb   = feat   + (size_t)(b*LL + l0) * DD;
    const float* bext = g_Bext + (size_t)(b*LL + l0) * 32;

    float part[4] = {0.f, 0.f, 0.f, 0.f};

    int phase = 0;
    for (int n0 = 0; n0 < AA; n0 += 128) {
        float acc[2][8][4];
#pragma unroll
        for (int i = 0; i < 2; i++)
#pragma unroll
            for (int j = 0; j < 8; j++)
#pragma unroll
                for (int r = 0; r < 4; r++) acc[i][j][r] = 0.f;

        auto issue = [&](int c) {
            int s = (phase + c) % 3;
            float* As_ = sm + s*STGF;
            float* Bs_ = As_ + 4608;
            const float* Ap; int lda; const float* Bp;
            if (c < 16) { Ap = fb + c*32; lda = DD; Bp = Ua + (size_t)c*32*AA + n0; }
            else        { Ap = bext;      lda = 32; Bp = g_Qext + n0; }
#pragma unroll
            for (int r = 0; r < 4; r++) {
                int i = t + 256*r;
                int m = i >> 3, k4 = (i & 7) << 2;
                cp_async16(&As_[m*36 + k4], Ap + (size_t)m*lda + k4);
                int kr = i >> 5, n4 = (i & 31) << 2;
                cp_async16(&Bs_[kr*136 + n4], Bp + (size_t)kr*AA + n4);
            }
            cp_commit();
        };

        issue(0); issue(1);
        for (int c = 0; c < NCHUNK; c++) {
            if (c == NCHUNK-1) cp_wait<0>(); else cp_wait<1>();
            __syncthreads();
            if (c + 2 < NCHUNK) issue(c + 2);
            int s = (phase + c) % 3;
            const float* As_ = sm + s*STGF;
            const float* Bs_ = As_ + 4608;
#pragma unroll
            for (int kk = 0; kk < 4; kk++) {
                uint32_t af[2][4], bf[8][2];
#pragma unroll
                for (int fm = 0; fm < 2; fm++) {
                    int m0 = wm*32 + fm*16 + qid;
                    af[fm][0] = __float_as_uint(As_[(m0    )*36 + kk*8 + tq    ]);
                    af[fm][1] = __float_as_uint(As_[(m0 + 8)*36 + kk*8 + tq    ]);
                    af[fm][2] = __float_as_uint(As_[(m0    )*36 + kk*8 + tq + 4]);
                    af[fm][3] = __float_as_uint(As_[(m0 + 8)*36 + kk*8 + tq + 4]);
                }
#pragma unroll
                for (int fn = 0; fn < 8; fn++) {
                    int nb = wn*64 + fn*8 + qid;
                    bf[fn][0] = __float_as_uint(Bs_[(kk*8 + tq    )*136 + nb]);
                    bf[fn][1] = __float_as_uint(Bs_[(kk*8 + tq + 4)*136 + nb]);
                }
#pragma unroll
                for (int fm = 0; fm < 2; fm++)
#pragma unroll
                    for (int fn = 0; fn < 8; fn++)
                        mma_tf32(acc[fm][fn], af[fm], bf[fn]);
            }
        }
        phase = (phase + NCHUNK) % 3;

#pragma unroll
        for (int fm = 0; fm < 2; fm++)
#pragma unroll
            for (int fn = 0; fn < 8; fn++)
#pragma unroll
                for (int r = 0; r < 4; r++) {
                    int half = r >> 1, j = r & 1;
                    int n = n0 + wn*64 + fn*8 + 2*tq + j;
                    part[fm*2 + half] += fast_tanh(acc[fm][fn][r] + has[n]) * vas[n];
                }
    }

    // cross-warp row reduction (red aliased onto stage 0)
    float* red = sm;   // [128][9]
    __syncthreads();
#pragma unroll
    for (int p = 0; p < 4; p++) {
        int fm = p >> 1, half = p & 1;
        int rl = wm*32 + fm*16 + half*8 + qid;
        red[rl*9 + wn*4 + tq] = part[p];
    }
    __syncthreads();
    if (t < 128) {
        float s = 0.f;
#pragma unroll
        for (int x = 0; x < 8; x++) s += red[t*9 + x];
        g_logit[b*LL + l0 + t] = s;
    }
}

// ---------------- softmax over L ----------------
__global__ void softmaxL_kernel(float* __restrict__ attn) {
    int b = blockIdx.x, t = threadIdx.x;
    __shared__ float sred[256];
    const float* lg = g_logit + b*LL;
    float mx = -1e30f;
    for (int l = t; l < LL; l += 256) mx = fmaxf(mx, lg[l]);
    sred[t] = mx; __syncthreads();
    for (int s = 128; s > 0; s >>= 1) { if (t < s) sred[t] = fmaxf(sred[t], sred[t+s]); __syncthreads(); }
    mx = sred[0]; __syncthreads();
    float sum = 0.f;
    for (int l = t; l < LL; l += 256) sum += __expf(lg[l] - mx);
    sred[t] = sum; __syncthreads();
    for (int s = 128; s > 0; s >>= 1) { if (t < s) sred[t] += sred[t+s]; __syncthreads(); }
    sum = sred[0]; __syncthreads();
    float inv = 1.f / sum;
    for (int l = t; l < LL; l += 256) attn[b*LL + l] = __expf(lg[l] - mx) * inv;
}

// ---------------- context ----------------
__global__ void ctx_part_kernel(const float* __restrict__ feat, const float* __restrict__ attn) {
    int b = blockIdx.x >> 4, lc = blockIdx.x & 15;
    int d = threadIdx.x;
    const float* fb = feat + (size_t)(b*LL + lc*128) * DD;
    const float* ab = attn + b*LL + lc*128;
    float s = 0.f;
#pragma unroll 4
    for (int l = 0; l < 128; l++) s = fmaf(ab[l], fb[(size_t)l*DD + d], s);
    g_ctxpart[lc*(BZ*DD) + b*DD + d] = s;
}
__global__ void ctx_reduce_kernel() {
    int i = blockIdx.x * blockDim.x + threadIdx.x;
    if (i >= BZ*DD) return;
    float s = 0.f;
#pragma unroll
    for (int lc = 0; lc < CTX_SPLIT; lc++) s += g_ctxpart[lc*(BZ*DD) + i];
    g_context[i] = s;
}

// ---------------- Ey: smem-staged split-K ----------------
__global__ void ey_part_kernel(const float* __restrict__ pt, const float* __restrict__ We) {
    extern __shared__ float pts[];   // [64][256]
    int kc = blockIdx.x;
    int k0 = kc * 256;
    int t = threadIdx.x;

    // stage pt chunk: 64 rows x 256 cols
    for (int i = t; i < 64*64; i += 256) {          // float4 count = 4096
        int m = i >> 6, c4 = (i & 63) << 2;
        float4 v = *(const float4*)&pt[(size_t)m*VV + k0 + c4];
        *(float4*)&pts[m*256 + c4] = v;
    }
    __syncthreads();

    int tx = t & 63, tg = t >> 6;
    int n4 = tx * 4;
    float4 acc[16];
#pragma unroll
    for (int mm = 0; mm < 16; mm++) acc[mm] = make_float4(0.f, 0.f, 0.f, 0.f);

    for (int k = 0; k < 256; k++) {
        float4 w = *(const float4*)&We[(size_t)(k0 + k)*EE + n4];
#pragma unroll
        for (int mm = 0; mm < 16; mm++) {
            float a = pts[(tg*16 + mm)*256 + k];
            acc[mm].x = fmaf(a, w.x, acc[mm].x);
            acc[mm].y = fmaf(a, w.y, acc[mm].y);
            acc[mm].z = fmaf(a, w.z, acc[mm].z);
            acc[mm].w = fmaf(a, w.w, acc[mm].w);
        }
    }
#pragma unroll
    for (int mm = 0; mm < 16; mm++)
        *(float4*)&g_eypart[(size_t)kc*(BZ*EE) + (tg*16 + mm)*EE + n4] = acc[mm];
}
__global__ void ey_reduce_kernel() {
    int i = blockIdx.x * blockDim.x + threadIdx.x;
    if (i >= BZ*EE) return;
    float s = 0.f;
    for (int kc = 0; kc < EY_SPLIT; kc++) s += g_eypart[(size_t)kc*(BZ*EE) + i];
    g_Ey[i] = s;
}

// ---------------- softmax over V (smem-cached) ----------------
__global__ void softmaxV_kernel(float* __restrict__ out) {
    extern __shared__ float row[];   // 32000 floats
    int b = blockIdx.x, t = threadIdx.x;
    __shared__ float sred[1024];
    const float4* lg4 = (const float4*)(g_vlogits + (size_t)b*VV);

    float mx = -1e30f;
    for (int i = t; i < VV/4; i += 1024) {
        float4 v = lg4[i];
        *(float4*)&row[i*4] = v;
        mx = fmaxf(fmaxf(mx, v.x), fmaxf(v.y, fmaxf(v.z, v.w)));
    }
    sred[t] = mx; __syncthreads();
    for (int s = 512; s > 0; s >>= 1) { if (t < s) sred[t] = fmaxf(sred[t], sred[t+s]); __syncthreads(); }
    mx = sred[0]; __syncthreads();

    float sum = 0.f;
    for (int v = t; v < VV; v += 1024) sum += __expf(row[v] - mx);
    sred[t] = sum; __syncthreads();
    for (int s = 512; s > 0; s >>= 1) { if (t < s) sred[t] += sred[t+s]; __syncthreads(); }
    sum = sred[0]; __syncthreads();

    float inv = 1.f / sum;
    float4* o4 = (float4*)(out + (size_t)b*VV);
    for (int i = t; i < VV/4; i += 1024) {
        float4 v = *(float4*)&row[i*4];
        v.x = __expf(v.x - mx) * inv;
        v.y = __expf(v.y - mx) * inv;
        v.z = __expf(v.z - mx) * inv;
        v.w = __expf(v.w - mx) * inv;
        o4[i] = v;
    }
}

// ---------------- launch ----------------
extern "C" void kernel_launch(void* const* d_in, const int* in_sizes, int n_in,
                              void* d_out, int out_size)
{
    const float* prev_target = (const float*)d_in[0];
    const float* prev_hidden = (const float*)d_in[1];
    const float* features    = (const float*)d_in[2];
    const float* Bmat        = (const float*)d_in[3];
    const float* Wa          = (const float*)d_in[4];
    const float* Ua          = (const float*)d_in[5];
    const float* Va          = (const float*)d_in[6];
    const float* Uf          = (const float*)d_in[7];
    const float* Qk          = (const float*)d_in[8];
    const float* We          = (const float*)d_in[9];
    const float* Wccz        = (const float*)d_in[10];
    const float* Wyz         = (const float*)d_in[11];
    const float* Uhz         = (const float*)d_in[12];
    const float* Wyr         = (const float*)d_in[13];
    const float* Uhr         = (const float*)d_in[14];
    const float* Ccr         = (const float*)d_in[15];
    const float* Wyh         = (const float*)d_in[16];
    const float* b_wyh       = (const float*)d_in[17];
    const float* Urh         = (const float*)d_in[18];
    const float* b_urh       = (const float*)d_in[19];
    const float* Wo          = (const float*)d_in[20];
    const float* Wh          = (const float*)d_in[21];
    const float* Wc          = (const float*)d_in[22];

    float* out      = (float*)d_out;
    float* out_ht   = (float*)d_out + HT_OFF;
    float* out_attn = (float*)d_out + ATTN_OFF;

    float* pctx;  cudaGetSymbolAddress((void**)&pctx, g_context);
    float* pEy;   cudaGetSymbolAddress((void**)&pEy, g_Ey);
    float* pht;   cudaGetSymbolAddress((void**)&pht, g_ht);
    float* poute; cudaGetSymbolAddress((void**)&poute, g_oute);
    float* pvlog; cudaGetSymbolAddress((void**)&pvlog, g_vlogits);

    cudaFuncSetAttribute(attn_mma_kernel, cudaFuncAttributeMaxDynamicSharedMemorySize, SM_TOTF*4);
    cudaFuncSetAttribute(ey_part_kernel, cudaFuncAttributeMaxDynamicSharedMemorySize, 64*256*4);
    cudaFuncSetAttribute(softmaxV_kernel, cudaFuncAttributeMaxDynamicSharedMemorySize, VV*4);

    // 1. prep (Qext | Bext | ha)
    prep_all_kernel<<<64 + 16384 + 64, 256>>>(Qk, Uf, Bmat, prev_hidden, Wa);

    // 2. Ey (independent branch)
    ey_part_kernel<<<EY_SPLIT, 256, 64*256*4>>>(prev_target, We);
    ey_reduce_kernel<<<(BZ*EE + 255)/256, 256>>>();

    // 3. attention logits
    attn_mma_kernel<<<BZ*16, 256, SM_TOTF*4>>>(features, Ua, Va);

    // 4. softmax over L -> attn (d_out)
    softmaxL_kernel<<<BZ, 256>>>(out_attn);

    // 5. context
    ctx_part_kernel<<<BZ*CTX_SPLIT, 512>>>(features, out_attn);
    ctx_reduce_kernel<<<(BZ*DD + 255)/256, 256>>>();

    // 6. zt & rt (one launch)
    { dim3 g(UU/64, 2); gates_zr_kernel<<<g, 256>>>(pEy, prev_hidden, pctx,
                                                    Wyz, Uhz, Wccz, Wyr, Uhr, Ccr); }

    // 7. hcand + ht
    hcand_ht_kernel<<<UU/64, 256>>>(pEy, prev_hidden, pctx, Wyh, Urh, Wccz,
                                    b_wyh, b_urh, out_ht);

    // 8. oute = Ey + ht@Wh + ctx@Wc
    sgemm3v2_kernel<<<EE/64, 256>>>(pht, Wh, UU,
                                    pctx, Wc, DD, nullptr,
                                    nullptr, nullptr, 0,
                                    nullptr, nullptr, pEy, poute, EE, 0);

    // 9. vlogits = oute @ Wo
    sgemm3v2_kernel<<<VV/64, 256>>>(poute, Wo, EE,
                                    nullptr, nullptr, 0, nullptr,
                                    nullptr, nullptr, 0,
                                    nullptr, nullptr, nullptr, pvlog, VV, 0);

    // 10. softmax over V -> out
    softmaxV_kernel<<<BZ, 1024, VV*4>>>(out);
}

// round 8
// speedup vs baseline: 4.6962x; 1.0410x over previous
#include <cuda_runtime.h>
#include <cstdint>

// ---------------- shapes ----------------
#define BZ 64
#define LL 2048
#define DD 512
#define UU 512
#define AA 512
#define KK 64
#define VV 32000
#define EE 256
#define QW 7

#define HT_OFF  (BZ*VV)
#define ATTN_OFF (BZ*VV + BZ*UU)

#define EY_SPLIT 125
#define CTX_SPLIT 16

// ---------------- scratch ----------------
__device__ float g_Bext[BZ*LL*32];
__device__ float g_Qext[32*512];
__device__ float g_ha[BZ*AA];
__device__ float g_logitpart[4*BZ*LL];
__device__ float g_logit[BZ*LL];
__device__ float g_ctxpart[CTX_SPLIT*BZ*DD];
__device__ float g_context[BZ*DD];
__device__ float g_eypart[EY_SPLIT*BZ*EE];
__device__ float g_Ey[BZ*EE];
__device__ float g_zt[BZ*UU];
__device__ float g_rt[BZ*UU];
__device__ float g_ht[BZ*UU];
__device__ float g_oute[BZ*EE];
__device__ float g_vlogits[BZ*VV];

// ---------------- cp.async helpers ----------------
__device__ __forceinline__ void cp_async16(void* smem, const void* gmem) {
    unsigned sa = (unsigned)__cvta_generic_to_shared(smem);
    asm volatile("cp.async.cg.shared.global [%0], [%1], 16;" :: "r"(sa), "l"(gmem));
}
__device__ __forceinline__ void cp_commit() { asm volatile("cp.async.commit_group;"); }
template<int N> __device__ __forceinline__ void cp_wait() {
    asm volatile("cp.async.wait_group %0;" :: "n"(N));
}

// ---------------- merged prep: Qext | Bext | ha ----------------
__global__ void prep_all_kernel(const float* __restrict__ Qk, const float* __restrict__ Uf,
                                const float* __restrict__ Bm,
                                const float* __restrict__ h,  const float* __restrict__ Wa)
{
    __shared__ float hs[UU];
    int bx = blockIdx.x, t = threadIdx.x;
    if (bx < 64) {
        int i = bx*256 + t;
        int w = i >> 9, a = i & 511;
        float s = 0.f;
        if (w < QW)
            for (int k = 0; k < KK; k++) s = fmaf(Qk[w*KK + k], Uf[k*AA + a], s);
        g_Qext[i] = s;
    } else if (bx < 64 + 16384) {
        int i = (bx - 64)*256 + t;
        int j = i & 31;
        int l = (i >> 5) & (LL-1);
        int b = i >> 16;
        int ls = l + j - 3;
        g_Bext[i] = (j < QW && ls >= 0 && ls < LL) ? Bm[b*LL + ls] : 0.f;
    } else {
        int b = bx - 16448;
        for (int i = t; i < UU; i += 256) hs[i] = h[b*UU + i];
        __syncthreads();
        float a0 = 0.f, a1 = 0.f;
        for (int k = 0; k < UU; k++) {
            float hv = hs[k];
            a0 = fmaf(hv, Wa[k*AA + t],       a0);
            a1 = fmaf(hv, Wa[k*AA + t + 256], a1);
        }
        g_ha[b*AA + t]       = a0;
        g_ha[b*AA + t + 256] = a1;
    }
}

// ---------------- generic small GEMM with register double-buffering ----------------
__global__ void sgemm3v2_kernel(const float* __restrict__ A0, const float* __restrict__ B0, int K0,
                                const float* __restrict__ A1, const float* __restrict__ B1, int K1,
                                const float* __restrict__ Amul1,
                                const float* __restrict__ A2, const float* __restrict__ B2, int K2,
                                const float* __restrict__ bias1, const float* __restrict__ bias2,
                                const float* __restrict__ addm,
                                float* __restrict__ C, int N, int act)
{
    __shared__ float As[64][33];
    __shared__ float Bs[32][64];
    int t = threadIdx.x;
    int tx = t & 15, ty = t >> 4;
    int n0 = blockIdx.x * 64;

    float acc[4][4];
#pragma unroll
    for (int i = 0; i < 4; i++)
#pragma unroll
        for (int j = 0; j < 4; j++) acc[i][j] = 0.f;

    const float* Aps[3] = {A0, A1, A2};
    const float* Bps[3] = {B0, B1, B2};
    const float* Mps[3] = {nullptr, Amul1, nullptr};
    int Ks[3] = {K0, K1, K2};

    for (int p = 0; p < 3; p++) {
        const float* A = Aps[p];
        if (A == nullptr) continue;
        const float* Bm = Bps[p];
        const float* Mu = Mps[p];
        int K = Ks[p];

        float ar[8], br[8];
#pragma unroll
        for (int r = 0; r < 8; r++) {
            int e = t + 256*r;
            int m = e >> 5, k = e & 31;
            float v = A[m*K + k];
            if (Mu) v *= Mu[m*K + k];
            ar[r] = v;
            int kb = e >> 6, n = e & 63;
            br[r] = Bm[(size_t)kb*N + n0 + n];
        }
        for (int kc = 0; kc < K; kc += 32) {
            __syncthreads();
#pragma unroll
            for (int r = 0; r < 8; r++) {
                int e = t + 256*r;
                As[e >> 5][e & 31] = ar[r];
                Bs[e >> 6][e & 63] = br[r];
            }
            __syncthreads();
            if (kc + 32 < K) {
#pragma unroll
                for (int r = 0; r < 8; r++) {
                    int e = t + 256*r;
                    int m = e >> 5, k = e & 31;
                    float v = A[m*K + kc + 32 + k];
                    if (Mu) v *= Mu[m*K + kc + 32 + k];
                    ar[r] = v;
                    int kb = e >> 6, n = e & 63;
                    br[r] = Bm[(size_t)(kc + 32 + kb)*N + n0 + n];
                }
            }
#pragma unroll
            for (int k = 0; k < 32; k++) {
                float a[4];
#pragma unroll
                for (int i = 0; i < 4; i++) a[i] = As[ty*4 + i][k];
                float4 bv = *(const float4*)&Bs[k][tx*4];
                float bj[4] = {bv.x, bv.y, bv.z, bv.w};
#pragma unroll
                for (int i = 0; i < 4; i++)
#pragma unroll
                    for (int j = 0; j < 4; j++) acc[i][j] = fmaf(a[i], bj[j], acc[i][j]);
            }
        }
    }

#pragma unroll
    for (int i = 0; i < 4; i++) {
        int m = ty*4 + i;
#pragma unroll
        for (int j = 0; j < 4; j++) {
            int n = n0 + tx*4 + j;
            float v = acc[i][j];
            if (bias1) v += bias1[n];
            if (bias2) v += bias2[n];
            if (addm)  v += addm[m*N + n];
            if (act == 1) v = 1.f / (1.f + __expf(-v));
            else if (act == 2) v = tanhf(v);
            C[m*N + n] = v;
        }
    }
}

// ---------------- fused zt & rt: grid (8, 2) ----------------
__global__ void gates_zr_kernel(const float* __restrict__ Ey, const float* __restrict__ h,
                                const float* __restrict__ ctx,
                                const float* __restrict__ Wyz, const float* __restrict__ Uhz,
                                const float* __restrict__ Wccz,
                                const float* __restrict__ Wyr, const float* __restrict__ Uhr,
                                const float* __restrict__ Ccr)
{
    __shared__ float As[64][33];
    __shared__ float Bs[32][64];
    int t = threadIdx.x;
    int tx = t & 15, ty = t >> 4;
    int n0 = blockIdx.x * 64;
    int gate = blockIdx.y;

    const float* Aps[3] = {Ey, h, ctx};
    const float* Bps[3];
    if (gate == 0) { Bps[0] = Wyz; Bps[1] = Uhz; Bps[2] = Wccz; }
    else           { Bps[0] = Wyr; Bps[1] = Uhr; Bps[2] = Ccr; }
    int Ks[3] = {EE, UU, DD};
    float* C = gate ? g_rt : g_zt;

    float acc[4][4];
#pragma unroll
    for (int i = 0; i < 4; i++)
#pragma unroll
        for (int j = 0; j < 4; j++) acc[i][j] = 0.f;

    for (int p = 0; p < 3; p++) {
        const float* A = Aps[p];
        const float* Bm = Bps[p];
        int K = Ks[p];
        float ar[8], br[8];
#pragma unroll
        for (int r = 0; r < 8; r++) {
            int e = t + 256*r;
            ar[r] = A[(e >> 5)*K + (e & 31)];
            br[r] = Bm[(size_t)(e >> 6)*UU + n0 + (e & 63)];
        }
        for (int kc = 0; kc < K; kc += 32) {
            __syncthreads();
#pragma unroll
            for (int r = 0; r < 8; r++) {
                int e = t + 256*r;
                As[e >> 5][e & 31] = ar[r];
                Bs[e >> 6][e & 63] = br[r];
            }
            __syncthreads();
            if (kc + 32 < K) {
#pragma unroll
                for (int r = 0; r < 8; r++) {
                    int e = t + 256*r;
                    ar[r] = A[(e >> 5)*K + kc + 32 + (e & 31)];
                    br[r] = Bm[(size_t)(kc + 32 + (e >> 6))*UU + n0 + (e & 63)];
                }
            }
#pragma unroll
            for (int k = 0; k < 32; k++) {
                float a[4];
#pragma unroll
                for (int i = 0; i < 4; i++) a[i] = As[ty*4 + i][k];
                float4 bv = *(const float4*)&Bs[k][tx*4];
                float bj[4] = {bv.x, bv.y, bv.z, bv.w};
#pragma unroll
                for (int i = 0; i < 4; i++)
#pragma unroll
                    for (int j = 0; j < 4; j++) acc[i][j] = fmaf(a[i], bj[j], acc[i][j]);
            }
        }
    }
#pragma unroll
    for (int i = 0; i < 4; i++) {
        int m = ty*4 + i;
#pragma unroll
        for (int j = 0; j < 4; j++) {
            int n = n0 + tx*4 + j;
            C[m*UU + n] = 1.f / (1.f + __expf(-acc[i][j]));
        }
    }
}

// ---------------- hcand + ht fused ----------------
__global__ void hcand_ht_kernel(const float* __restrict__ Ey, const float* __restrict__ h,
                                const float* __restrict__ ctx,
                                const float* __restrict__ Wyh, const float* __restrict__ Urh,
                                const float* __restrict__ Wccz,
                                const float* __restrict__ b_wyh, const float* __restrict__ b_urh,
                                float* __restrict__ out_ht)
{
    __shared__ float As[64][33];
    __shared__ float Bs[32][64];
    int t = threadIdx.x;
    int tx = t & 15, ty = t >> 4;
    int n0 = blockIdx.x * 64;

    const float* Aps[3] = {Ey, h, ctx};
    const float* Bps[3] = {Wyh, Urh, Wccz};
    int Ks[3] = {EE, UU, DD};

    float acc[4][4];
#pragma unroll
    for (int i = 0; i < 4; i++)
#pragma unroll
        for (int j = 0; j < 4; j++) acc[i][j] = 0.f;

    for (int p = 0; p < 3; p++) {
        const float* A = Aps[p];
        const float* Bm = Bps[p];
        int K = Ks[p];
        bool mul = (p == 1);
        float ar[8], br[8];
#pragma unroll
        for (int r = 0; r < 8; r++) {
            int e = t + 256*r;
            int m = e >> 5, k = e & 31;
            float v = A[m*K + k];
            if (mul) v *= g_rt[m*UU + k];
            ar[r] = v;
            br[r] = Bm[(size_t)(e >> 6)*UU + n0 + (e & 63)];
        }
        for (int kc = 0; kc < K; kc += 32) {
            __syncthreads();
#pragma unroll
            for (int r = 0; r < 8; r++) {
                int e = t + 256*r;
                As[e >> 5][e & 31] = ar[r];
                Bs[e >> 6][e & 63] = br[r];
            }
            __syncthreads();
            if (kc + 32 < K) {
#pragma unroll
                for (int r = 0; r < 8; r++) {
                    int e = t + 256*r;
                    int m = e >> 5, k = kc + 32 + (e & 31);
                    float v = A[m*K + k];
                    if (mul) v *= g_rt[m*UU + k];
                    ar[r] = v;
                    br[r] = Bm[(size_t)(kc + 32 + (e >> 6))*UU + n0 + (e & 63)];
                }
            }
#pragma unroll
            for (int k = 0; k < 32; k++) {
                float a[4];
#pragma unroll
                for (int i = 0; i < 4; i++) a[i] = As[ty*4 + i][k];
                float4 bv = *(const float4*)&Bs[k][tx*4];
                float bj[4] = {bv.x, bv.y, bv.z, bv.w};
#pragma unroll
                for (int i = 0; i < 4; i++)
#pragma unroll
                    for (int j = 0; j < 4; j++) acc[i][j] = fmaf(a[i], bj[j], acc[i][j]);
            }
        }
    }
#pragma unroll
    for (int i = 0; i < 4; i++) {
        int m = ty*4 + i;
#pragma unroll
        for (int j = 0; j < 4; j++) {
            int n = n0 + tx*4 + j;
            float hc = tanhf(acc[i][j] + b_wyh[n] + b_urh[n]);
            float z  = g_zt[m*UU + n];
            float v  = (1.f - z) * h[m*UU + n] + z * hc;
            g_ht[m*UU + n] = v;
            out_ht[m*UU + n] = v;
        }
    }
}

// ---------------- tf32 mma ----------------
__device__ __forceinline__ void mma_tf32(float* c, const uint32_t* a, const uint32_t* b) {
    asm volatile(
        "mma.sync.aligned.m16n8k8.row.col.f32.tf32.tf32.f32 "
        "{%0,%1,%2,%3}, {%4,%5,%6,%7}, {%8,%9}, {%0,%1,%2,%3};"
        : "+f"(c[0]), "+f"(c[1]), "+f"(c[2]), "+f"(c[3])
        : "r"(a[0]), "r"(a[1]), "r"(a[2]), "r"(a[3]), "r"(b[0]), "r"(b[1]));
}
__device__ __forceinline__ float fast_tanh(float x) {
    x = fminf(fmaxf(x, -15.f), 15.f);
    float e = __expf(2.f * x);
    return (e - 1.f) / (e + 1.f);
}

// ---------------- attention logits: 3-stage pipelined tf32 HMMA, N-split ----------------
// grid 4096: bx = (b<<6) | (lt<<2) | np.  Each CTA: 128 l-rows x 128 a-cols, K=544.
#define NCHUNK 17
#define STGF 8960            // floats per stage: As 128x36 + Bs 32x136
#define SM_HAS (3*STGF)      // 26880
#define SM_VAS (SM_HAS+128)
#define SM_TOTF (SM_VAS+128) // 27136 floats = 108544 B

__global__ __launch_bounds__(256, 2)
void attn_mma_kernel(const float* __restrict__ feat,
                     const float* __restrict__ Ua,
                     const float* __restrict__ Va)
{
    extern __shared__ float sm[];
    float* has = sm + SM_HAS;
    float* vas = sm + SM_VAS;

    int t = threadIdx.x;
    int lane = t & 31, wid = t >> 5;
    int wm = wid & 3, wn = wid >> 2;
    int qid = lane >> 2, tq = lane & 3;

    int b  = blockIdx.x >> 6;
    int l0 = ((blockIdx.x >> 2) & 15) << 7;
    int n0 = (blockIdx.x & 3) << 7;

    if (t < 128) { has[t] = g_ha[b*AA + n0 + t]; vas[t] = Va[n0 + t]; }

    const float* fb   = feat   + (size_t)(b*LL + l0) * DD;
    const float* bext = g_Bext + (size_t)(b*LL + l0) * 32;

    float acc[2][8][4];
#pragma unroll
    for (int i = 0; i < 2; i++)
#pragma unroll
        for (int j = 0; j < 8; j++)
#pragma unroll
            for (int r = 0; r < 4; r++) acc[i][j][r] = 0.f;

    auto issue = [&](int c) {
        int s = c % 3;
        float* As_ = sm + s*STGF;
        float* Bs_ = As_ + 4608;
        const float* Ap; int lda; const float* Bp;
        if (c < 16) { Ap = fb + c*32; lda = DD; Bp = Ua + (size_t)c*32*AA + n0; }
        else        { Ap = bext;      lda = 32; Bp = g_Qext + n0; }
#pragma unroll
        for (int r = 0; r < 4; r++) {
            int i = t + 256*r;
            int m = i >> 3, k4 = (i & 7) << 2;
            cp_async16(&As_[m*36 + k4], Ap + (size_t)m*lda + k4);
            int kr = i >> 5, n4 = (i & 31) << 2;
            cp_async16(&Bs_[kr*136 + n4], Bp + (size_t)kr*AA + n4);
        }
        cp_commit();
    };

    issue(0); issue(1);
    for (int c = 0; c < NCHUNK; c++) {
        if (c == NCHUNK-1) cp_wait<0>(); else cp_wait<1>();
        __syncthreads();
        if (c + 2 < NCHUNK) issue(c + 2);
        int s = c % 3;
        const float* As_ = sm + s*STGF;
        const float* Bs_ = As_ + 4608;
#pragma unroll
        for (int kk = 0; kk < 4; kk++) {
            uint32_t af[2][4], bf[8][2];
#pragma unroll
            for (int fm = 0; fm < 2; fm++) {
                int m0 = wm*32 + fm*16 + qid;
                af[fm][0] = __float_as_uint(As_[(m0    )*36 + kk*8 + tq    ]);
                af[fm][1] = __float_as_uint(As_[(m0 + 8)*36 + kk*8 + tq    ]);
                af[fm][2] = __float_as_uint(As_[(m0    )*36 + kk*8 + tq + 4]);
                af[fm][3] = __float_as_uint(As_[(m0 + 8)*36 + kk*8 + tq + 4]);
            }
#pragma unroll
            for (int fn = 0; fn < 8; fn++) {
                int nb = wn*64 + fn*8 + qid;
                bf[fn][0] = __float_as_uint(Bs_[(kk*8 + tq    )*136 + nb]);
                bf[fn][1] = __float_as_uint(Bs_[(kk*8 + tq + 4)*136 + nb]);
            }
#pragma unroll
            for (int fm = 0; fm < 2; fm++)
#pragma unroll
                for (int fn = 0; fn < 8; fn++)
                    mma_tf32(acc[fm][fn], af[fm], bf[fn]);
        }
    }

    // epilogue: tanh + dot with Va (local 128 cols)
    float part[4] = {0.f, 0.f, 0.f, 0.f};
#pragma unroll
    for (int fm = 0; fm < 2; fm++)
#pragma unroll
        for (int fn = 0; fn < 8; fn++)
#pragma unroll
            for (int r = 0; r < 4; r++) {
                int half = r >> 1, j = r & 1;
                int nl = wn*64 + fn*8 + 2*tq + j;
                part[fm*2 + half] += fast_tanh(acc[fm][fn][r] + has[nl]) * vas[nl];
            }

    // cross-warp row reduction (red aliased onto stage 0)
    float* red = sm;   // [128][9]
    __syncthreads();
#pragma unroll
    for (int p = 0; p < 4; p++) {
        int fm = p >> 1, half = p & 1;
        int rl = wm*32 + fm*16 + half*8 + qid;
        red[rl*9 + wn*4 + tq] = part[p];
    }
    __syncthreads();
    if (t < 128) {
        float s = 0.f;
#pragma unroll
        for (int x = 0; x < 8; x++) s += red[t*9 + x];
        g_logitpart[(size_t)(blockIdx.x & 3)*(BZ*LL) + b*LL + l0 + t] = s;
    }
}

// ---------------- softmax over L (sums 4 n-split partials) ----------------
__global__ void softmaxL_kernel(float* __restrict__ attn) {
    int b = blockIdx.x, t = threadIdx.x;
    __shared__ float sred[256];
    const float* p0 = g_logitpart + 0*(BZ*LL) + b*LL;
    const float* p1 = g_logitpart + 1*(BZ*LL) + b*LL;
    const float* p2 = g_logitpart + 2*(BZ*LL) + b*LL;
    const float* p3 = g_logitpart + 3*(BZ*LL) + b*LL;
    float* lg = g_logit + b*LL;

    float mx = -1e30f;
    for (int l = t; l < LL; l += 256) {
        float v = p0[l] + p1[l] + p2[l] + p3[l];
        lg[l] = v;
        mx = fmaxf(mx, v);
    }
    sred[t] = mx; __syncthreads();
    for (int s = 128; s > 0; s >>= 1) { if (t < s) sred[t] = fmaxf(sred[t], sred[t+s]); __syncthreads(); }
    mx = sred[0]; __syncthreads();
    float sum = 0.f;
    for (int l = t; l < LL; l += 256) sum += __expf(lg[l] - mx);
    sred[t] = sum; __syncthreads();
    for (int s = 128; s > 0; s >>= 1) { if (t < s) sred[t] += sred[t+s]; __syncthreads(); }
    sum = sred[0]; __syncthreads();
    float inv = 1.f / sum;
    for (int l = t; l < LL; l += 256) attn[b*LL + l] = __expf(lg[l] - mx) * inv;
}

// ---------------- context ----------------
__global__ void ctx_part_kernel(const float* __restrict__ feat, const float* __restrict__ attn) {
    int b = blockIdx.x >> 4, lc = blockIdx.x & 15;
    int d = threadIdx.x;
    const float* fb = feat + (size_t)(b*LL + lc*128) * DD;
    const float* ab = attn + b*LL + lc*128;
    float s = 0.f;
#pragma unroll 8
    for (int l = 0; l < 128; l++) s = fmaf(ab[l], fb[(size_t)l*DD + d], s);
    g_ctxpart[lc*(BZ*DD) + b*DD + d] = s;
}
__global__ void ctx_reduce_kernel() {
    int i = blockIdx.x * blockDim.x + threadIdx.x;
    if (i >= BZ*DD) return;
    float s = 0.f;
#pragma unroll
    for (int lc = 0; lc < CTX_SPLIT; lc++) s += g_ctxpart[lc*(BZ*DD) + i];
    g_context[i] = s;
}

// ---------------- Ey: smem-staged split-K ----------------
__global__ void ey_part_kernel(const float* __restrict__ pt, const float* __restrict__ We) {
    extern __shared__ float pts[];
    int kc = blockIdx.x;
    int k0 = kc * 256;
    int t = threadIdx.x;

    for (int i = t; i < 64*64; i += 256) {
        int m = i >> 6, c4 = (i & 63) << 2;
        float4 v = *(const float4*)&pt[(size_t)m*VV + k0 + c4];
        *(float4*)&pts[m*256 + c4] = v;
    }
    __syncthreads();

    int tx = t & 63, tg = t >> 6;
    int n4 = tx * 4;
    float4 acc[16];
#pragma unroll
    for (int mm = 0; mm < 16; mm++) acc[mm] = make_float4(0.f, 0.f, 0.f, 0.f);

    for (int k = 0; k < 256; k++) {
        float4 w = *(const float4*)&We[(size_t)(k0 + k)*EE + n4];
#pragma unroll
        for (int mm = 0; mm < 16; mm++) {
            float a = pts[(tg*16 + mm)*256 + k];
            acc[mm].x = fmaf(a, w.x, acc[mm].x);
            acc[mm].y = fmaf(a, w.y, acc[mm].y);
            acc[mm].z = fmaf(a, w.z, acc[mm].z);
            acc[mm].w = fmaf(a, w.w, acc[mm].w);
        }
    }
#pragma unroll
    for (int mm = 0; mm < 16; mm++)
        *(float4*)&g_eypart[(size_t)kc*(BZ*EE) + (tg*16 + mm)*EE + n4] = acc[mm];
}
__global__ void ey_reduce_kernel() {
    int i = blockIdx.x * blockDim.x + threadIdx.x;
    if (i >= BZ*EE) return;
    float s = 0.f;
    for (int kc = 0; kc < EY_SPLIT; kc++) s += g_eypart[(size_t)kc*(BZ*EE) + i];
    g_Ey[i] = s;
}

// ---------------- softmax over V (smem-cached) ----------------
__global__ void softmaxV_kernel(float* __restrict__ out) {
    extern __shared__ float row[];
    int b = blockIdx.x, t = threadIdx.x;
    __shared__ float sred[1024];
    const float4* lg4 = (const float4*)(g_vlogits + (size_t)b*VV);

    float mx = -1e30f;
    for (int i = t; i < VV/4; i += 1024) {
        float4 v = lg4[i];
        *(float4*)&row[i*4] = v;
        mx = fmaxf(fmaxf(mx, v.x), fmaxf(v.y, fmaxf(v.z, v.w)));
    }
    sred[t] = mx; __syncthreads();
    for (int s = 512; s > 0; s >>= 1) { if (t < s) sred[t] = fmaxf(sred[t], sred[t+s]); __syncthreads(); }
    mx = sred[0]; __syncthreads();

    float sum = 0.f;
    for (int v = t; v < VV; v += 1024) sum += __expf(row[v] - mx);
    sred[t] = sum; __syncthreads();
    for (int s = 512; s > 0; s >>= 1) { if (t < s) sred[t] += sred[t+s]; __syncthreads(); }
    sum = sred[0]; __syncthreads();

    float inv = 1.f / sum;
    float4* o4 = (float4*)(out + (size_t)b*VV);
    for (int i = t; i < VV/4; i += 1024) {
        float4 v = *(float4*)&row[i*4];
        v.x = __expf(v.x - mx) * inv;
        v.y = __expf(v.y - mx) * inv;
        v.z = __expf(v.z - mx) * inv;
        v.w = __expf(v.w - mx) * inv;
        o4[i] = v;
    }
}

// ---------------- launch ----------------
extern "C" void kernel_launch(void* const* d_in, const int* in_sizes, int n_in,
                              void* d_out, int out_size)
{
    const float* prev_target = (const float*)d_in[0];
    const float* prev_hidden = (const float*)d_in[1];
    const float* features    = (const float*)d_in[2];
    const float* Bmat        = (const float*)d_in[3];
    const float* Wa          = (const float*)d_in[4];
    const float* Ua          = (const float*)d_in[5];
    const float* Va          = (const float*)d_in[6];
    const float* Uf          = (const float*)d_in[7];
    const float* Qk          = (const float*)d_in[8];
    const float* We          = (const float*)d_in[9];
    const float* Wccz        = (const float*)d_in[10];
    const float* Wyz         = (const float*)d_in[11];
    const float* Uhz         = (const float*)d_in[12];
    const float* Wyr         = (const float*)d_in[13];
    const float* Uhr         = (const float*)d_in[14];
    const float* Ccr         = (const float*)d_in[15];
    const float* Wyh         = (const float*)d_in[16];
    const float* b_wyh       = (const float*)d_in[17];
    const float* Urh         = (const float*)d_in[18];
    const float* b_urh       = (const float*)d_in[19];
    const float* Wo          = (const float*)d_in[20];
    const float* Wh          = (const float*)d_in[21];
    const float* Wc          = (const float*)d_in[22];

    float* out      = (float*)d_out;
    float* out_ht   = (float*)d_out + HT_OFF;
    float* out_attn = (float*)d_out + ATTN_OFF;

    float* pctx;  cudaGetSymbolAddress((void**)&pctx, g_context);
    float* pEy;   cudaGetSymbolAddress((void**)&pEy, g_Ey);
    float* pht;   cudaGetSymbolAddress((void**)&pht, g_ht);
    float* poute; cudaGetSymbolAddress((void**)&poute, g_oute);
    float* pvlog; cudaGetSymbolAddress((void**)&pvlog, g_vlogits);

    cudaFuncSetAttribute(attn_mma_kernel, cudaFuncAttributeMaxDynamicSharedMemorySize, SM_TOTF*4);
    cudaFuncSetAttribute(ey_part_kernel, cudaFuncAttributeMaxDynamicSharedMemorySize, 64*256*4);
    cudaFuncSetAttribute(softmaxV_kernel, cudaFuncAttributeMaxDynamicSharedMemorySize, VV*4);

    // 1. prep (Qext | Bext | ha)
    prep_all_kernel<<<64 + 16384 + 64, 256>>>(Qk, Uf, Bmat, prev_hidden, Wa);

    // 2. Ey (independent branch)
    ey_part_kernel<<<EY_SPLIT, 256, 64*256*4>>>(prev_target, We);
    ey_reduce_kernel<<<(BZ*EE + 255)/256, 256>>>();

    // 3. attention logits (n-split: 64 b x 16 l-tiles x 4 n-tiles)
    attn_mma_kernel<<<BZ*16*4, 256, SM_TOTF*4>>>(features, Ua, Va);

    // 4. softmax over L (sums n-split partials)
    softmaxL_kernel<<<BZ, 256>>>(out_attn);

    // 5. context
    ctx_part_kernel<<<BZ*CTX_SPLIT, 512>>>(features, out_attn);
    ctx_reduce_kernel<<<(BZ*DD + 255)/256, 256>>>();

    // 6. zt & rt
    { dim3 g(UU/64, 2); gates_zr_kernel<<<g, 256>>>(pEy, prev_hidden, pctx,
                                                    Wyz, Uhz, Wccz, Wyr, Uhr, Ccr); }

    // 7. hcand + ht
    hcand_ht_kernel<<<UU/64, 256>>>(pEy, prev_hidden, pctx, Wyh, Urh, Wccz,
                                    b_wyh, b_urh, out_ht);

    // 8. oute = Ey + ht@Wh + ctx@Wc
    sgemm3v2_kernel<<<EE/64, 256>>>(pht, Wh, UU,
                                    pctx, Wc, DD, nullptr,
                                    nullptr, nullptr, 0,
                                    nullptr, nullptr, pEy, poute, EE, 0);

    // 9. vlogits = oute @ Wo
    sgemm3v2_kernel<<<VV/64, 256>>>(poute, Wo, EE,
                                    nullptr, nullptr, 0, nullptr,
                                    nullptr, nullptr, 0,
                                    nullptr, nullptr, nullptr, pvlog, VV, 0);

    // 10. softmax over V
    softmaxV_kernel<<<BZ, 1024, VV*4>>>(out);
}

// round 10
// speedup vs baseline: 5.1408x; 1.0947x over previous
#include <cuda_runtime.h>
#include <cstdint>

// ---------------- shapes ----------------
#define BZ 64
#define LL 2048
#define DD 512
#define UU 512
#define AA 512
#define KK 64
#define VV 32000
#define EE 256
#define QW 7

#define HT_OFF  (BZ*VV)
#define ATTN_OFF (BZ*VV + BZ*UU)

#define EY_SPLIT 250
#define CTX_SPLIT 16

// ---------------- scratch ----------------
__device__ float g_Bext[BZ*LL*32];
__device__ float2 g_Ut[17*16*512];      // [chunk][kk*4+tq][n] = (W[k], W[k+4])
__device__ float g_ha[BZ*AA];
__device__ float g_logitpart[4*BZ*LL];
__device__ float g_logit[BZ*LL];
__device__ float g_ctxpart[CTX_SPLIT*BZ*DD];
__device__ float g_context[BZ*DD];
__device__ float g_eypart[EY_SPLIT*BZ*EE];
__device__ float g_Ey[BZ*EE];
__device__ float g_zt[BZ*UU];
__device__ float g_rt[BZ*UU];
__device__ float g_ht[BZ*UU];
__device__ float g_oute[BZ*EE];
__device__ float g_vlogits[BZ*VV];

// ---------------- cp.async helpers ----------------
__device__ __forceinline__ void cp_async16(void* smem, const void* gmem) {
    unsigned sa = (unsigned)__cvta_generic_to_shared(smem);
    asm volatile("cp.async.cg.shared.global [%0], [%1], 16;" :: "r"(sa), "l"(gmem));
}
__device__ __forceinline__ void cp_commit() { asm volatile("cp.async.commit_group;"); }
template<int N> __device__ __forceinline__ void cp_wait() {
    asm volatile("cp.async.wait_group %0;" :: "n"(N));
}

// ---------------- merged prep: Ut | Bext | ha ----------------
__global__ void prep_all_kernel(const float* __restrict__ Qk, const float* __restrict__ Uf,
                                const float* __restrict__ Ua,
                                const float* __restrict__ Bm,
                                const float* __restrict__ h,  const float* __restrict__ Wa)
{
    __shared__ float hs[UU];
    int bx = blockIdx.x, t = threadIdx.x;
    if (bx < 1088) {
        int i = bx*256 + t;                 // 278528 floats of g_Ut
        int f = i >> 1, comp = i & 1;
        int c = f >> 13;
        int rem = f & 8191;
        int r = rem >> 9;                   // kk*4+tq
        int n = rem & 511;
        int kk = r >> 2, tq = r & 3;
        int k = c*32 + kk*8 + tq + (comp ? 4 : 0);
        float v;
        if (k < 512) v = Ua[k*AA + n];
        else {
            int w = k - 512;
            v = 0.f;
            if (w < QW)
                for (int kk2 = 0; kk2 < KK; kk2++)
                    v = fmaf(Qk[w*KK + kk2], Uf[kk2*AA + n], v);
        }
        ((float*)g_Ut)[i] = v;
    } else if (bx < 1088 + 16384) {
        int i = (bx - 1088)*256 + t;
        int j = i & 31;
        int l = (i >> 5) & (LL-1);
        int b = i >> 16;
        int ls = l + j - 3;
        g_Bext[i] = (j < QW && ls >= 0 && ls < LL) ? Bm[b*LL + ls] : 0.f;
    } else {
        int b = bx - 17472;
        for (int i = t; i < UU; i += 256) hs[i] = h[b*UU + i];
        __syncthreads();
        float a0 = 0.f, a1 = 0.f;
        for (int k = 0; k < UU; k++) {
            float hv = hs[k];
            a0 = fmaf(hv, Wa[k*AA + t],       a0);
            a1 = fmaf(hv, Wa[k*AA + t + 256], a1);
        }
        g_ha[b*AA + t]       = a0;
        g_ha[b*AA + t + 256] = a1;
    }
}

// ---------------- generic small GEMM with register double-buffering ----------------
__global__ void sgemm3v2_kernel(const float* __restrict__ A0, const float* __restrict__ B0, int K0,
                                const float* __restrict__ A1, const float* __restrict__ B1, int K1,
                                const float* __restrict__ Amul1,
                                const float* __restrict__ A2, const float* __restrict__ B2, int K2,
                                const float* __restrict__ bias1, const float* __restrict__ bias2,
                                const float* __restrict__ addm,
                                float* __restrict__ C, int N, int act)
{
    __shared__ float As[64][33];
    __shared__ float Bs[32][64];
    int t = threadIdx.x;
    int tx = t & 15, ty = t >> 4;
    int n0 = blockIdx.x * 64;

    float acc[4][4];
#pragma unroll
    for (int i = 0; i < 4; i++)
#pragma unroll
        for (int j = 0; j < 4; j++) acc[i][j] = 0.f;

    const float* Aps[3] = {A0, A1, A2};
    const float* Bps[3] = {B0, B1, B2};
    const float* Mps[3] = {nullptr, Amul1, nullptr};
    int Ks[3] = {K0, K1, K2};

    for (int p = 0; p < 3; p++) {
        const float* A = Aps[p];
        if (A == nullptr) continue;
        const float* Bm = Bps[p];
        const float* Mu = Mps[p];
        int K = Ks[p];

        float ar[8], br[8];
#pragma unroll
        for (int r = 0; r < 8; r++) {
            int e = t + 256*r;
            int m = e >> 5, k = e & 31;
            float v = A[m*K + k];
            if (Mu) v *= Mu[m*K + k];
            ar[r] = v;
            int kb = e >> 6, n = e & 63;
            br[r] = Bm[(size_t)kb*N + n0 + n];
        }
        for (int kc = 0; kc < K; kc += 32) {
            __syncthreads();
#pragma unroll
            for (int r = 0; r < 8; r++) {
                int e = t + 256*r;
                As[e >> 5][e & 31] = ar[r];
                Bs[e >> 6][e & 63] = br[r];
            }
            __syncthreads();
            if (kc + 32 < K) {
#pragma unroll
                for (int r = 0; r < 8; r++) {
                    int e = t + 256*r;
                    int m = e >> 5, k = e & 31;
                    float v = A[m*K + kc + 32 + k];
                    if (Mu) v *= Mu[m*K + kc + 32 + k];
                    ar[r] = v;
                    int kb = e >> 6, n = e & 63;
                    br[r] = Bm[(size_t)(kc + 32 + kb)*N + n0 + n];
                }
            }
#pragma unroll
            for (int k = 0; k < 32; k++) {
                float a[4];
#pragma unroll
                for (int i = 0; i < 4; i++) a[i] = As[ty*4 + i][k];
                float4 bv = *(const float4*)&Bs[k][tx*4];
                float bj[4] = {bv.x, bv.y, bv.z, bv.w};
#pragma unroll
                for (int i = 0; i < 4; i++)
#pragma unroll
                    for (int j = 0; j < 4; j++) acc[i][j] = fmaf(a[i], bj[j], acc[i][j]);
            }
        }
    }

#pragma unroll
    for (int i = 0; i < 4; i++) {
        int m = ty*4 + i;
#pragma unroll
        for (int j = 0; j < 4; j++) {
            int n = n0 + tx*4 + j;
            float v = acc[i][j];
            if (bias1) v += bias1[n];
            if (bias2) v += bias2[n];
            if (addm)  v += addm[m*N + n];
            if (act == 1) v = 1.f / (1.f + __expf(-v));
            else if (act == 2) v = tanhf(v);
            C[m*N + n] = v;
        }
    }
}

// ---------------- fused zt & rt: grid (8, 2) ----------------
__global__ void gates_zr_kernel(const float* __restrict__ Ey, const float* __restrict__ h,
                                const float* __restrict__ ctx,
                                const float* __restrict__ Wyz, const float* __restrict__ Uhz,
                                const float* __restrict__ Wccz,
                                const float* __restrict__ Wyr, const float* __restrict__ Uhr,
                                const float* __restrict__ Ccr)
{
    __shared__ float As[64][33];
    __shared__ float Bs[32][64];
    int t = threadIdx.x;
    int tx = t & 15, ty = t >> 4;
    int n0 = blockIdx.x * 64;
    int gate = blockIdx.y;

    const float* Aps[3] = {Ey, h, ctx};
    const float* Bps[3];
    if (gate == 0) { Bps[0] = Wyz; Bps[1] = Uhz; Bps[2] = Wccz; }
    else           { Bps[0] = Wyr; Bps[1] = Uhr; Bps[2] = Ccr; }
    int Ks[3] = {EE, UU, DD};
    float* C = gate ? g_rt : g_zt;

    float acc[4][4];
#pragma unroll
    for (int i = 0; i < 4; i++)
#pragma unroll
        for (int j = 0; j < 4; j++) acc[i][j] = 0.f;

    for (int p = 0; p < 3; p++) {
        const float* A = Aps[p];
        const float* Bm = Bps[p];
        int K = Ks[p];
        float ar[8], br[8];
#pragma unroll
        for (int r = 0; r < 8; r++) {
            int e = t + 256*r;
            ar[r] = A[(e >> 5)*K + (e & 31)];
            br[r] = Bm[(size_t)(e >> 6)*UU + n0 + (e & 63)];
        }
        for (int kc = 0; kc < K; kc += 32) {
            __syncthreads();
#pragma unroll
            for (int r = 0; r < 8; r++) {
                int e = t + 256*r;
                As[e >> 5][e & 31] = ar[r];
                Bs[e >> 6][e & 63] = br[r];
            }
            __syncthreads();
            if (kc + 32 < K) {
#pragma unroll
                for (int r = 0; r < 8; r++) {
                    int e = t + 256*r;
                    ar[r] = A[(e >> 5)*K + kc + 32 + (e & 31)];
                    br[r] = Bm[(size_t)(kc + 32 + (e >> 6))*UU + n0 + (e & 63)];
                }
            }
#pragma unroll
            for (int k = 0; k < 32; k++) {
                float a[4];
#pragma unroll
                for (int i = 0; i < 4; i++) a[i] = As[ty*4 + i][k];
                float4 bv = *(const float4*)&Bs[k][tx*4];
                float bj[4] = {bv.x, bv.y, bv.z, bv.w};
#pragma unroll
                for (int i = 0; i < 4; i++)
#pragma unroll
                    for (int j = 0; j < 4; j++) acc[i][j] = fmaf(a[i], bj[j], acc[i][j]);
            }
        }
    }
#pragma unroll
    for (int i = 0; i < 4; i++) {
        int m = ty*4 + i;
#pragma unroll
        for (int j = 0; j < 4; j++) {
            int n = n0 + tx*4 + j;
            C[m*UU + n] = 1.f / (1.f + __expf(-acc[i][j]));
        }
    }
}

// ---------------- hcand + ht fused ----------------
__global__ void hcand_ht_kernel(const float* __restrict__ Ey, const float* __restrict__ h,
                                const float* __restrict__ ctx,
                                const float* __restrict__ Wyh, const float* __restrict__ Urh,
                                const float* __restrict__ Wccz,
                                const float* __restrict__ b_wyh, const float* __restrict__ b_urh,
                                float* __restrict__ out_ht)
{
    __shared__ float As[64][33];
    __shared__ float Bs[32][64];
    int t = threadIdx.x;
    int tx = t & 15, ty = t >> 4;
    int n0 = blockIdx.x * 64;

    const float* Aps[3] = {Ey, h, ctx};
    const float* Bps[3] = {Wyh, Urh, Wccz};
    int Ks[3] = {EE, UU, DD};

    float acc[4][4];
#pragma unroll
    for (int i = 0; i < 4; i++)
#pragma unroll
        for (int j = 0; j < 4; j++) acc[i][j] = 0.f;

    for (int p = 0; p < 3; p++) {
        const float* A = Aps[p];
        const float* Bm = Bps[p];
        int K = Ks[p];
        bool mul = (p == 1);
        float ar[8], br[8];
#pragma unroll
        for (int r = 0; r < 8; r++) {
            int e = t + 256*r;
            int m = e >> 5, k = e & 31;
            float v = A[m*K + k];
            if (mul) v *= g_rt[m*UU + k];
            ar[r] = v;
            br[r] = Bm[(size_t)(e >> 6)*UU + n0 + (e & 63)];
        }
        for (int kc = 0; kc < K; kc += 32) {
            __syncthreads();
#pragma unroll
            for (int r = 0; r < 8; r++) {
                int e = t + 256*r;
                As[e >> 5][e & 31] = ar[r];
                Bs[e >> 6][e & 63] = br[r];
            }
            __syncthreads();
            if (kc + 32 < K) {
#pragma unroll
                for (int r = 0; r < 8; r++) {
                    int e = t + 256*r;
                    int m = e >> 5, k = kc + 32 + (e & 31);
                    float v = A[m*K + k];
                    if (mul) v *= g_rt[m*UU + k];
                    ar[r] = v;
                    br[r] = Bm[(size_t)(kc + 32 + (e >> 6))*UU + n0 + (e & 63)];
                }
            }
#pragma unroll
            for (int k = 0; k < 32; k++) {
                float a[4];
#pragma unroll
                for (int i = 0; i < 4; i++) a[i] = As[ty*4 + i][k];
                float4 bv = *(const float4*)&Bs[k][tx*4];
                float bj[4] = {bv.x, bv.y, bv.z, bv.w};
#pragma unroll
                for (int i = 0; i < 4; i++)
#pragma unroll
                    for (int j = 0; j < 4; j++) acc[i][j] = fmaf(a[i], bj[j], acc[i][j]);
            }
        }
    }
#pragma unroll
    for (int i = 0; i < 4; i++) {
        int m = ty*4 + i;
#pragma unroll
        for (int j = 0; j < 4; j++) {
            int n = n0 + tx*4 + j;
            float hc = tanhf(acc[i][j] + b_wyh[n] + b_urh[n]);
            float z  = g_zt[m*UU + n];
            float v  = (1.f - z) * h[m*UU + n] + z * hc;
            g_ht[m*UU + n] = v;
            out_ht[m*UU + n] = v;
        }
    }
}

// ---------------- tf32 mma ----------------
__device__ __forceinline__ void mma_tf32(float* c, const uint32_t* a, const uint32_t* b) {
    asm volatile(
        "mma.sync.aligned.m16n8k8.row.col.f32.tf32.tf32.f32 "
        "{%0,%1,%2,%3}, {%4,%5,%6,%7}, {%8,%9}, {%0,%1,%2,%3};"
        : "+f"(c[0]), "+f"(c[1]), "+f"(c[2]), "+f"(c[3])
        : "r"(a[0]), "r"(a[1]), "r"(a[2]), "r"(a[3]), "r"(b[0]), "r"(b[1]));
}
__device__ __forceinline__ float fast_tanh(float x) {
    x = fminf(fmaxf(x, -15.f), 15.f);
    float e = __expf(2.f * x);
    return (e - 1.f) / (e + 1.f);
}

// ---------------- attention logits: 3-stage pipelined tf32 HMMA, N-split, paired B frags ----------------
#define NCHUNK 17
#define BS2_STRIDE 132
#define STGF (4608 + 16*BS2_STRIDE*2)
#define SM_HAS (3*STGF)
#define SM_VAS (SM_HAS+128)
#define SM_TOTF (SM_VAS+128)

__global__ __launch_bounds__(256, 2)
void attn_mma_kernel(const float* __restrict__ feat,
                     const float* __restrict__ Va)
{
    extern __shared__ float sm[];
    float* has = sm + SM_HAS;
    float* vas = sm + SM_VAS;

    int t = threadIdx.x;
    int lane = t & 31, wid = t >> 5;
    int wm = wid & 3, wn = wid >> 2;
    int qid = lane >> 2, tq = lane & 3;

    int b  = blockIdx.x >> 6;
    int l0 = ((blockIdx.x >> 2) & 15) << 7;
    int n0 = (blockIdx.x & 3) << 7;

    if (t < 128) { has[t] = g_ha[b*AA + n0 + t]; vas[t] = Va[n0 + t]; }

    const float* fb   = feat   + (size_t)(b*LL + l0) * DD;
    const float* bext = g_Bext + (size_t)(b*LL + l0) * 32;

    float acc[2][8][4];
#pragma unroll
    for (int i = 0; i < 2; i++)
#pragma unroll
        for (int j = 0; j < 8; j++)
#pragma unroll
            for (int r = 0; r < 4; r++) acc[i][j][r] = 0.f;

    auto issue = [&](int c) {
        int s = c % 3;
        float*  As_ = sm + s*STGF;
        float2* Bs2 = (float2*)(As_ + 4608);
        const float* Ap; int lda;
        if (c < 16) { Ap = fb + c*32; lda = DD; }
        else        { Ap = bext;      lda = 32; }
#pragma unroll
        for (int r = 0; r < 4; r++) {
            int i = t + 256*r;
            int m = i >> 3, k4 = (i & 7) << 2;
            cp_async16(&As_[m*36 + k4], Ap + (size_t)m*lda + k4);
        }
        const float2* Up = g_Ut + (size_t)c*16*512 + n0;
#pragma unroll
        for (int r = 0; r < 4; r++) {
            int g = t + 256*r;
            int row = g >> 6, gc = (g & 63) << 1;
            cp_async16(&Bs2[row*BS2_STRIDE + gc], Up + (size_t)row*512 + gc);
        }
        cp_commit();
    };

    issue(0); issue(1);
    for (int c = 0; c < NCHUNK; c++) {
        if (c == NCHUNK-1) cp_wait<0>(); else cp_wait<1>();
        __syncthreads();
        if (c + 2 < NCHUNK) issue(c + 2);
        int s = c % 3;
        const float*  As_ = sm + s*STGF;
        const float2* Bs2 = (const float2*)(As_ + 4608);
#pragma unroll
        for (int kk = 0; kk < 4; kk++) {
            uint32_t af[2][4], bf[8][2];
#pragma unroll
            for (int fm = 0; fm < 2; fm++) {
                int m0 = wm*32 + fm*16 + qid;
                af[fm][0] = __float_as_uint(As_[(m0    )*36 + kk*8 + tq    ]);
                af[fm][1] = __float_as_uint(As_[(m0 + 8)*36 + kk*8 + tq    ]);
                af[fm][2] = __float_as_uint(As_[(m0    )*36 + kk*8 + tq + 4]);
                af[fm][3] = __float_as_uint(As_[(m0 + 8)*36 + kk*8 + tq + 4]);
            }
            int brow = (kk*4 + tq)*BS2_STRIDE;
#pragma unroll
            for (int fn = 0; fn < 8; fn++) {
                int nb = wn*64 + fn*8 + qid;
                float2 bv = Bs2[brow + nb];
                bf[fn][0] = __float_as_uint(bv.x);
                bf[fn][1] = __float_as_uint(bv.y);
            }
#pragma unroll
            for (int fm = 0; fm < 2; fm++)
#pragma unroll
                for (int fn = 0; fn < 8; fn++)
                    mma_tf32(acc[fm][fn], af[fm], bf[fn]);
        }
    }

    float part[4] = {0.f, 0.f, 0.f, 0.f};
#pragma unroll
    for (int fm = 0; fm < 2; fm++)
#pragma unroll
        for (int fn = 0; fn < 8; fn++)
#pragma unroll
            for (int r = 0; r < 4; r++) {
                int half = r >> 1, j = r & 1;
                int nl = wn*64 + fn*8 + 2*tq + j;
                part[fm*2 + half] += fast_tanh(acc[fm][fn][r] + has[nl]) * vas[nl];
            }

    float* red = sm;
    __syncthreads();
#pragma unroll
    for (int p = 0; p < 4; p++) {
        int fm = p >> 1, half = p & 1;
        int rl = wm*32 + fm*16 + half*8 + qid;
        red[rl*9 + wn*4 + tq] = part[p];
    }
    __syncthreads();
    if (t < 128) {
        float s = 0.f;
#pragma unroll
        for (int x = 0; x < 8; x++) s += red[t*9 + x];
        g_logitpart[(size_t)(blockIdx.x & 3)*(BZ*LL) + b*LL + l0 + t] = s;
    }
}

// ---------------- vlogits: tf32 MMA, 3-stage (fixes R8 double-buffer race) ----------------
#define VG_STGF (2304 + 4352)   // As 64x36 + Bs 32x136
__global__ __launch_bounds__(256)
void vgemm_mma_kernel(const float* __restrict__ Aee, const float* __restrict__ Wo)
{
    extern __shared__ float sm[];
    int t = threadIdx.x;
    int lane = t & 31, wid = t >> 5;
    int qid = lane >> 2, tq = lane & 3;
    int n0 = blockIdx.x << 7;

    float acc[4][2][4];
#pragma unroll
    for (int i = 0; i < 4; i++)
#pragma unroll
        for (int j = 0; j < 2; j++)
#pragma unroll
            for (int r = 0; r < 4; r++) acc[i][j][r] = 0.f;

    auto issue = [&](int c) {
        float* As_ = sm + (c % 3)*VG_STGF;
        float* Bs_ = As_ + 2304;
#pragma unroll
        for (int r = 0; r < 2; r++) {
            int i = t + 256*r;
            int m = i >> 3, k4 = (i & 7) << 2;
            cp_async16(&As_[m*36 + k4], Aee + (size_t)m*EE + c*32 + k4);
        }
#pragma unroll
        for (int r = 0; r < 4; r++) {
            int i = t + 256*r;
            int kr = i >> 5, n4 = (i & 31) << 2;
            cp_async16(&Bs_[kr*136 + n4], Wo + (size_t)(c*32 + kr)*VV + n0 + n4);
        }
        cp_commit();
    };

    issue(0); issue(1);
    for (int c = 0; c < 8; c++) {
        if (c == 7) cp_wait<0>(); else cp_wait<1>();
        __syncthreads();
        if (c + 2 < 8) issue(c + 2);
        const float* As_ = sm + (c % 3)*VG_STGF;
        const float* Bs_ = As_ + 2304;
#pragma unroll
        for (int kk = 0; kk < 4; kk++) {
            uint32_t af[4][4], bf[2][2];
#pragma unroll
            for (int fm = 0; fm < 4; fm++) {
                int m0 = fm*16 + qid;
                af[fm][0] = __float_as_uint(As_[(m0    )*36 + kk*8 + tq    ]);
                af[fm][1] = __float_as_uint(As_[(m0 + 8)*36 + kk*8 + tq    ]);
                af[fm][2] = __float_as_uint(As_[(m0    )*36 + kk*8 + tq + 4]);
                af[fm][3] = __float_as_uint(As_[(m0 + 8)*36 + kk*8 + tq + 4]);
            }
#pragma unroll
            for (int fn = 0; fn < 2; fn++) {
                int nb = wid*16 + fn*8 + qid;
                bf[fn][0] = __float_as_uint(Bs_[(kk*8 + tq    )*136 + nb]);
                bf[fn][1] = __float_as_uint(Bs_[(kk*8 + tq + 4)*136 + nb]);
            }
#pragma unroll
            for (int fm = 0; fm < 4; fm++)
#pragma unroll
                for (int fn = 0; fn < 2; fn++)
                    mma_tf32(acc[fm][fn], af[fm], bf[fn]);
        }
    }

#pragma unroll
    for (int fm = 0; fm < 4; fm++)
#pragma unroll
        for (int fn = 0; fn < 2; fn++)
#pragma unroll
            for (int r = 0; r < 4; r++) {
                int m = fm*16 + (r >> 1)*8 + qid;
                int n = n0 + wid*16 + fn*8 + 2*tq + (r & 1);
                g_vlogits[(size_t)m*VV + n] = acc[fm][fn][r];
            }
}

// ---------------- softmax over L (sums 4 n-split partials) ----------------
__global__ void softmaxL_kernel(float* __restrict__ attn) {
    int b = blockIdx.x, t = threadIdx.x;
    __shared__ float sred[256];
    const float* p0 = g_logitpart + 0*(BZ*LL) + b*LL;
    const float* p1 = g_logitpart + 1*(BZ*LL) + b*LL;
    const float* p2 = g_logitpart + 2*(BZ*LL) + b*LL;
    const float* p3 = g_logitpart + 3*(BZ*LL) + b*LL;
    float* lg = g_logit + b*LL;

    float mx = -1e30f;
    for (int l = t; l < LL; l += 256) {
        float v = p0[l] + p1[l] + p2[l] + p3[l];
        lg[l] = v;
        mx = fmaxf(mx, v);
    }
    sred[t] = mx; __syncthreads();
    for (int s = 128; s > 0; s >>= 1) { if (t < s) sred[t] = fmaxf(sred[t], sred[t+s]); __syncthreads(); }
    mx = sred[0]; __syncthreads();
    float sum = 0.f;
    for (int l = t; l < LL; l += 256) sum += __expf(lg[l] - mx);
    sred[t] = sum; __syncthreads();
    for (int s = 128; s > 0; s >>= 1) { if (t < s) sred[t] += sred[t+s]; __syncthreads(); }
    sum = sred[0]; __syncthreads();
    float inv = 1.f / sum;
    for (int l = t; l < LL; l += 256) attn[b*LL + l] = __expf(lg[l] - mx) * inv;
}

// ---------------- context ----------------
__global__ void ctx_part_kernel(const float* __restrict__ feat, const float* __restrict__ attn) {
    int b = blockIdx.x >> 4, lc = blockIdx.x & 15;
    int d = threadIdx.x;
    const float* fb = feat + (size_t)(b*LL + lc*128) * DD;
    const float* ab = attn + b*LL + lc*128;
    float s = 0.f;
#pragma unroll 8
    for (int l = 0; l < 128; l++) s = fmaf(ab[l], fb[(size_t)l*DD + d], s);
    g_ctxpart[lc*(BZ*DD) + b*DD + d] = s;
}
__global__ void ctx_reduce_kernel() {
    int i = blockIdx.x * blockDim.x + threadIdx.x;
    if (i >= BZ*DD) return;
    float s = 0.f;
#pragma unroll
    for (int lc = 0; lc < CTX_SPLIT; lc++) s += g_ctxpart[lc*(BZ*DD) + i];
    g_context[i] = s;
}

// ---------------- Ey: smem-staged split-K (250 x 128k) ----------------
__global__ void ey_part_kernel(const float* __restrict__ pt, const float* __restrict__ We) {
    extern __shared__ float pts[];
    int kc = blockIdx.x;
    int k0 = kc * 128;
    int t = threadIdx.x;

    for (int i = t; i < 64*32; i += 256) {
        int m = i >> 5, c4 = (i & 31) << 2;
        float4 v = *(const float4*)&pt[(size_t)m*VV + k0 + c4];
        *(float4*)&pts[m*128 + c4] = v;
    }
    __syncthreads();

    int tx = t & 63, tg = t >> 6;
    int n4 = tx * 4;
    float4 acc[16];
#pragma unroll
    for (int mm = 0; mm < 16; mm++) acc[mm] = make_float4(0.f, 0.f, 0.f, 0.f);

    for (int k = 0; k < 128; k++) {
        float4 w = *(const float4*)&We[(size_t)(k0 + k)*EE + n4];
#pragma unroll
        for (int mm = 0; mm < 16; mm++) {
            float a = pts[(tg*16 + mm)*128 + k];
            acc[mm].x = fmaf(a, w.x, acc[mm].x);
            acc[mm].y = fmaf(a, w.y, acc[mm].y);
            acc[mm].z = fmaf(a, w.z, acc[mm].z);
            acc[mm].w = fmaf(a, w.w, acc[mm].w);
        }
    }
#pragma unroll
    for (int mm = 0; mm < 16; mm++)
        *(float4*)&g_eypart[(size_t)kc*(BZ*EE) + (tg*16 + mm)*EE + n4] = acc[mm];
}
__global__ void ey_reduce_kernel() {
    int i = blockIdx.x * blockDim.x + threadIdx.x;
    if (i >= BZ*EE) return;
    float s = 0.f;
    for (int kc = 0; kc < EY_SPLIT; kc++) s += g_eypart[(size_t)kc*(BZ*EE) + i];
    g_Ey[i] = s;
}

// ---------------- softmax over V (smem-cached) ----------------
__global__ void softmaxV_kernel(float* __restrict__ out) {
    extern __shared__ float row[];
    int b = blockIdx.x, t = threadIdx.x;
    __shared__ float sred[1024];
    const float4* lg4 = (const float4*)(g_vlogits + (size_t)b*VV);

    float mx = -1e30f;
    for (int i = t; i < VV/4; i += 1024) {
        float4 v = lg4[i];
        *(float4*)&row[i*4] = v;
        mx = fmaxf(fmaxf(mx, v.x), fmaxf(v.y, fmaxf(v.z, v.w)));
    }
    sred[t] = mx; __syncthreads();
    for (int s = 512; s > 0; s >>= 1) { if (t < s) sred[t] = fmaxf(sred[t], sred[t+s]); __syncthreads(); }
    mx = sred[0]; __syncthreads();

    float sum = 0.f;
    for (int v = t; v < VV; v += 1024) sum += __expf(row[v] - mx);
    sred[t] = sum; __syncthreads();
    for (int s = 512; s > 0; s >>= 1) { if (t < s) sred[t] += sred[t+s]; __syncthreads(); }
    sum = sred[0]; __syncthreads();

    float inv = 1.f / sum;
    float4* o4 = (float4*)(out + (size_t)b*VV);
    for (int i = t; i < VV/4; i += 1024) {
        float4 v = *(float4*)&row[i*4];
        v.x = __expf(v.x - mx) * inv;
        v.y = __expf(v.y - mx) * inv;
        v.z = __expf(v.z - mx) * inv;
        v.w = __expf(v.w - mx) * inv;
        o4[i] = v;
    }
}

// ---------------- launch ----------------
extern "C" void kernel_launch(void* const* d_in, const int* in_sizes, int n_in,
                              void* d_out, int out_size)
{
    const float* prev_target = (const float*)d_in[0];
    const float* prev_hidden = (const float*)d_in[1];
    const float* features    = (const float*)d_in[2];
    const float* Bmat        = (const float*)d_in[3];
    const float* Wa          = (const float*)d_in[4];
    const float* Ua          = (const float*)d_in[5];
    const float* Va          = (const float*)d_in[6];
    const float* Uf          = (const float*)d_in[7];
    const float* Qk          = (const float*)d_in[8];
    const float* We          = (const float*)d_in[9];
    const float* Wccz        = (const float*)d_in[10];
    const float* Wyz         = (const float*)d_in[11];
    const float* Uhz         = (const float*)d_in[12];
    const float* Wyr         = (const float*)d_in[13];
    const float* Uhr         = (const float*)d_in[14];
    const float* Ccr         = (const float*)d_in[15];
    const float* Wyh         = (const float*)d_in[16];
    const float* b_wyh       = (const float*)d_in[17];
    const float* Urh         = (const float*)d_in[18];
    const float* b_urh       = (const float*)d_in[19];
    const float* Wo          = (const float*)d_in[20];
    const float* Wh          = (const float*)d_in[21];
    const float* Wc          = (const float*)d_in[22];

    float* out      = (float*)d_out;
    float* out_ht   = (float*)d_out + HT_OFF;
    float* out_attn = (float*)d_out + ATTN_OFF;

    float* pctx;  cudaGetSymbolAddress((void**)&pctx, g_context);
    float* pEy;   cudaGetSymbolAddress((void**)&pEy, g_Ey);
    float* pht;   cudaGetSymbolAddress((void**)&pht, g_ht);
    float* poute; cudaGetSymbolAddress((void**)&poute, g_oute);

    cudaFuncSetAttribute(attn_mma_kernel, cudaFuncAttributeMaxDynamicSharedMemorySize, SM_TOTF*4);
    cudaFuncSetAttribute(vgemm_mma_kernel, cudaFuncAttributeMaxDynamicSharedMemorySize, 3*VG_STGF*4);
    cudaFuncSetAttribute(ey_part_kernel, cudaFuncAttributeMaxDynamicSharedMemorySize, 64*128*4);
    cudaFuncSetAttribute(softmaxV_kernel, cudaFuncAttributeMaxDynamicSharedMemorySize, VV*4);

    // 1. prep (Ut | Bext | ha)
    prep_all_kernel<<<1088 + 16384 + 64, 256>>>(Qk, Uf, Ua, Bmat, prev_hidden, Wa);

    // 2. Ey (independent branch)
    ey_part_kernel<<<EY_SPLIT, 256, 64*128*4>>>(prev_target, We);
    ey_reduce_kernel<<<(BZ*EE + 255)/256, 256>>>();

    // 3. attention logits
    attn_mma_kernel<<<BZ*16*4, 256, SM_TOTF*4>>>(features, Va);

    // 4. softmax over L
    softmaxL_kernel<<<BZ, 256>>>(out_attn);

    // 5. context
    ctx_part_kernel<<<BZ*CTX_SPLIT, 512>>>(features, out_attn);
    ctx_reduce_kernel<<<(BZ*DD + 255)/256, 256>>>();

    // 6. zt & rt
    { dim3 g(UU/64, 2); gates_zr_kernel<<<g, 256>>>(pEy, prev_hidden, pctx,
                                                    Wyz, Uhz, Wccz, Wyr, Uhr, Ccr); }

    // 7. hcand + ht
    hcand_ht_kernel<<<UU/64, 256>>>(pEy, prev_hidden, pctx, Wyh, Urh, Wccz,
                                    b_wyh, b_urh, out_ht);

    // 8. oute = Ey + ht@Wh + ctx@Wc
    sgemm3v2_kernel<<<EE/64, 256>>>(pht, Wh, UU,
                                    pctx, Wc, DD, nullptr,
                                    nullptr, nullptr, 0,
                                    nullptr, nullptr, pEy, poute, EE, 0);

    // 9. vlogits = oute @ Wo (tf32 mma, 3-stage)
    vgemm_mma_kernel<<<VV/128, 256, 3*VG_STGF*4>>>(poute, Wo);

    // 10. softmax over V
    softmaxV_kernel<<<BZ, 1024, VV*4>>>(out);
}

// round 11
// speedup vs baseline: 5.4992x; 1.0697x over previous
#include <cuda_runtime.h>
#include <cstdint>

// ---------------- shapes ----------------
#define BZ 64
#define LL 2048
#define DD 512
#define UU 512
#define AA 512
#define KK 64
#define VV 32000
#define EE 256
#define QW 7

#define HT_OFF  (BZ*VV)
#define ATTN_OFF (BZ*VV + BZ*UU)

#define EY_SPLIT 250
#define CTX_SPLIT 16

// ---------------- scratch ----------------
__device__ float g_Bext[BZ*LL*32];
__device__ float g_Qext[32*512];
__device__ float g_ha[BZ*AA];
__device__ float g_logitpart[4*BZ*LL];
__device__ float g_logit[BZ*LL];
__device__ float g_ctxpart[CTX_SPLIT*BZ*DD];
__device__ float g_context[BZ*DD];
__device__ float g_eypart[EY_SPLIT*BZ*EE];
__device__ float g_Ey[BZ*EE];
__device__ float g_zt[BZ*UU];
__device__ float g_rt[BZ*UU];
__device__ float g_hpart[BZ*UU];
__device__ float g_ht[BZ*UU];
__device__ float g_oute[BZ*EE];
__device__ float g_vlogits[BZ*VV];

// ---------------- cp.async helpers ----------------
__device__ __forceinline__ void cp_async16(void* smem, const void* gmem) {
    unsigned sa = (unsigned)__cvta_generic_to_shared(smem);
    asm volatile("cp.async.cg.shared.global [%0], [%1], 16;" :: "r"(sa), "l"(gmem));
}
__device__ __forceinline__ void cp_commit() { asm volatile("cp.async.commit_group;"); }
template<int N> __device__ __forceinline__ void cp_wait() {
    asm volatile("cp.async.wait_group %0;" :: "n"(N));
}

// ---------------- merged prep: Qext | Bext | ha (R7 version) ----------------
__global__ void prep_all_kernel(const float* __restrict__ Qk, const float* __restrict__ Uf,
                                const float* __restrict__ Bm,
                                const float* __restrict__ h,  const float* __restrict__ Wa)
{
    __shared__ float hs[UU];
    int bx = blockIdx.x, t = threadIdx.x;
    if (bx < 64) {
        int i = bx*256 + t;
        int w = i >> 9, a = i & 511;
        float s = 0.f;
        if (w < QW)
            for (int k = 0; k < KK; k++) s = fmaf(Qk[w*KK + k], Uf[k*AA + a], s);
        g_Qext[i] = s;
    } else if (bx < 64 + 16384) {
        int i = (bx - 64)*256 + t;
        int j = i & 31;
        int l = (i >> 5) & (LL-1);
        int b = i >> 16;
        int ls = l + j - 3;
        g_Bext[i] = (j < QW && ls >= 0 && ls < LL) ? Bm[b*LL + ls] : 0.f;
    } else {
        int b = bx - 16448;
        for (int i = t; i < UU; i += 256) hs[i] = h[b*UU + i];
        __syncthreads();
        float a0 = 0.f, a1 = 0.f;
        for (int k = 0; k < UU; k++) {
            float hv = hs[k];
            a0 = fmaf(hv, Wa[k*AA + t],       a0);
            a1 = fmaf(hv, Wa[k*AA + t + 256], a1);
        }
        g_ha[b*AA + t]       = a0;
        g_ha[b*AA + t + 256] = a1;
    }
}

// ---------------- generic small GEMM with register double-buffering ----------------
__global__ void sgemm3v2_kernel(const float* __restrict__ A0, const float* __restrict__ B0, int K0,
                                const float* __restrict__ A1, const float* __restrict__ B1, int K1,
                                const float* __restrict__ Amul1,
                                const float* __restrict__ A2, const float* __restrict__ B2, int K2,
                                const float* __restrict__ bias1, const float* __restrict__ bias2,
                                const float* __restrict__ addm,
                                float* __restrict__ C, int N, int act)
{
    __shared__ float As[64][33];
    __shared__ float Bs[32][64];
    int t = threadIdx.x;
    int tx = t & 15, ty = t >> 4;
    int n0 = blockIdx.x * 64;

    float acc[4][4];
#pragma unroll
    for (int i = 0; i < 4; i++)
#pragma unroll
        for (int j = 0; j < 4; j++) acc[i][j] = 0.f;

    const float* Aps[3] = {A0, A1, A2};
    const float* Bps[3] = {B0, B1, B2};
    const float* Mps[3] = {nullptr, Amul1, nullptr};
    int Ks[3] = {K0, K1, K2};

    for (int p = 0; p < 3; p++) {
        const float* A = Aps[p];
        if (A == nullptr) continue;
        const float* Bm = Bps[p];
        const float* Mu = Mps[p];
        int K = Ks[p];

        float ar[8], br[8];
#pragma unroll
        for (int r = 0; r < 8; r++) {
            int e = t + 256*r;
            int m = e >> 5, k = e & 31;
            float v = A[m*K + k];
            if (Mu) v *= Mu[m*K + k];
            ar[r] = v;
            int kb = e >> 6, n = e & 63;
            br[r] = Bm[(size_t)kb*N + n0 + n];
        }
        for (int kc = 0; kc < K; kc += 32) {
            __syncthreads();
#pragma unroll
            for (int r = 0; r < 8; r++) {
                int e = t + 256*r;
                As[e >> 5][e & 31] = ar[r];
                Bs[e >> 6][e & 63] = br[r];
            }
            __syncthreads();
            if (kc + 32 < K) {
#pragma unroll
                for (int r = 0; r < 8; r++) {
                    int e = t + 256*r;
                    int m = e >> 5, k = e & 31;
                    float v = A[m*K + kc + 32 + k];
                    if (Mu) v *= Mu[m*K + kc + 32 + k];
                    ar[r] = v;
                    int kb = e >> 6, n = e & 63;
                    br[r] = Bm[(size_t)(kc + 32 + kb)*N + n0 + n];
                }
            }
#pragma unroll
            for (int k = 0; k < 32; k++) {
                float a[4];
#pragma unroll
                for (int i = 0; i < 4; i++) a[i] = As[ty*4 + i][k];
                float4 bv = *(const float4*)&Bs[k][tx*4];
                float bj[4] = {bv.x, bv.y, bv.z, bv.w};
#pragma unroll
                for (int i = 0; i < 4; i++)
#pragma unroll
                    for (int j = 0; j < 4; j++) acc[i][j] = fmaf(a[i], bj[j], acc[i][j]);
            }
        }
    }

#pragma unroll
    for (int i = 0; i < 4; i++) {
        int m = ty*4 + i;
#pragma unroll
        for (int j = 0; j < 4; j++) {
            int n = n0 + tx*4 + j;
            float v = acc[i][j];
            if (bias1) v += bias1[n];
            if (bias2) v += bias2[n];
            if (addm)  v += addm[m*N + n];
            if (act == 1) v = 1.f / (1.f + __expf(-v));
            else if (act == 2) v = tanhf(v);
            C[m*N + n] = v;
        }
    }
}

// ---------------- gates3: zt | rt | hpart in one launch, grid (8, 3) ----------------
__global__ void gates3_kernel(const float* __restrict__ Ey, const float* __restrict__ h,
                              const float* __restrict__ ctx,
                              const float* __restrict__ Wyz, const float* __restrict__ Uhz,
                              const float* __restrict__ Wccz,
                              const float* __restrict__ Wyr, const float* __restrict__ Uhr,
                              const float* __restrict__ Ccr,
                              const float* __restrict__ Wyh,
                              const float* __restrict__ b_wyh, const float* __restrict__ b_urh)
{
    __shared__ float As[64][33];
    __shared__ float Bs[32][64];
    int t = threadIdx.x;
    int tx = t & 15, ty = t >> 4;
    int n0 = blockIdx.x * 64;
    int gate = blockIdx.y;

    const float* Aps[3];
    const float* Bps[3];
    int Ks[3];
    float* C;
    if (gate == 0) {
        Aps[0]=Ey; Bps[0]=Wyz; Ks[0]=EE;
        Aps[1]=h;  Bps[1]=Uhz; Ks[1]=UU;
        Aps[2]=ctx;Bps[2]=Wccz;Ks[2]=DD;
        C = g_zt;
    } else if (gate == 1) {
        Aps[0]=Ey; Bps[0]=Wyr; Ks[0]=EE;
        Aps[1]=h;  Bps[1]=Uhr; Ks[1]=UU;
        Aps[2]=ctx;Bps[2]=Ccr; Ks[2]=DD;
        C = g_rt;
    } else {
        Aps[0]=Ey; Bps[0]=Wyh; Ks[0]=EE;
        Aps[1]=ctx;Bps[1]=Wccz;Ks[1]=DD;
        Aps[2]=nullptr; Bps[2]=nullptr; Ks[2]=0;
        C = g_hpart;
    }

    float acc[4][4];
#pragma unroll
    for (int i = 0; i < 4; i++)
#pragma unroll
        for (int j = 0; j < 4; j++) acc[i][j] = 0.f;

    for (int p = 0; p < 3; p++) {
        const float* A = Aps[p];
        if (A == nullptr) continue;
        const float* Bm = Bps[p];
        int K = Ks[p];
        float ar[8], br[8];
#pragma unroll
        for (int r = 0; r < 8; r++) {
            int e = t + 256*r;
            ar[r] = A[(e >> 5)*K + (e & 31)];
            br[r] = Bm[(size_t)(e >> 6)*UU + n0 + (e & 63)];
        }
        for (int kc = 0; kc < K; kc += 32) {
            __syncthreads();
#pragma unroll
            for (int r = 0; r < 8; r++) {
                int e = t + 256*r;
                As[e >> 5][e & 31] = ar[r];
                Bs[e >> 6][e & 63] = br[r];
            }
            __syncthreads();
            if (kc + 32 < K) {
#pragma unroll
                for (int r = 0; r < 8; r++) {
                    int e = t + 256*r;
                    ar[r] = A[(e >> 5)*K + kc + 32 + (e & 31)];
                    br[r] = Bm[(size_t)(kc + 32 + (e >> 6))*UU + n0 + (e & 63)];
                }
            }
#pragma unroll
            for (int k = 0; k < 32; k++) {
                float a[4];
#pragma unroll
                for (int i = 0; i < 4; i++) a[i] = As[ty*4 + i][k];
                float4 bv = *(const float4*)&Bs[k][tx*4];
                float bj[4] = {bv.x, bv.y, bv.z, bv.w};
#pragma unroll
                for (int i = 0; i < 4; i++)
#pragma unroll
                    for (int j = 0; j < 4; j++) acc[i][j] = fmaf(a[i], bj[j], acc[i][j]);
            }
        }
    }
#pragma unroll
    for (int i = 0; i < 4; i++) {
        int m = ty*4 + i;
#pragma unroll
        for (int j = 0; j < 4; j++) {
            int n = n0 + tx*4 + j;
            float v = acc[i][j];
            if (gate < 2) v = 1.f / (1.f + __expf(-v));
            else          v += b_wyh[n] + b_urh[n];
            C[m*UU + n] = v;
        }
    }
}

// ---------------- hcand finish + ht: (rt*h)@Urh + hpart, blend ----------------
__global__ void hcand_ht_kernel(const float* __restrict__ h,
                                const float* __restrict__ Urh,
                                float* __restrict__ out_ht)
{
    __shared__ float As[64][33];
    __shared__ float Bs[32][64];
    int t = threadIdx.x;
    int tx = t & 15, ty = t >> 4;
    int n0 = blockIdx.x * 64;

    float acc[4][4];
#pragma unroll
    for (int i = 0; i < 4; i++)
#pragma unroll
        for (int j = 0; j < 4; j++) acc[i][j] = 0.f;

    float ar[8], br[8];
#pragma unroll
    for (int r = 0; r < 8; r++) {
        int e = t + 256*r;
        int m = e >> 5, k = e & 31;
        ar[r] = h[m*UU + k] * g_rt[m*UU + k];
        br[r] = Urh[(size_t)(e >> 6)*UU + n0 + (e & 63)];
    }
    for (int kc = 0; kc < UU; kc += 32) {
        __syncthreads();
#pragma unroll
        for (int r = 0; r < 8; r++) {
            int e = t + 256*r;
            As[e >> 5][e & 31] = ar[r];
            Bs[e >> 6][e & 63] = br[r];
        }
        __syncthreads();
        if (kc + 32 < UU) {
#pragma unroll
            for (int r = 0; r < 8; r++) {
                int e = t + 256*r;
                int m = e >> 5, k = kc + 32 + (e & 31);
                ar[r] = h[m*UU + k] * g_rt[m*UU + k];
                br[r] = Urh[(size_t)(kc + 32 + (e >> 6))*UU + n0 + (e & 63)];
            }
        }
#pragma unroll
        for (int k = 0; k < 32; k++) {
            float a[4];
#pragma unroll
            for (int i = 0; i < 4; i++) a[i] = As[ty*4 + i][k];
            float4 bv = *(const float4*)&Bs[k][tx*4];
            float bj[4] = {bv.x, bv.y, bv.z, bv.w};
#pragma unroll
            for (int i = 0; i < 4; i++)
#pragma unroll
                for (int j = 0; j < 4; j++) acc[i][j] = fmaf(a[i], bj[j], acc[i][j]);
        }
    }
#pragma unroll
    for (int i = 0; i < 4; i++) {
        int m = ty*4 + i;
#pragma unroll
        for (int j = 0; j < 4; j++) {
            int n = n0 + tx*4 + j;
            float hc = tanhf(acc[i][j] + g_hpart[m*UU + n]);
            float z  = g_zt[m*UU + n];
            float v  = (1.f - z) * h[m*UU + n] + z * hc;
            g_ht[m*UU + n] = v;
            out_ht[m*UU + n] = v;
        }
    }
}

// ---------------- tf32 mma ----------------
__device__ __forceinline__ void mma_tf32(float* c, const uint32_t* a, const uint32_t* b) {
    asm volatile(
        "mma.sync.aligned.m16n8k8.row.col.f32.tf32.tf32.f32 "
        "{%0,%1,%2,%3}, {%4,%5,%6,%7}, {%8,%9}, {%0,%1,%2,%3};"
        : "+f"(c[0]), "+f"(c[1]), "+f"(c[2]), "+f"(c[3])
        : "r"(a[0]), "r"(a[1]), "r"(a[2]), "r"(a[3]), "r"(b[0]), "r"(b[1]));
}
__device__ __forceinline__ float fast_tanh(float x) {
    x = fminf(fmaxf(x, -15.f), 15.f);
    float e = __expf(2.f * x);
    return (e - 1.f) / (e + 1.f);
}

// ---------------- attention logits: R7-exact mainloop, 3-stage, N-split ----------------
#define NCHUNK 17
#define STGF 8960            // As 128x36 + Bs 32x136
#define SM_HAS (3*STGF)
#define SM_VAS (SM_HAS+128)
#define SM_TOTF (SM_VAS+128)

__global__ __launch_bounds__(256, 2)
void attn_mma_kernel(const float* __restrict__ feat,
                     const float* __restrict__ Ua,
                     const float* __restrict__ Va)
{
    extern __shared__ float sm[];
    float* has = sm + SM_HAS;
    float* vas = sm + SM_VAS;

    int t = threadIdx.x;
    int lane = t & 31, wid = t >> 5;
    int wm = wid & 3, wn = wid >> 2;
    int qid = lane >> 2, tq = lane & 3;

    int b  = blockIdx.x >> 6;
    int l0 = ((blockIdx.x >> 2) & 15) << 7;
    int n0 = (blockIdx.x & 3) << 7;

    if (t < 128) { has[t] = g_ha[b*AA + n0 + t]; vas[t] = Va[n0 + t]; }

    const float* fb   = feat   + (size_t)(b*LL + l0) * DD;
    const float* bext = g_Bext + (size_t)(b*LL + l0) * 32;

    float acc[2][8][4];
#pragma unroll
    for (int i = 0; i < 2; i++)
#pragma unroll
        for (int j = 0; j < 8; j++)
#pragma unroll
            for (int r = 0; r < 4; r++) acc[i][j][r] = 0.f;

    auto issue = [&](int c) {
        int s = c % 3;
        float* As_ = sm + s*STGF;
        float* Bs_ = As_ + 4608;
        const float* Ap; int lda; const float* Bp;
        if (c < 16) { Ap = fb + c*32; lda = DD; Bp = Ua + (size_t)c*32*AA + n0; }
        else        { Ap = bext;      lda = 32; Bp = g_Qext + n0; }
#pragma unroll
        for (int r = 0; r < 4; r++) {
            int i = t + 256*r;
            int m = i >> 3, k4 = (i & 7) << 2;
            cp_async16(&As_[m*36 + k4], Ap + (size_t)m*lda + k4);
            int kr = i >> 5, n4 = (i & 31) << 2;
            cp_async16(&Bs_[kr*136 + n4], Bp + (size_t)kr*AA + n4);
        }
        cp_commit();
    };

    issue(0); issue(1);
    for (int c = 0; c < NCHUNK; c++) {
        if (c == NCHUNK-1) cp_wait<0>(); else cp_wait<1>();
        __syncthreads();
        if (c + 2 < NCHUNK) issue(c + 2);
        int s = c % 3;
        const float* As_ = sm + s*STGF;
        const float* Bs_ = As_ + 4608;
#pragma unroll
        for (int kk = 0; kk < 4; kk++) {
            uint32_t af[2][4], bf[8][2];
#pragma unroll
            for (int fm = 0; fm < 2; fm++) {
                int m0 = wm*32 + fm*16 + qid;
                af[fm][0] = __float_as_uint(As_[(m0    )*36 + kk*8 + tq    ]);
                af[fm][1] = __float_as_uint(As_[(m0 + 8)*36 + kk*8 + tq    ]);
                af[fm][2] = __float_as_uint(As_[(m0    )*36 + kk*8 + tq + 4]);
                af[fm][3] = __float_as_uint(As_[(m0 + 8)*36 + kk*8 + tq + 4]);
            }
#pragma unroll
            for (int fn = 0; fn < 8; fn++) {
                int nb = wn*64 + fn*8 + qid;
                bf[fn][0] = __float_as_uint(Bs_[(kk*8 + tq    )*136 + nb]);
                bf[fn][1] = __float_as_uint(Bs_[(kk*8 + tq + 4)*136 + nb]);
            }
#pragma unroll
            for (int fm = 0; fm < 2; fm++)
#pragma unroll
                for (int fn = 0; fn < 8; fn++)
                    mma_tf32(acc[fm][fn], af[fm], bf[fn]);
        }
    }

    float part[4] = {0.f, 0.f, 0.f, 0.f};
#pragma unroll
    for (int fm = 0; fm < 2; fm++)
#pragma unroll
        for (int fn = 0; fn < 8; fn++)
#pragma unroll
            for (int r = 0; r < 4; r++) {
                int half = r >> 1, j = r & 1;
                int nl = wn*64 + fn*8 + 2*tq + j;
                part[fm*2 + half] += fast_tanh(acc[fm][fn][r] + has[nl]) * vas[nl];
            }

    float* red = sm;
    __syncthreads();
#pragma unroll
    for (int p = 0; p < 4; p++) {
        int fm = p >> 1, half = p & 1;
        int rl = wm*32 + fm*16 + half*8 + qid;
        red[rl*9 + wn*4 + tq] = part[p];
    }
    __syncthreads();
    if (t < 128) {
        float s = 0.f;
#pragma unroll
        for (int x = 0; x < 8; x++) s += red[t*9 + x];
        g_logitpart[(size_t)(blockIdx.x & 3)*(BZ*LL) + b*LL + l0 + t] = s;
    }
}

// ---------------- vlogits: tf32 MMA, 3-stage ----------------
#define VG_STGF (2304 + 4352)
__global__ __launch_bounds__(256)
void vgemm_mma_kernel(const float* __restrict__ Aee, const float* __restrict__ Wo)
{
    extern __shared__ float sm[];
    int t = threadIdx.x;
    int lane = t & 31, wid = t >> 5;
    int qid = lane >> 2, tq = lane & 3;
    int n0 = blockIdx.x << 7;

    float acc[4][2][4];
#pragma unroll
    for (int i = 0; i < 4; i++)
#pragma unroll
        for (int j = 0; j < 2; j++)
#pragma unroll
            for (int r = 0; r < 4; r++) acc[i][j][r] = 0.f;

    auto issue = [&](int c) {
        float* As_ = sm + (c % 3)*VG_STGF;
        float* Bs_ = As_ + 2304;
#pragma unroll
        for (int r = 0; r < 2; r++) {
            int i = t + 256*r;
            int m = i >> 3, k4 = (i & 7) << 2;
            cp_async16(&As_[m*36 + k4], Aee + (size_t)m*EE + c*32 + k4);
        }
#pragma unroll
        for (int r = 0; r < 4; r++) {
            int i = t + 256*r;
            int kr = i >> 5, n4 = (i & 31) << 2;
            cp_async16(&Bs_[kr*136 + n4], Wo + (size_t)(c*32 + kr)*VV + n0 + n4);
        }
        cp_commit();
    };

    issue(0); issue(1);
    for (int c = 0; c < 8; c++) {
        if (c == 7) cp_wait<0>(); else cp_wait<1>();
        __syncthreads();
        if (c + 2 < 8) issue(c + 2);
        const float* As_ = sm + (c % 3)*VG_STGF;
        const float* Bs_ = As_ + 2304;
#pragma unroll
        for (int kk = 0; kk < 4; kk++) {
            uint32_t af[4][4], bf[2][2];
#pragma unroll
            for (int fm = 0; fm < 4; fm++) {
                int m0 = fm*16 + qid;
                af[fm][0] = __float_as_uint(As_[(m0    )*36 + kk*8 + tq    ]);
                af[fm][1] = __float_as_uint(As_[(m0 + 8)*36 + kk*8 + tq    ]);
                af[fm][2] = __float_as_uint(As_[(m0    )*36 + kk*8 + tq + 4]);
                af[fm][3] = __float_as_uint(As_[(m0 + 8)*36 + kk*8 + tq + 4]);
            }
#pragma unroll
            for (int fn = 0; fn < 2; fn++) {
                int nb = wid*16 + fn*8 + qid;
                bf[fn][0] = __float_as_uint(Bs_[(kk*8 + tq    )*136 + nb]);
                bf[fn][1] = __float_as_uint(Bs_[(kk*8 + tq + 4)*136 + nb]);
            }
#pragma unroll
            for (int fm = 0; fm < 4; fm++)
#pragma unroll
                for (int fn = 0; fn < 2; fn++)
                    mma_tf32(acc[fm][fn], af[fm], bf[fn]);
        }
    }

#pragma unroll
    for (int fm = 0; fm < 4; fm++)
#pragma unroll
        for (int fn = 0; fn < 2; fn++)
#pragma unroll
            for (int r = 0; r < 4; r++) {
                int m = fm*16 + (r >> 1)*8 + qid;
                int n = n0 + wid*16 + fn*8 + 2*tq + (r & 1);
                g_vlogits[(size_t)m*VV + n] = acc[fm][fn][r];
            }
}

// ---------------- softmax over L (sums 4 n-split partials) ----------------
__global__ void softmaxL_kernel(float* __restrict__ attn) {
    int b = blockIdx.x, t = threadIdx.x;
    __shared__ float sred[256];
    const float* p0 = g_logitpart + 0*(BZ*LL) + b*LL;
    const float* p1 = g_logitpart + 1*(BZ*LL) + b*LL;
    const float* p2 = g_logitpart + 2*(BZ*LL) + b*LL;
    const float* p3 = g_logitpart + 3*(BZ*LL) + b*LL;
    float* lg = g_logit + b*LL;

    float mx = -1e30f;
    for (int l = t; l < LL; l += 256) {
        float v = p0[l] + p1[l] + p2[l] + p3[l];
        lg[l] = v;
        mx = fmaxf(mx, v);
    }
    sred[t] = mx; __syncthreads();
    for (int s = 128; s > 0; s >>= 1) { if (t < s) sred[t] = fmaxf(sred[t], sred[t+s]); __syncthreads(); }
    mx = sred[0]; __syncthreads();
    float sum = 0.f;
    for (int l = t; l < LL; l += 256) sum += __expf(lg[l] - mx);
    sred[t] = sum; __syncthreads();
    for (int s = 128; s > 0; s >>= 1) { if (t < s) sred[t] += sred[t+s]; __syncthreads(); }
    sum = sred[0]; __syncthreads();
    float inv = 1.f / sum;
    for (int l = t; l < LL; l += 256) attn[b*LL + l] = __expf(lg[l] - mx) * inv;
}

// ---------------- context ----------------
__global__ void ctx_part_kernel(const float* __restrict__ feat, const float* __restrict__ attn) {
    int b = blockIdx.x >> 4, lc = blockIdx.x & 15;
    int d = threadIdx.x;
    const float* fb = feat + (size_t)(b*LL + lc*128) * DD;
    const float* ab = attn + b*LL + lc*128;
    float s = 0.f;
#pragma unroll 8
    for (int l = 0; l < 128; l++) s = fmaf(ab[l], fb[(size_t)l*DD + d], s);
    g_ctxpart[lc*(BZ*DD) + b*DD + d] = s;
}
__global__ void ctx_reduce_kernel() {
    int i = blockIdx.x * blockDim.x + threadIdx.x;
    if (i >= BZ*DD) return;
    float s = 0.f;
#pragma unroll
    for (int lc = 0; lc < CTX_SPLIT; lc++) s += g_ctxpart[lc*(BZ*DD) + i];
    g_context[i] = s;
}

// ---------------- Ey: smem-staged split-K (250 x 128k) ----------------
__global__ void ey_part_kernel(const float* __restrict__ pt, const float* __restrict__ We) {
    extern __shared__ float pts[];
    int kc = blockIdx.x;
    int k0 = kc * 128;
    int t = threadIdx.x;

    for (int i = t; i < 64*32; i += 256) {
        int m = i >> 5, c4 = (i & 31) << 2;
        float4 v = *(const float4*)&pt[(size_t)m*VV + k0 + c4];
        *(float4*)&pts[m*128 + c4] = v;
    }
    __syncthreads();

    int tx = t & 63, tg = t >> 6;
    int n4 = tx * 4;
    float4 acc[16];
#pragma unroll
    for (int mm = 0; mm < 16; mm++) acc[mm] = make_float4(0.f, 0.f, 0.f, 0.f);

    for (int k = 0; k < 128; k++) {
        float4 w = *(const float4*)&We[(size_t)(k0 + k)*EE + n4];
#pragma unroll
        for (int mm = 0; mm < 16; mm++) {
            float a = pts[(tg*16 + mm)*128 + k];
            acc[mm].x = fmaf(a, w.x, acc[mm].x);
            acc[mm].y = fmaf(a, w.y, acc[mm].y);
            acc[mm].z = fmaf(a, w.z, acc[mm].z);
            acc[mm].w = fmaf(a, w.w, acc[mm].w);
        }
    }
#pragma unroll
    for (int mm = 0; mm < 16; mm++)
        *(float4*)&g_eypart[(size_t)kc*(BZ*EE) + (tg*16 + mm)*EE + n4] = acc[mm];
}
__global__ void ey_reduce_kernel() {
    int i = blockIdx.x * blockDim.x + threadIdx.x;
    if (i >= BZ*EE) return;
    float s = 0.f;
    for (int kc = 0; kc < EY_SPLIT; kc++) s += g_eypart[(size_t)kc*(BZ*EE) + i];
    g_Ey[i] = s;
}

// ---------------- softmax over V (smem-cached) ----------------
__global__ void softmaxV_kernel(float* __restrict__ out) {
    extern __shared__ float row[];
    int b = blockIdx.x, t = threadIdx.x;
    __shared__ float sred[1024];
    const float4* lg4 = (const float4*)(g_vlogits + (size_t)b*VV);

    float mx = -1e30f;
    for (int i = t; i < VV/4; i += 1024) {
        float4 v = lg4[i];
        *(float4*)&row[i*4] = v;
        mx = fmaxf(fmaxf(mx, v.x), fmaxf(v.y, fmaxf(v.z, v.w)));
    }
    sred[t] = mx; __syncthreads();
    for (int s = 512; s > 0; s >>= 1) { if (t < s) sred[t] = fmaxf(sred[t], sred[t+s]); __syncthreads(); }
    mx = sred[0]; __syncthreads();

    float sum = 0.f;
    for (int v = t; v < VV; v += 1024) sum += __expf(row[v] - mx);
    sred[t] = sum; __syncthreads();
    for (int s = 512; s > 0; s >>= 1) { if (t < s) sred[t] += sred[t+s]; __syncthreads(); }
    sum = sred[0]; __syncthreads();

    float inv = 1.f / sum;
    float4* o4 = (float4*)(out + (size_t)b*VV);
    for (int i = t; i < VV/4; i += 1024) {
        float4 v = *(float4*)&row[i*4];
        v.x = __expf(v.x - mx) * inv;
        v.y = __expf(v.y - mx) * inv;
        v.z = __expf(v.z - mx) * inv;
        v.w = __expf(v.w - mx) * inv;
        o4[i] = v;
    }
}

// ---------------- launch ----------------
extern "C" void kernel_launch(void* const* d_in, const int* in_sizes, int n_in,
                              void* d_out, int out_size)
{
    const float* prev_target = (const float*)d_in[0];
    const float* prev_hidden = (const float*)d_in[1];
    const float* features    = (const float*)d_in[2];
    const float* Bmat        = (const float*)d_in[3];
    const float* Wa          = (const float*)d_in[4];
    const float* Ua          = (const float*)d_in[5];
    const float* Va          = (const float*)d_in[6];
    const float* Uf          = (const float*)d_in[7];
    const float* Qk          = (const float*)d_in[8];
    const float* We          = (const float*)d_in[9];
    const float* Wccz        = (const float*)d_in[10];
    const float* Wyz         = (const float*)d_in[11];
    const float* Uhz         = (const float*)d_in[12];
    const float* Wyr         = (const float*)d_in[13];
    const float* Uhr         = (const float*)d_in[14];
    const float* Ccr         = (const float*)d_in[15];
    const float* Wyh         = (const float*)d_in[16];
    const float* b_wyh       = (const float*)d_in[17];
    const float* Urh         = (const float*)d_in[18];
    const float* b_urh       = (const float*)d_in[19];
    const float* Wo          = (const float*)d_in[20];
    const float* Wh          = (const float*)d_in[21];
    const float* Wc          = (const float*)d_in[22];

    float* out      = (float*)d_out;
    float* out_ht   = (float*)d_out + HT_OFF;
    float* out_attn = (float*)d_out + ATTN_OFF;

    float* pctx;  cudaGetSymbolAddress((void**)&pctx, g_context);
    float* pEy;   cudaGetSymbolAddress((void**)&pEy, g_Ey);
    float* pht;   cudaGetSymbolAddress((void**)&pht, g_ht);
    float* poute; cudaGetSymbolAddress((void**)&poute, g_oute);

    cudaFuncSetAttribute(attn_mma_kernel, cudaFuncAttributeMaxDynamicSharedMemorySize, SM_TOTF*4);
    cudaFuncSetAttribute(vgemm_mma_kernel, cudaFuncAttributeMaxDynamicSharedMemorySize, 3*VG_STGF*4);
    cudaFuncSetAttribute(ey_part_kernel, cudaFuncAttributeMaxDynamicSharedMemorySize, 64*128*4);
    cudaFuncSetAttribute(softmaxV_kernel, cudaFuncAttributeMaxDynamicSharedMemorySize, VV*4);

    // 1. prep (Qext | Bext | ha)
    prep_all_kernel<<<64 + 16384 + 64, 256>>>(Qk, Uf, Bmat, prev_hidden, Wa);

    // 2. Ey (independent branch)
    ey_part_kernel<<<EY_SPLIT, 256, 64*128*4>>>(prev_target, We);
    ey_reduce_kernel<<<(BZ*EE + 255)/256, 256>>>();

    // 3. attention logits (R7-exact mainloop)
    attn_mma_kernel<<<BZ*16*4, 256, SM_TOTF*4>>>(features, Ua, Va);

    // 4. softmax over L
    softmaxL_kernel<<<BZ, 256>>>(out_attn);

    // 5. context
    ctx_part_kernel<<<BZ*CTX_SPLIT, 512>>>(features, out_attn);
    ctx_reduce_kernel<<<(BZ*DD + 255)/256, 256>>>();

    // 6. zt | rt | hpart in one launch
    { dim3 g(UU/64, 3); gates3_kernel<<<g, 256>>>(pEy, prev_hidden, pctx,
                                                  Wyz, Uhz, Wccz, Wyr, Uhr, Ccr,
                                                  Wyh, b_wyh, b_urh); }

    // 7. hcand finish + ht
    hcand_ht_kernel<<<UU/64, 256>>>(prev_hidden, Urh, out_ht);

    // 8. oute = Ey + ht@Wh + ctx@Wc
    sgemm3v2_kernel<<<EE/64, 256>>>(pht, Wh, UU,
                                    pctx, Wc, DD, nullptr,
                                    nullptr, nullptr, 0,
                                    nullptr, nullptr, pEy, poute, EE, 0);

    // 9. vlogits = oute @ Wo (tf32 mma, 3-stage)
    vgemm_mma_kernel<<<VV/128, 256, 3*VG_STGF*4>>>(poute, Wo);

    // 10. softmax over V
    softmaxV_kernel<<<BZ, 1024, VV*4>>>(out);
}

// round 12
// speedup vs baseline: 5.9037x; 1.0736x over previous
#include <cuda_runtime.h>
#include <cstdint>

// ---------------- shapes ----------------
#define BZ 64
#define LL 2048
#define DD 512
#define UU 512
#define AA 512
#define KK 64
#define VV 32000
#define EE 256
#define QW 7

#define HT_OFF  (BZ*VV)
#define ATTN_OFF (BZ*VV + BZ*UU)

#define EY_SPLIT 125
#define CTX_SPLIT 16

// ---------------- scratch ----------------
__device__ float g_Bext[BZ*LL*32];
__device__ float g_Qext[32*512];
__device__ float g_ha[BZ*AA];
__device__ float g_logitpart[4*BZ*LL];
__device__ float g_logit[BZ*LL];
__device__ float g_ctxpart[CTX_SPLIT*BZ*DD];
__device__ float g_context[BZ*DD];
__device__ float g_eypart[EY_SPLIT*BZ*EE];
__device__ float g_Ey[BZ*EE];
__device__ float g_zt[BZ*UU];
__device__ float g_rt[BZ*UU];
__device__ float g_hpart[BZ*UU];
__device__ float g_ht[BZ*UU];
__device__ float g_oute[BZ*EE];
__device__ float g_vlogits[BZ*VV];

// ---------------- cp.async helpers ----------------
__device__ __forceinline__ void cp_async16(void* smem, const void* gmem) {
    unsigned sa = (unsigned)__cvta_generic_to_shared(smem);
    asm volatile("cp.async.cg.shared.global [%0], [%1], 16;" :: "r"(sa), "l"(gmem));
}
__device__ __forceinline__ void cp_commit() { asm volatile("cp.async.commit_group;"); }
template<int N> __device__ __forceinline__ void cp_wait() {
    asm volatile("cp.async.wait_group %0;" :: "n"(N));
}

// ---------------- merged prep: Qext | Bext | ha ----------------
__global__ void prep_all_kernel(const float* __restrict__ Qk, const float* __restrict__ Uf,
                                const float* __restrict__ Bm,
                                const float* __restrict__ h,  const float* __restrict__ Wa)
{
    __shared__ float hs[UU];
    int bx = blockIdx.x, t = threadIdx.x;
    if (bx < 64) {
        int i = bx*256 + t;
        int w = i >> 9, a = i & 511;
        float s = 0.f;
        if (w < QW)
            for (int k = 0; k < KK; k++) s = fmaf(Qk[w*KK + k], Uf[k*AA + a], s);
        g_Qext[i] = s;
    } else if (bx < 64 + 16384) {
        int i = (bx - 64)*256 + t;
        int j = i & 31;
        int l = (i >> 5) & (LL-1);
        int b = i >> 16;
        int ls = l + j - 3;
        g_Bext[i] = (j < QW && ls >= 0 && ls < LL) ? Bm[b*LL + ls] : 0.f;
    } else {
        int b = bx - 16448;
        for (int i = t; i < UU; i += 256) hs[i] = h[b*UU + i];
        __syncthreads();
        float a0 = 0.f, a1 = 0.f;
        for (int k = 0; k < UU; k++) {
            float hv = hs[k];
            a0 = fmaf(hv, Wa[k*AA + t],       a0);
            a1 = fmaf(hv, Wa[k*AA + t + 256], a1);
        }
        g_ha[b*AA + t]       = a0;
        g_ha[b*AA + t + 256] = a1;
    }
}

// ---------------- generic small GEMM with register double-buffering ----------------
__global__ void sgemm3v2_kernel(const float* __restrict__ A0, const float* __restrict__ B0, int K0,
                                const float* __restrict__ A1, const float* __restrict__ B1, int K1,
                                const float* __restrict__ Amul1,
                                const float* __restrict__ A2, const float* __restrict__ B2, int K2,
                                const float* __restrict__ bias1, const float* __restrict__ bias2,
                                const float* __restrict__ addm,
                                float* __restrict__ C, int N, int act)
{
    __shared__ float As[64][33];
    __shared__ float Bs[32][64];
    int t = threadIdx.x;
    int tx = t & 15, ty = t >> 4;
    int n0 = blockIdx.x * 64;

    float acc[4][4];
#pragma unroll
    for (int i = 0; i < 4; i++)
#pragma unroll
        for (int j = 0; j < 4; j++) acc[i][j] = 0.f;

    const float* Aps[3] = {A0, A1, A2};
    const float* Bps[3] = {B0, B1, B2};
    const float* Mps[3] = {nullptr, Amul1, nullptr};
    int Ks[3] = {K0, K1, K2};

    for (int p = 0; p < 3; p++) {
        const float* A = Aps[p];
        if (A == nullptr) continue;
        const float* Bm = Bps[p];
        const float* Mu = Mps[p];
        int K = Ks[p];

        float ar[8], br[8];
#pragma unroll
        for (int r = 0; r < 8; r++) {
            int e = t + 256*r;
            int m = e >> 5, k = e & 31;
            float v = A[m*K + k];
            if (Mu) v *= Mu[m*K + k];
            ar[r] = v;
            int kb = e >> 6, n = e & 63;
            br[r] = Bm[(size_t)kb*N + n0 + n];
        }
        for (int kc = 0; kc < K; kc += 32) {
            __syncthreads();
#pragma unroll
            for (int r = 0; r < 8; r++) {
                int e = t + 256*r;
                As[e >> 5][e & 31] = ar[r];
                Bs[e >> 6][e & 63] = br[r];
            }
            __syncthreads();
            if (kc + 32 < K) {
#pragma unroll
                for (int r = 0; r < 8; r++) {
                    int e = t + 256*r;
                    int m = e >> 5, k = e & 31;
                    float v = A[m*K + kc + 32 + k];
                    if (Mu) v *= Mu[m*K + kc + 32 + k];
                    ar[r] = v;
                    int kb = e >> 6, n = e & 63;
                    br[r] = Bm[(size_t)(kc + 32 + kb)*N + n0 + n];
                }
            }
#pragma unroll
            for (int k = 0; k < 32; k++) {
                float a[4];
#pragma unroll
                for (int i = 0; i < 4; i++) a[i] = As[ty*4 + i][k];
                float4 bv = *(const float4*)&Bs[k][tx*4];
                float bj[4] = {bv.x, bv.y, bv.z, bv.w};
#pragma unroll
                for (int i = 0; i < 4; i++)
#pragma unroll
                    for (int j = 0; j < 4; j++) acc[i][j] = fmaf(a[i], bj[j], acc[i][j]);
            }
        }
    }

#pragma unroll
    for (int i = 0; i < 4; i++) {
        int m = ty*4 + i;
#pragma unroll
        for (int j = 0; j < 4; j++) {
            int n = n0 + tx*4 + j;
            float v = acc[i][j];
            if (bias1) v += bias1[n];
            if (bias2) v += bias2[n];
            if (addm)  v += addm[m*N + n];
            if (act == 1) v = 1.f / (1.f + __expf(-v));
            else if (act == 2) v = tanhf(v);
            C[m*N + n] = v;
        }
    }
}

// ---------------- gates3: zt | rt | hpart in one launch, grid (8, 3) ----------------
__global__ void gates3_kernel(const float* __restrict__ Ey, const float* __restrict__ h,
                              const float* __restrict__ ctx,
                              const float* __restrict__ Wyz, const float* __restrict__ Uhz,
                              const float* __restrict__ Wccz,
                              const float* __restrict__ Wyr, const float* __restrict__ Uhr,
                              const float* __restrict__ Ccr,
                              const float* __restrict__ Wyh,
                              const float* __restrict__ b_wyh, const float* __restrict__ b_urh)
{
    __shared__ float As[64][33];
    __shared__ float Bs[32][64];
    int t = threadIdx.x;
    int tx = t & 15, ty = t >> 4;
    int n0 = blockIdx.x * 64;
    int gate = blockIdx.y;

    const float* Aps[3];
    const float* Bps[3];
    int Ks[3];
    float* C;
    if (gate == 0) {
        Aps[0]=Ey; Bps[0]=Wyz; Ks[0]=EE;
        Aps[1]=h;  Bps[1]=Uhz; Ks[1]=UU;
        Aps[2]=ctx;Bps[2]=Wccz;Ks[2]=DD;
        C = g_zt;
    } else if (gate == 1) {
        Aps[0]=Ey; Bps[0]=Wyr; Ks[0]=EE;
        Aps[1]=h;  Bps[1]=Uhr; Ks[1]=UU;
        Aps[2]=ctx;Bps[2]=Ccr; Ks[2]=DD;
        C = g_rt;
    } else {
        Aps[0]=Ey; Bps[0]=Wyh; Ks[0]=EE;
        Aps[1]=ctx;Bps[1]=Wccz;Ks[1]=DD;
        Aps[2]=nullptr; Bps[2]=nullptr; Ks[2]=0;
        C = g_hpart;
    }

    float acc[4][4];
#pragma unroll
    for (int i = 0; i < 4; i++)
#pragma unroll
        for (int j = 0; j < 4; j++) acc[i][j] = 0.f;

    for (int p = 0; p < 3; p++) {
        const float* A = Aps[p];
        if (A == nullptr) continue;
        const float* Bm = Bps[p];
        int K = Ks[p];
        float ar[8], br[8];
#pragma unroll
        for (int r = 0; r < 8; r++) {
            int e = t + 256*r;
            ar[r] = A[(e >> 5)*K + (e & 31)];
            br[r] = Bm[(size_t)(e >> 6)*UU + n0 + (e & 63)];
        }
        for (int kc = 0; kc < K; kc += 32) {
            __syncthreads();
#pragma unroll
            for (int r = 0; r < 8; r++) {
                int e = t + 256*r;
                As[e >> 5][e & 31] = ar[r];
                Bs[e >> 6][e & 63] = br[r];
            }
            __syncthreads();
            if (kc + 32 < K) {
#pragma unroll
                for (int r = 0; r < 8; r++) {
                    int e = t + 256*r;
                    ar[r] = A[(e >> 5)*K + kc + 32 + (e & 31)];
                    br[r] = Bm[(size_t)(kc + 32 + (e >> 6))*UU + n0 + (e & 63)];
                }
            }
#pragma unroll
            for (int k = 0; k < 32; k++) {
                float a[4];
#pragma unroll
                for (int i = 0; i < 4; i++) a[i] = As[ty*4 + i][k];
                float4 bv = *(const float4*)&Bs[k][tx*4];
                float bj[4] = {bv.x, bv.y, bv.z, bv.w};
#pragma unroll
                for (int i = 0; i < 4; i++)
#pragma unroll
                    for (int j = 0; j < 4; j++) acc[i][j] = fmaf(a[i], bj[j], acc[i][j]);
            }
        }
    }
#pragma unroll
    for (int i = 0; i < 4; i++) {
        int m = ty*4 + i;
#pragma unroll
        for (int j = 0; j < 4; j++) {
            int n = n0 + tx*4 + j;
            float v = acc[i][j];
            if (gate < 2) v = 1.f / (1.f + __expf(-v));
            else          v += b_wyh[n] + b_urh[n];
            C[m*UU + n] = v;
        }
    }
}

// ---------------- hcand finish + ht: (rt*h)@Urh + hpart, blend ----------------
__global__ void hcand_ht_kernel(const float* __restrict__ h,
                                const float* __restrict__ Urh,
                                float* __restrict__ out_ht)
{
    __shared__ float As[64][33];
    __shared__ float Bs[32][64];
    int t = threadIdx.x;
    int tx = t & 15, ty = t >> 4;
    int n0 = blockIdx.x * 64;

    float acc[4][4];
#pragma unroll
    for (int i = 0; i < 4; i++)
#pragma unroll
        for (int j = 0; j < 4; j++) acc[i][j] = 0.f;

    float ar[8], br[8];
#pragma unroll
    for (int r = 0; r < 8; r++) {
        int e = t + 256*r;
        int m = e >> 5, k = e & 31;
        ar[r] = h[m*UU + k] * g_rt[m*UU + k];
        br[r] = Urh[(size_t)(e >> 6)*UU + n0 + (e & 63)];
    }
    for (int kc = 0; kc < UU; kc += 32) {
        __syncthreads();
#pragma unroll
        for (int r = 0; r < 8; r++) {
            int e = t + 256*r;
            As[e >> 5][e & 31] = ar[r];
            Bs[e >> 6][e & 63] = br[r];
        }
        __syncthreads();
        if (kc + 32 < UU) {
#pragma unroll
            for (int r = 0; r < 8; r++) {
                int e = t + 256*r;
                int m = e >> 5, k = kc + 32 + (e & 31);
                ar[r] = h[m*UU + k] * g_rt[m*UU + k];
                br[r] = Urh[(size_t)(kc + 32 + (e >> 6))*UU + n0 + (e & 63)];
            }
        }
#pragma unroll
        for (int k = 0; k < 32; k++) {
            float a[4];
#pragma unroll
            for (int i = 0; i < 4; i++) a[i] = As[ty*4 + i][k];
            float4 bv = *(const float4*)&Bs[k][tx*4];
            float bj[4] = {bv.x, bv.y, bv.z, bv.w};
#pragma unroll
            for (int i = 0; i < 4; i++)
#pragma unroll
                for (int j = 0; j < 4; j++) acc[i][j] = fmaf(a[i], bj[j], acc[i][j]);
        }
    }
#pragma unroll
    for (int i = 0; i < 4; i++) {
        int m = ty*4 + i;
#pragma unroll
        for (int j = 0; j < 4; j++) {
            int n = n0 + tx*4 + j;
            float hc = tanhf(acc[i][j] + g_hpart[m*UU + n]);
            float z  = g_zt[m*UU + n];
            float v  = (1.f - z) * h[m*UU + n] + z * hc;
            g_ht[m*UU + n] = v;
            out_ht[m*UU + n] = v;
        }
    }
}

// ---------------- tf32 mma ----------------
__device__ __forceinline__ void mma_tf32(float* c, const uint32_t* a, const uint32_t* b) {
    asm volatile(
        "mma.sync.aligned.m16n8k8.row.col.f32.tf32.tf32.f32 "
        "{%0,%1,%2,%3}, {%4,%5,%6,%7}, {%8,%9}, {%0,%1,%2,%3};"
        : "+f"(c[0]), "+f"(c[1]), "+f"(c[2]), "+f"(c[3])
        : "r"(a[0]), "r"(a[1]), "r"(a[2]), "r"(a[3]), "r"(b[0]), "r"(b[1]));
}
__device__ __forceinline__ float fast_tanh(float x) {
    x = fminf(fmaxf(x, -15.f), 15.f);
    float e = __expf(2.f * x);
    return (e - 1.f) / (e + 1.f);
}

// ---------------- attention logits: R7-exact mainloop, 3-stage, N-split ----------------
#define NCHUNK 17
#define STGF 8960            // As 128x36 + Bs 32x136
#define SM_HAS (3*STGF)
#define SM_VAS (SM_HAS+128)
#define SM_TOTF (SM_VAS+128)

__global__ __launch_bounds__(256, 2)
void attn_mma_kernel(const float* __restrict__ feat,
                     const float* __restrict__ Ua,
                     const float* __restrict__ Va)
{
    extern __shared__ float sm[];
    float* has = sm + SM_HAS;
    float* vas = sm + SM_VAS;

    int t = threadIdx.x;
    int lane = t & 31, wid = t >> 5;
    int wm = wid & 3, wn = wid >> 2;
    int qid = lane >> 2, tq = lane & 3;

    int b  = blockIdx.x >> 6;
    int l0 = ((blockIdx.x >> 2) & 15) << 7;
    int n0 = (blockIdx.x & 3) << 7;

    if (t < 128) { has[t] = g_ha[b*AA + n0 + t]; vas[t] = Va[n0 + t]; }

    const float* fb   = feat   + (size_t)(b*LL + l0) * DD;
    const float* bext = g_Bext + (size_t)(b*LL + l0) * 32;

    float acc[2][8][4];
#pragma unroll
    for (int i = 0; i < 2; i++)
#pragma unroll
        for (int j = 0; j < 8; j++)
#pragma unroll
            for (int r = 0; r < 4; r++) acc[i][j][r] = 0.f;

    auto issue = [&](int c) {
        int s = c % 3;
        float* As_ = sm + s*STGF;
        float* Bs_ = As_ + 4608;
        const float* Ap; int lda; const float* Bp;
        if (c < 16) { Ap = fb + c*32; lda = DD; Bp = Ua + (size_t)c*32*AA + n0; }
        else        { Ap = bext;      lda = 32; Bp = g_Qext + n0; }
#pragma unroll
        for (int r = 0; r < 4; r++) {
            int i = t + 256*r;
            int m = i >> 3, k4 = (i & 7) << 2;
            cp_async16(&As_[m*36 + k4], Ap + (size_t)m*lda + k4);
            int kr = i >> 5, n4 = (i & 31) << 2;
            cp_async16(&Bs_[kr*136 + n4], Bp + (size_t)kr*AA + n4);
        }
        cp_commit();
    };

    issue(0); issue(1);
    for (int c = 0; c < NCHUNK; c++) {
        if (c == NCHUNK-1) cp_wait<0>(); else cp_wait<1>();
        __syncthreads();
        if (c + 2 < NCHUNK) issue(c + 2);
        int s = c % 3;
        const float* As_ = sm + s*STGF;
        const float* Bs_ = As_ + 4608;
#pragma unroll
        for (int kk = 0; kk < 4; kk++) {
            uint32_t af[2][4], bf[8][2];
#pragma unroll
            for (int fm = 0; fm < 2; fm++) {
                int m0 = wm*32 + fm*16 + qid;
                af[fm][0] = __float_as_uint(As_[(m0    )*36 + kk*8 + tq    ]);
                af[fm][1] = __float_as_uint(As_[(m0 + 8)*36 + kk*8 + tq    ]);
                af[fm][2] = __float_as_uint(As_[(m0    )*36 + kk*8 + tq + 4]);
                af[fm][3] = __float_as_uint(As_[(m0 + 8)*36 + kk*8 + tq + 4]);
            }
#pragma unroll
            for (int fn = 0; fn < 8; fn++) {
                int nb = wn*64 + fn*8 + qid;
                bf[fn][0] = __float_as_uint(Bs_[(kk*8 + tq    )*136 + nb]);
                bf[fn][1] = __float_as_uint(Bs_[(kk*8 + tq + 4)*136 + nb]);
            }
#pragma unroll
            for (int fm = 0; fm < 2; fm++)
#pragma unroll
                for (int fn = 0; fn < 8; fn++)
                    mma_tf32(acc[fm][fn], af[fm], bf[fn]);
        }
    }

    float part[4] = {0.f, 0.f, 0.f, 0.f};
#pragma unroll
    for (int fm = 0; fm < 2; fm++)
#pragma unroll
        for (int fn = 0; fn < 8; fn++)
#pragma unroll
            for (int r = 0; r < 4; r++) {
                int half = r >> 1, j = r & 1;
                int nl = wn*64 + fn*8 + 2*tq + j;
                part[fm*2 + half] += fast_tanh(acc[fm][fn][r] + has[nl]) * vas[nl];
            }

    float* red = sm;
    __syncthreads();
#pragma unroll
    for (int p = 0; p < 4; p++) {
        int fm = p >> 1, half = p & 1;
        int rl = wm*32 + fm*16 + half*8 + qid;
        red[rl*9 + wn*4 + tq] = part[p];
    }
    __syncthreads();
    if (t < 128) {
        float s = 0.f;
#pragma unroll
        for (int x = 0; x < 8; x++) s += red[t*9 + x];
        g_logitpart[(size_t)(blockIdx.x & 3)*(BZ*LL) + b*LL + l0 + t] = s;
    }
}

// ---------------- vlogits: tf32 MMA, 3-stage ----------------
#define VG_STGF (2304 + 4352)
__global__ __launch_bounds__(256)
void vgemm_mma_kernel(const float* __restrict__ Aee, const float* __restrict__ Wo)
{
    extern __shared__ float sm[];
    int t = threadIdx.x;
    int lane = t & 31, wid = t >> 5;
    int qid = lane >> 2, tq = lane & 3;
    int n0 = blockIdx.x << 7;

    float acc[4][2][4];
#pragma unroll
    for (int i = 0; i < 4; i++)
#pragma unroll
        for (int j = 0; j < 2; j++)
#pragma unroll
            for (int r = 0; r < 4; r++) acc[i][j][r] = 0.f;

    auto issue = [&](int c) {
        float* As_ = sm + (c % 3)*VG_STGF;
        float* Bs_ = As_ + 2304;
#pragma unroll
        for (int r = 0; r < 2; r++) {
            int i = t + 256*r;
            int m = i >> 3, k4 = (i & 7) << 2;
            cp_async16(&As_[m*36 + k4], Aee + (size_t)m*EE + c*32 + k4);
        }
#pragma unroll
        for (int r = 0; r < 4; r++) {
            int i = t + 256*r;
            int kr = i >> 5, n4 = (i & 31) << 2;
            cp_async16(&Bs_[kr*136 + n4], Wo + (size_t)(c*32 + kr)*VV + n0 + n4);
        }
        cp_commit();
    };

    issue(0); issue(1);
    for (int c = 0; c < 8; c++) {
        if (c == 7) cp_wait<0>(); else cp_wait<1>();
        __syncthreads();
        if (c + 2 < 8) issue(c + 2);
        const float* As_ = sm + (c % 3)*VG_STGF;
        const float* Bs_ = As_ + 2304;
#pragma unroll
        for (int kk = 0; kk < 4; kk++) {
            uint32_t af[4][4], bf[2][2];
#pragma unroll
            for (int fm = 0; fm < 4; fm++) {
                int m0 = fm*16 + qid;
                af[fm][0] = __float_as_uint(As_[(m0    )*36 + kk*8 + tq    ]);
                af[fm][1] = __float_as_uint(As_[(m0 + 8)*36 + kk*8 + tq    ]);
                af[fm][2] = __float_as_uint(As_[(m0    )*36 + kk*8 + tq + 4]);
                af[fm][3] = __float_as_uint(As_[(m0 + 8)*36 + kk*8 + tq + 4]);
            }
#pragma unroll
            for (int fn = 0; fn < 2; fn++) {
                int nb = wid*16 + fn*8 + qid;
                bf[fn][0] = __float_as_uint(Bs_[(kk*8 + tq    )*136 + nb]);
                bf[fn][1] = __float_as_uint(Bs_[(kk*8 + tq + 4)*136 + nb]);
            }
#pragma unroll
            for (int fm = 0; fm < 4; fm++)
#pragma unroll
                for (int fn = 0; fn < 2; fn++)
                    mma_tf32(acc[fm][fn], af[fm], bf[fn]);
        }
    }

#pragma unroll
    for (int fm = 0; fm < 4; fm++)
#pragma unroll
        for (int fn = 0; fn < 2; fn++)
#pragma unroll
            for (int r = 0; r < 4; r++) {
                int m = fm*16 + (r >> 1)*8 + qid;
                int n = n0 + wid*16 + fn*8 + 2*tq + (r & 1);
                g_vlogits[(size_t)m*VV + n] = acc[fm][fn][r];
            }
}

// ---------------- Ey: tf32 MMA split-K, grid (2 n-tiles, 125 k-chunks) ----------------
__global__ __launch_bounds__(256)
void ey_mma_kernel(const float* __restrict__ pt, const float* __restrict__ We)
{
    extern __shared__ float sm[];
    int t = threadIdx.x;
    int lane = t & 31, wid = t >> 5;
    int qid = lane >> 2, tq = lane & 3;
    int n0 = blockIdx.x << 7;          // 0 or 128
    int k0 = blockIdx.y << 8;          // chunk * 256

    float acc[4][2][4];
#pragma unroll
    for (int i = 0; i < 4; i++)
#pragma unroll
        for (int j = 0; j < 2; j++)
#pragma unroll
            for (int r = 0; r < 4; r++) acc[i][j][r] = 0.f;

    auto issue = [&](int c) {
        float* As_ = sm + (c % 3)*VG_STGF;
        float* Bs_ = As_ + 2304;
#pragma unroll
        for (int r = 0; r < 2; r++) {
            int i = t + 256*r;
            int m = i >> 3, k4 = (i & 7) << 2;
            cp_async16(&As_[m*36 + k4], pt + (size_t)m*VV + k0 + c*32 + k4);
        }
#pragma unroll
        for (int r = 0; r < 4; r++) {
            int i = t + 256*r;
            int kr = i >> 5, n4 = (i & 31) << 2;
            cp_async16(&Bs_[kr*136 + n4], We + (size_t)(k0 + c*32 + kr)*EE + n0 + n4);
        }
        cp_commit();
    };

    issue(0); issue(1);
    for (int c = 0; c < 8; c++) {
        if (c == 7) cp_wait<0>(); else cp_wait<1>();
        __syncthreads();
        if (c + 2 < 8) issue(c + 2);
        const float* As_ = sm + (c % 3)*VG_STGF;
        const float* Bs_ = As_ + 2304;
#pragma unroll
        for (int kk = 0; kk < 4; kk++) {
            uint32_t af[4][4], bf[2][2];
#pragma unroll
            for (int fm = 0; fm < 4; fm++) {
                int m0 = fm*16 + qid;
                af[fm][0] = __float_as_uint(As_[(m0    )*36 + kk*8 + tq    ]);
                af[fm][1] = __float_as_uint(As_[(m0 + 8)*36 + kk*8 + tq    ]);
                af[fm][2] = __float_as_uint(As_[(m0    )*36 + kk*8 + tq + 4]);
                af[fm][3] = __float_as_uint(As_[(m0 + 8)*36 + kk*8 + tq + 4]);
            }
#pragma unroll
            for (int fn = 0; fn < 2; fn++) {
                int nb = wid*16 + fn*8 + qid;
                bf[fn][0] = __float_as_uint(Bs_[(kk*8 + tq    )*136 + nb]);
                bf[fn][1] = __float_as_uint(Bs_[(kk*8 + tq + 4)*136 + nb]);
            }
#pragma unroll
            for (int fm = 0; fm < 4; fm++)
#pragma unroll
                for (int fn = 0; fn < 2; fn++)
                    mma_tf32(acc[fm][fn], af[fm], bf[fn]);
        }
    }

    float* outp = g_eypart + (size_t)blockIdx.y*(BZ*EE);
#pragma unroll
    for (int fm = 0; fm < 4; fm++)
#pragma unroll
        for (int fn = 0; fn < 2; fn++)
#pragma unroll
            for (int r = 0; r < 4; r++) {
                int m = fm*16 + (r >> 1)*8 + qid;
                int n = n0 + wid*16 + fn*8 + 2*tq + (r & 1);
                outp[m*EE + n] = acc[fm][fn][r];
            }
}

__global__ void ey_reduce_kernel() {
    int i = blockIdx.x * blockDim.x + threadIdx.x;
    if (i >= BZ*EE) return;
    float s = 0.f;
    for (int kc = 0; kc < EY_SPLIT; kc++) s += g_eypart[(size_t)kc*(BZ*EE) + i];
    g_Ey[i] = s;
}

// ---------------- softmax over L (sums 4 n-split partials) ----------------
__global__ void softmaxL_kernel(float* __restrict__ attn) {
    int b = blockIdx.x, t = threadIdx.x;
    __shared__ float sred[256];
    const float* p0 = g_logitpart + 0*(BZ*LL) + b*LL;
    const float* p1 = g_logitpart + 1*(BZ*LL) + b*LL;
    const float* p2 = g_logitpart + 2*(BZ*LL) + b*LL;
    const float* p3 = g_logitpart + 3*(BZ*LL) + b*LL;
    float* lg = g_logit + b*LL;

    float mx = -1e30f;
    for (int l = t; l < LL; l += 256) {
        float v = p0[l] + p1[l] + p2[l] + p3[l];
        lg[l] = v;
        mx = fmaxf(mx, v);
    }
    sred[t] = mx; __syncthreads();
    for (int s = 128; s > 0; s >>= 1) { if (t < s) sred[t] = fmaxf(sred[t], sred[t+s]); __syncthreads(); }
    mx = sred[0]; __syncthreads();
    float sum = 0.f;
    for (int l = t; l < LL; l += 256) sum += __expf(lg[l] - mx);
    sred[t] = sum; __syncthreads();
    for (int s = 128; s > 0; s >>= 1) { if (t < s) sred[t] += sred[t+s]; __syncthreads(); }
    sum = sred[0]; __syncthreads();
    float inv = 1.f / sum;
    for (int l = t; l < LL; l += 256) attn[b*LL + l] = __expf(lg[l] - mx) * inv;
}

// ---------------- context ----------------
__global__ void ctx_part_kernel(const float* __restrict__ feat, const float* __restrict__ attn) {
    int b = blockIdx.x >> 4, lc = blockIdx.x & 15;
    int d = threadIdx.x;
    const float* fb = feat + (size_t)(b*LL + lc*128) * DD;
    const float* ab = attn + b*LL + lc*128;
    float s = 0.f;
#pragma unroll 8
    for (int l = 0; l < 128; l++) s = fmaf(ab[l], fb[(size_t)l*DD + d], s);
    g_ctxpart[lc*(BZ*DD) + b*DD + d] = s;
}
__global__ void ctx_reduce_kernel() {
    int i = blockIdx.x * blockDim.x + threadIdx.x;
    if (i >= BZ*DD) return;
    float s = 0.f;
#pragma unroll
    for (int lc = 0; lc < CTX_SPLIT; lc++) s += g_ctxpart[lc*(BZ*DD) + i];
    g_context[i] = s;
}

// ---------------- softmax over V (smem-cached) ----------------
__global__ void softmaxV_kernel(float* __restrict__ out) {
    extern __shared__ float row[];
    int b = blockIdx.x, t = threadIdx.x;
    __shared__ float sred[1024];
    const float4* lg4 = (const float4*)(g_vlogits + (size_t)b*VV);

    float mx = -1e30f;
    for (int i = t; i < VV/4; i += 1024) {
        float4 v = lg4[i];
        *(float4*)&row[i*4] = v;
        mx = fmaxf(fmaxf(mx, v.x), fmaxf(v.y, fmaxf(v.z, v.w)));
    }
    sred[t] = mx; __syncthreads();
    for (int s = 512; s > 0; s >>= 1) { if (t < s) sred[t] = fmaxf(sred[t], sred[t+s]); __syncthreads(); }
    mx = sred[0]; __syncthreads();

    float sum = 0.f;
    for (int v = t; v < VV; v += 1024) sum += __expf(row[v] - mx);
    sred[t] = sum; __syncthreads();
    for (int s = 512; s > 0; s >>= 1) { if (t < s) sred[t] += sred[t+s]; __syncthreads(); }
    sum = sred[0]; __syncthreads();

    float inv = 1.f / sum;
    float4* o4 = (float4*)(out + (size_t)b*VV);
    for (int i = t; i < VV/4; i += 1024) {
        float4 v = *(float4*)&row[i*4];
        v.x = __expf(v.x - mx) * inv;
        v.y = __expf(v.y - mx) * inv;
        v.z = __expf(v.z - mx) * inv;
        v.w = __expf(v.w - mx) * inv;
        o4[i] = v;
    }
}

// ---------------- launch ----------------
extern "C" void kernel_launch(void* const* d_in, const int* in_sizes, int n_in,
                              void* d_out, int out_size)
{
    const float* prev_target = (const float*)d_in[0];
    const float* prev_hidden = (const float*)d_in[1];
    const float* features    = (const float*)d_in[2];
    const float* Bmat        = (const float*)d_in[3];
    const float* Wa          = (const float*)d_in[4];
    const float* Ua          = (const float*)d_in[5];
    const float* Va          = (const float*)d_in[6];
    const float* Uf          = (const float*)d_in[7];
    const float* Qk          = (const float*)d_in[8];
    const float* We          = (const float*)d_in[9];
    const float* Wccz        = (const float*)d_in[10];
    const float* Wyz         = (const float*)d_in[11];
    const float* Uhz         = (const float*)d_in[12];
    const float* Wyr         = (const float*)d_in[13];
    const float* Uhr         = (const float*)d_in[14];
    const float* Ccr         = (const float*)d_in[15];
    const float* Wyh         = (const float*)d_in[16];
    const float* b_wyh       = (const float*)d_in[17];
    const float* Urh         = (const float*)d_in[18];
    const float* b_urh       = (const float*)d_in[19];
    const float* Wo          = (const float*)d_in[20];
    const float* Wh          = (const float*)d_in[21];
    const float* Wc          = (const float*)d_in[22];

    float* out      = (float*)d_out;
    float* out_ht   = (float*)d_out + HT_OFF;
    float* out_attn = (float*)d_out + ATTN_OFF;

    float* pctx;  cudaGetSymbolAddress((void**)&pctx, g_context);
    float* pEy;   cudaGetSymbolAddress((void**)&pEy, g_Ey);
    float* pht;   cudaGetSymbolAddress((void**)&pht, g_ht);
    float* poute; cudaGetSymbolAddress((void**)&poute, g_oute);

    cudaFuncSetAttribute(attn_mma_kernel, cudaFuncAttributeMaxDynamicSharedMemorySize, SM_TOTF*4);
    cudaFuncSetAttribute(vgemm_mma_kernel, cudaFuncAttributeMaxDynamicSharedMemorySize, 3*VG_STGF*4);
    cudaFuncSetAttribute(ey_mma_kernel, cudaFuncAttributeMaxDynamicSharedMemorySize, 3*VG_STGF*4);
    cudaFuncSetAttribute(softmaxV_kernel, cudaFuncAttributeMaxDynamicSharedMemorySize, VV*4);

    // 1. prep (Qext | Bext | ha)
    prep_all_kernel<<<64 + 16384 + 64, 256>>>(Qk, Uf, Bmat, prev_hidden, Wa);

    // 2. Ey (independent branch, tf32 mma split-K)
    { dim3 g(2, EY_SPLIT); ey_mma_kernel<<<g, 256, 3*VG_STGF*4>>>(prev_target, We); }
    ey_reduce_kernel<<<(BZ*EE + 255)/256, 256>>>();

    // 3. attention logits (R7-exact mainloop)
    attn_mma_kernel<<<BZ*16*4, 256, SM_TOTF*4>>>(features, Ua, Va);

    // 4. softmax over L
    softmaxL_kernel<<<BZ, 256>>>(out_attn);

    // 5. context
    ctx_part_kernel<<<BZ*CTX_SPLIT, 512>>>(features, out_attn);
    ctx_reduce_kernel<<<(BZ*DD + 255)/256, 256>>>();

    // 6. zt | rt | hpart in one launch
    { dim3 g(UU/64, 3); gates3_kernel<<<g, 256>>>(pEy, prev_hidden, pctx,
                                                  Wyz, Uhz, Wccz, Wyr, Uhr, Ccr,
                                                  Wyh, b_wyh, b_urh); }

    // 7. hcand finish + ht
    hcand_ht_kernel<<<UU/64, 256>>>(prev_hidden, Urh, out_ht);

    // 8. oute = Ey + ht@Wh + ctx@Wc
    sgemm3v2_kernel<<<EE/64, 256>>>(pht, Wh, UU,
                                    pctx, Wc, DD, nullptr,
                                    nullptr, nullptr, 0,
                                    nullptr, nullptr, pEy, poute, EE, 0);

    // 9. vlogits = oute @ Wo (tf32 mma, 3-stage)
    vgemm_mma_kernel<<<VV/128, 256, 3*VG_STGF*4>>>(poute, Wo);

    // 10. softmax over V
    softmaxV_kernel<<<BZ, 1024, VV*4>>>(out);
}

// round 15
// speedup vs baseline: 6.2433x; 1.0575x over previous
#include <cuda_runtime.h>
#include <cstdint>

// ---------------- shapes ----------------
#define BZ 64
#define LL 2048
#define DD 512
#define UU 512
#define AA 512
#define KK 64
#define VV 32000
#define EE 256
#define QW 7

#define HT_OFF  (BZ*VV)
#define ATTN_OFF (BZ*VV + BZ*UU)

#define EY_SPLIT 125
#define CTX_SPLIT 16

// ---------------- scratch ----------------
__device__ float g_Bext[BZ*LL*32];
__device__ float g_Qext[32*512];
__device__ float g_ha[BZ*AA];
__device__ float g_logitpart[4*BZ*LL];
__device__ float g_logit[BZ*LL];
__device__ float g_ctxpart[CTX_SPLIT*BZ*DD];
__device__ float g_context[BZ*DD];
__device__ float g_eypart[EY_SPLIT*BZ*EE];
__device__ float g_Ey[BZ*EE];
__device__ float g_zt[BZ*UU];
__device__ float g_rt[BZ*UU];
__device__ float g_hpart[BZ*UU];
__device__ float g_ht[BZ*UU];
__device__ float g_oute[BZ*EE];
__device__ float g_vlogits[BZ*VV];

// ---------------- cp.async helpers ----------------
__device__ __forceinline__ void cp_async16(void* smem, const void* gmem) {
    unsigned sa = (unsigned)__cvta_generic_to_shared(smem);
    asm volatile("cp.async.cg.shared.global [%0], [%1], 16;" :: "r"(sa), "l"(gmem));
}
__device__ __forceinline__ void cp_commit() { asm volatile("cp.async.commit_group;"); }
template<int N> __device__ __forceinline__ void cp_wait() {
    asm volatile("cp.async.wait_group %0;" :: "n"(N));
}

// ---------------- merged prep: Qext | Bext | ha ----------------
__global__ void prep_all_kernel(const float* __restrict__ Qk, const float* __restrict__ Uf,
                                const float* __restrict__ Bm,
                                const float* __restrict__ h,  const float* __restrict__ Wa)
{
    __shared__ float hs[UU];
    int bx = blockIdx.x, t = threadIdx.x;
    if (bx < 64) {
        int i = bx*256 + t;
        int w = i >> 9, a = i & 511;
        float s = 0.f;
        if (w < QW)
            for (int k = 0; k < KK; k++) s = fmaf(Qk[w*KK + k], Uf[k*AA + a], s);
        g_Qext[i] = s;
    } else if (bx < 64 + 16384) {
        int i = (bx - 64)*256 + t;
        int j = i & 31;
        int l = (i >> 5) & (LL-1);
        int b = i >> 16;
        int ls = l + j - 3;
        g_Bext[i] = (j < QW && ls >= 0 && ls < LL) ? Bm[b*LL + ls] : 0.f;
    } else {
        int b = bx - 16448;
        for (int i = t; i < UU; i += 256) hs[i] = h[b*UU + i];
        __syncthreads();
        float a0 = 0.f, a1 = 0.f;
        for (int k = 0; k < UU; k++) {
            float hv = hs[k];
            a0 = fmaf(hv, Wa[k*AA + t],       a0);
            a1 = fmaf(hv, Wa[k*AA + t + 256], a1);
        }
        g_ha[b*AA + t]       = a0;
        g_ha[b*AA + t + 256] = a1;
    }
}

// ---------------- tf32 mma ----------------
__device__ __forceinline__ void mma_tf32(float* c, const uint32_t* a, const uint32_t* b) {
    asm volatile(
        "mma.sync.aligned.m16n8k8.row.col.f32.tf32.tf32.f32 "
        "{%0,%1,%2,%3}, {%4,%5,%6,%7}, {%8,%9}, {%0,%1,%2,%3};"
        : "+f"(c[0]), "+f"(c[1]), "+f"(c[2]), "+f"(c[3])
        : "r"(a[0]), "r"(a[1]), "r"(a[2]), "r"(a[3]), "r"(b[0]), "r"(b[1]));
}
__device__ __forceinline__ float fast_tanh(float x) {
    x = fminf(fmaxf(x, -15.f), 15.f);
    float e = __expf(2.f * x);
    return (e - 1.f) / (e + 1.f);
}

// ---------------- attention logits: R7-exact mainloop, 3-stage, N-split ----------------
#define NCHUNK 17
#define STGF 8960            // As 128x36 + Bs 32x136
#define SM_HAS (3*STGF)
#define SM_VAS (SM_HAS+128)
#define SM_TOTF (SM_VAS+128)

__global__ __launch_bounds__(256, 2)
void attn_mma_kernel(const float* __restrict__ feat,
                     const float* __restrict__ Ua,
                     const float* __restrict__ Va)
{
    extern __shared__ float sm[];
    float* has = sm + SM_HAS;
    float* vas = sm + SM_VAS;

    int t = threadIdx.x;
    int lane = t & 31, wid = t >> 5;
    int wm = wid & 3, wn = wid >> 2;
    int qid = lane >> 2, tq = lane & 3;

    int b  = blockIdx.x >> 6;
    int l0 = ((blockIdx.x >> 2) & 15) << 7;
    int n0 = (blockIdx.x & 3) << 7;

    if (t < 128) { has[t] = g_ha[b*AA + n0 + t]; vas[t] = Va[n0 + t]; }

    const float* fb   = feat   + (size_t)(b*LL + l0) * DD;
    const float* bext = g_Bext + (size_t)(b*LL + l0) * 32;

    float acc[2][8][4];
#pragma unroll
    for (int i = 0; i < 2; i++)
#pragma unroll
        for (int j = 0; j < 8; j++)
#pragma unroll
            for (int r = 0; r < 4; r++) acc[i][j][r] = 0.f;

    auto issue = [&](int c) {
        int s = c % 3;
        float* As_ = sm + s*STGF;
        float* Bs_ = As_ + 4608;
        const float* Ap; int lda; const float* Bp;
        if (c < 16) { Ap = fb + c*32; lda = DD; Bp = Ua + (size_t)c*32*AA + n0; }
        else        { Ap = bext;      lda = 32; Bp = g_Qext + n0; }
#pragma unroll
        for (int r = 0; r < 4; r++) {
            int i = t + 256*r;
            int m = i >> 3, k4 = (i & 7) << 2;
            cp_async16(&As_[m*36 + k4], Ap + (size_t)m*lda + k4);
            int kr = i >> 5, n4 = (i & 31) << 2;
            cp_async16(&Bs_[kr*136 + n4], Bp + (size_t)kr*AA + n4);
        }
        cp_commit();
    };

    issue(0); issue(1);
    for (int c = 0; c < NCHUNK; c++) {
        if (c == NCHUNK-1) cp_wait<0>(); else cp_wait<1>();
        __syncthreads();
        if (c + 2 < NCHUNK) issue(c + 2);
        int s = c % 3;
        const float* As_ = sm + s*STGF;
        const float* Bs_ = As_ + 4608;
#pragma unroll
        for (int kk = 0; kk < 4; kk++) {
            uint32_t af[2][4], bf[8][2];
#pragma unroll
            for (int fm = 0; fm < 2; fm++) {
                int m0 = wm*32 + fm*16 + qid;
                af[fm][0] = __float_as_uint(As_[(m0    )*36 + kk*8 + tq    ]);
                af[fm][1] = __float_as_uint(As_[(m0 + 8)*36 + kk*8 + tq    ]);
                af[fm][2] = __float_as_uint(As_[(m0    )*36 + kk*8 + tq + 4]);
                af[fm][3] = __float_as_uint(As_[(m0 + 8)*36 + kk*8 + tq + 4]);
            }
#pragma unroll
            for (int fn = 0; fn < 8; fn++) {
                int nb = wn*64 + fn*8 + qid;
                bf[fn][0] = __float_as_uint(Bs_[(kk*8 + tq    )*136 + nb]);
                bf[fn][1] = __float_as_uint(Bs_[(kk*8 + tq + 4)*136 + nb]);
            }
#pragma unroll
            for (int fm = 0; fm < 2; fm++)
#pragma unroll
                for (int fn = 0; fn < 8; fn++)
                    mma_tf32(acc[fm][fn], af[fm], bf[fn]);
        }
    }

    float part[4] = {0.f, 0.f, 0.f, 0.f};
#pragma unroll
    for (int fm = 0; fm < 2; fm++)
#pragma unroll
        for (int fn = 0; fn < 8; fn++)
#pragma unroll
            for (int r = 0; r < 4; r++) {
                int half = r >> 1, j = r & 1;
                int nl = wn*64 + fn*8 + 2*tq + j;
                part[fm*2 + half] += fast_tanh(acc[fm][fn][r] + has[nl]) * vas[nl];
            }

    float* red = sm;
    __syncthreads();
#pragma unroll
    for (int p = 0; p < 4; p++) {
        int fm = p >> 1, half = p & 1;
        int rl = wm*32 + fm*16 + half*8 + qid;
        red[rl*9 + wn*4 + tq] = part[p];
    }
    __syncthreads();
    if (t < 128) {
        float s = 0.f;
#pragma unroll
        for (int x = 0; x < 8; x++) s += red[t*9 + x];
        g_logitpart[(size_t)(blockIdx.x & 3)*(BZ*LL) + b*LL + l0 + t] = s;
    }
}

// ---------------- gates3: zt | rt | hpart in one launch, grid (8, 3), fp32 ----------------
__global__ void gates3_kernel(const float* __restrict__ Ey, const float* __restrict__ h,
                              const float* __restrict__ ctx,
                              const float* __restrict__ Wyz, const float* __restrict__ Uhz,
                              const float* __restrict__ Wccz,
                              const float* __restrict__ Wyr, const float* __restrict__ Uhr,
                              const float* __restrict__ Ccr,
                              const float* __restrict__ Wyh,
                              const float* __restrict__ b_wyh, const float* __restrict__ b_urh)
{
    __shared__ float As[64][33];
    __shared__ float Bs[32][64];
    int t = threadIdx.x;
    int tx = t & 15, ty = t >> 4;
    int n0 = blockIdx.x * 64;
    int gate = blockIdx.y;

    const float* Aps[3];
    const float* Bps[3];
    int Ks[3];
    float* C;
    if (gate == 0) {
        Aps[0]=Ey; Bps[0]=Wyz; Ks[0]=EE;
        Aps[1]=h;  Bps[1]=Uhz; Ks[1]=UU;
        Aps[2]=ctx;Bps[2]=Wccz;Ks[2]=DD;
        C = g_zt;
    } else if (gate == 1) {
        Aps[0]=Ey; Bps[0]=Wyr; Ks[0]=EE;
        Aps[1]=h;  Bps[1]=Uhr; Ks[1]=UU;
        Aps[2]=ctx;Bps[2]=Ccr; Ks[2]=DD;
        C = g_rt;
    } else {
        Aps[0]=Ey; Bps[0]=Wyh; Ks[0]=EE;
        Aps[1]=ctx;Bps[1]=Wccz;Ks[1]=DD;
        Aps[2]=nullptr; Bps[2]=nullptr; Ks[2]=0;
        C = g_hpart;
    }

    float acc[4][4];
#pragma unroll
    for (int i = 0; i < 4; i++)
#pragma unroll
        for (int j = 0; j < 4; j++) acc[i][j] = 0.f;

    for (int p = 0; p < 3; p++) {
        const float* A = Aps[p];
        if (A == nullptr) continue;
        const float* Bm = Bps[p];
        int K = Ks[p];
        float ar[8], br[8];
#pragma unroll
        for (int r = 0; r < 8; r++) {
            int e = t + 256*r;
            ar[r] = A[(e >> 5)*K + (e & 31)];
            br[r] = Bm[(size_t)(e >> 6)*UU + n0 + (e & 63)];
        }
        for (int kc = 0; kc < K; kc += 32) {
            __syncthreads();
#pragma unroll
            for (int r = 0; r < 8; r++) {
                int e = t + 256*r;
                As[e >> 5][e & 31] = ar[r];
                Bs[e >> 6][e & 63] = br[r];
            }
            __syncthreads();
            if (kc + 32 < K) {
#pragma unroll
                for (int r = 0; r < 8; r++) {
                    int e = t + 256*r;
                    ar[r] = A[(e >> 5)*K + kc + 32 + (e & 31)];
                    br[r] = Bm[(size_t)(kc + 32 + (e >> 6))*UU + n0 + (e & 63)];
                }
            }
#pragma unroll
            for (int k = 0; k < 32; k++) {
                float a[4];
#pragma unroll
                for (int i = 0; i < 4; i++) a[i] = As[ty*4 + i][k];
                float4 bv = *(const float4*)&Bs[k][tx*4];
                float bj[4] = {bv.x, bv.y, bv.z, bv.w};
#pragma unroll
                for (int i = 0; i < 4; i++)
#pragma unroll
                    for (int j = 0; j < 4; j++) acc[i][j] = fmaf(a[i], bj[j], acc[i][j]);
            }
        }
    }
#pragma unroll
    for (int i = 0; i < 4; i++) {
        int m = ty*4 + i;
#pragma unroll
        for (int j = 0; j < 4; j++) {
            int n = n0 + tx*4 + j;
            float v = acc[i][j];
            if (gate < 2) v = 1.f / (1.f + __expf(-v));
            else          v += b_wyh[n] + b_urh[n];
            C[m*UU + n] = v;
        }
    }
}

// ---------------- hcand finish + ht (fp32): (rt*h)@Urh + hpart, blend ----------------
__global__ void hcand_ht_kernel(const float* __restrict__ h,
                                const float* __restrict__ Urh,
                                float* __restrict__ out_ht)
{
    __shared__ float As[64][33];
    __shared__ float Bs[32][64];
    int t = threadIdx.x;
    int tx = t & 15, ty = t >> 4;
    int n0 = blockIdx.x * 64;

    float acc[4][4];
#pragma unroll
    for (int i = 0; i < 4; i++)
#pragma unroll
        for (int j = 0; j < 4; j++) acc[i][j] = 0.f;

    float ar[8], br[8];
#pragma unroll
    for (int r = 0; r < 8; r++) {
        int e = t + 256*r;
        int m = e >> 5, k = e & 31;
        ar[r] = h[m*UU + k] * g_rt[m*UU + k];
        br[r] = Urh[(size_t)(e >> 6)*UU + n0 + (e & 63)];
    }
    for (int kc = 0; kc < UU; kc += 32) {
        __syncthreads();
#pragma unroll
        for (int r = 0; r < 8; r++) {
            int e = t + 256*r;
            As[e >> 5][e & 31] = ar[r];
            Bs[e >> 6][e & 63] = br[r];
        }
        __syncthreads();
        if (kc + 32 < UU) {
#pragma unroll
            for (int r = 0; r < 8; r++) {
                int e = t + 256*r;
                int m = e >> 5, k = kc + 32 + (e & 31);
                ar[r] = h[m*UU + k] * g_rt[m*UU + k];
                br[r] = Urh[(size_t)(kc + 32 + (e >> 6))*UU + n0 + (e & 63)];
            }
        }
#pragma unroll
        for (int k = 0; k < 32; k++) {
            float a[4];
#pragma unroll
            for (int i = 0; i < 4; i++) a[i] = As[ty*4 + i][k];
            float4 bv = *(const float4*)&Bs[k][tx*4];
            float bj[4] = {bv.x, bv.y, bv.z, bv.w};
#pragma unroll
            for (int i = 0; i < 4; i++)
#pragma unroll
                for (int j = 0; j < 4; j++) acc[i][j] = fmaf(a[i], bj[j], acc[i][j]);
        }
    }
#pragma unroll
    for (int i = 0; i < 4; i++) {
        int m = ty*4 + i;
#pragma unroll
        for (int j = 0; j < 4; j++) {
            int n = n0 + tx*4 + j;
            float hc = tanhf(acc[i][j] + g_hpart[m*UU + n]);
            float z  = g_zt[m*UU + n];
            float v  = (1.f - z) * h[m*UU + n] + z * hc;
            g_ht[m*UU + n] = v;
            out_ht[m*UU + n] = v;
        }
    }
}

// ---------------- generic small tf32 GEMM (oute only): M=64, N=128/CTA, up to 3 segments ----------------
#define VG_STGF (2304 + 4352)
__global__ __launch_bounds__(256)
void small3_mma_kernel(const float* __restrict__ A0, int lda0, const float* __restrict__ B0, int ldb0, int K0,
                       const float* __restrict__ A1, int lda1, const float* __restrict__ B1, int ldb1, int K1,
                       const float* __restrict__ addm,
                       float* __restrict__ C, int ldc)
{
    extern __shared__ float sm[];
    int t = threadIdx.x;
    int lane = t & 31, wid = t >> 5;
    int qid = lane >> 2, tq = lane & 3;
    int n0 = blockIdx.x << 7;

    int c0 = K0 >> 5, c1 = K1 >> 5;
    int nchunk = c0 + c1;

    float acc[4][2][4];
#pragma unroll
    for (int i = 0; i < 4; i++)
#pragma unroll
        for (int j = 0; j < 2; j++)
#pragma unroll
            for (int r = 0; r < 4; r++) acc[i][j][r] = 0.f;

    auto issue = [&](int c) {
        float* As_ = sm + (c % 3)*VG_STGF;
        float* Bs_ = As_ + 2304;
        const float* Ap; int lda; const float* Bp; int ldb;
        int koff;
        if (c < c0) { Ap = A0; lda = lda0; Bp = B0; ldb = ldb0; koff = c*32; }
        else        { Ap = A1; lda = lda1; Bp = B1; ldb = ldb1; koff = (c - c0)*32; }
#pragma unroll
        for (int r = 0; r < 2; r++) {
            int i = t + 256*r;
            int m = i >> 3, k4 = (i & 7) << 2;
            cp_async16(&As_[m*36 + k4], Ap + (size_t)m*lda + koff + k4);
        }
#pragma unroll
        for (int r = 0; r < 4; r++) {
            int i = t + 256*r;
            int kr = i >> 5, n4 = (i & 31) << 2;
            cp_async16(&Bs_[kr*136 + n4], Bp + (size_t)(koff + kr)*ldb + n0 + n4);
        }
        cp_commit();
    };

    issue(0);
    if (nchunk > 1) issue(1);
    for (int c = 0; c < nchunk; c++) {
        if (c == nchunk-1) cp_wait<0>(); else cp_wait<1>();
        __syncthreads();
        if (c + 2 < nchunk) issue(c + 2);
        const float* As_ = sm + (c % 3)*VG_STGF;
        const float* Bs_ = As_ + 2304;
#pragma unroll
        for (int kk = 0; kk < 4; kk++) {
            uint32_t af[4][4], bf[2][2];
#pragma unroll
            for (int fm = 0; fm < 4; fm++) {
                int m0 = fm*16 + qid;
                af[fm][0] = __float_as_uint(As_[(m0    )*36 + kk*8 + tq    ]);
                af[fm][1] = __float_as_uint(As_[(m0 + 8)*36 + kk*8 + tq    ]);
                af[fm][2] = __float_as_uint(As_[(m0    )*36 + kk*8 + tq + 4]);
                af[fm][3] = __float_as_uint(As_[(m0 + 8)*36 + kk*8 + tq + 4]);
            }
#pragma unroll
            for (int fn = 0; fn < 2; fn++) {
                int nb = wid*16 + fn*8 + qid;
                bf[fn][0] = __float_as_uint(Bs_[(kk*8 + tq    )*136 + nb]);
                bf[fn][1] = __float_as_uint(Bs_[(kk*8 + tq + 4)*136 + nb]);
            }
#pragma unroll
            for (int fm = 0; fm < 4; fm++)
#pragma unroll
                for (int fn = 0; fn < 2; fn++)
                    mma_tf32(acc[fm][fn], af[fm], bf[fn]);
        }
        __syncthreads();
    }

#pragma unroll
    for (int fm = 0; fm < 4; fm++)
#pragma unroll
        for (int fn = 0; fn < 2; fn++)
#pragma unroll
            for (int r = 0; r < 4; r++) {
                int m = fm*16 + (r >> 1)*8 + qid;
                int n = n0 + wid*16 + fn*8 + 2*tq + (r & 1);
                C[m*ldc + n] = acc[fm][fn][r] + addm[m*ldc + n];
            }
}

// ---------------- vlogits: tf32 MMA, 3-stage ----------------
__global__ __launch_bounds__(256)
void vgemm_mma_kernel(const float* __restrict__ Aee, const float* __restrict__ Wo)
{
    extern __shared__ float sm[];
    int t = threadIdx.x;
    int lane = t & 31, wid = t >> 5;
    int qid = lane >> 2, tq = lane & 3;
    int n0 = blockIdx.x << 7;

    float acc[4][2][4];
#pragma unroll
    for (int i = 0; i < 4; i++)
#pragma unroll
        for (int j = 0; j < 2; j++)
#pragma unroll
            for (int r = 0; r < 4; r++) acc[i][j][r] = 0.f;

    auto issue = [&](int c) {
        float* As_ = sm + (c % 3)*VG_STGF;
        float* Bs_ = As_ + 2304;
#pragma unroll
        for (int r = 0; r < 2; r++) {
            int i = t + 256*r;
            int m = i >> 3, k4 = (i & 7) << 2;
            cp_async16(&As_[m*36 + k4], Aee + (size_t)m*EE + c*32 + k4);
        }
#pragma unroll
        for (int r = 0; r < 4; r++) {
            int i = t + 256*r;
            int kr = i >> 5, n4 = (i & 31) << 2;
            cp_async16(&Bs_[kr*136 + n4], Wo + (size_t)(c*32 + kr)*VV + n0 + n4);
        }
        cp_commit();
    };

    issue(0); issue(1);
    for (int c = 0; c < 8; c++) {
        if (c == 7) cp_wait<0>(); else cp_wait<1>();
        __syncthreads();
        if (c + 2 < 8) issue(c + 2);
        const float* As_ = sm + (c % 3)*VG_STGF;
        const float* Bs_ = As_ + 2304;
#pragma unroll
        for (int kk = 0; kk < 4; kk++) {
            uint32_t af[4][4], bf[2][2];
#pragma unroll
            for (int fm = 0; fm < 4; fm++) {
                int m0 = fm*16 + qid;
                af[fm][0] = __float_as_uint(As_[(m0    )*36 + kk*8 + tq    ]);
                af[fm][1] = __float_as_uint(As_[(m0 + 8)*36 + kk*8 + tq    ]);
                af[fm][2] = __float_as_uint(As_[(m0    )*36 + kk*8 + tq + 4]);
                af[fm][3] = __float_as_uint(As_[(m0 + 8)*36 + kk*8 + tq + 4]);
            }
#pragma unroll
            for (int fn = 0; fn < 2; fn++) {
                int nb = wid*16 + fn*8 + qid;
                bf[fn][0] = __float_as_uint(Bs_[(kk*8 + tq    )*136 + nb]);
                bf[fn][1] = __float_as_uint(Bs_[(kk*8 + tq + 4)*136 + nb]);
            }
#pragma unroll
            for (int fm = 0; fm < 4; fm++)
#pragma unroll
                for (int fn = 0; fn < 2; fn++)
                    mma_tf32(acc[fm][fn], af[fm], bf[fn]);
        }
    }

#pragma unroll
    for (int fm = 0; fm < 4; fm++)
#pragma unroll
        for (int fn = 0; fn < 2; fn++)
#pragma unroll
            for (int r = 0; r < 4; r++) {
                int m = fm*16 + (r >> 1)*8 + qid;
                int n = n0 + wid*16 + fn*8 + 2*tq + (r & 1);
                g_vlogits[(size_t)m*VV + n] = acc[fm][fn][r];
            }
}

// ---------------- Ey: tf32 MMA split-K, grid (2 n-tiles, 125 k-chunks) ----------------
__global__ __launch_bounds__(256)
void ey_mma_kernel(const float* __restrict__ pt, const float* __restrict__ We)
{
    extern __shared__ float sm[];
    int t = threadIdx.x;
    int lane = t & 31, wid = t >> 5;
    int qid = lane >> 2, tq = lane & 3;
    int n0 = blockIdx.x << 7;
    int k0 = blockIdx.y << 8;

    float acc[4][2][4];
#pragma unroll
    for (int i = 0; i < 4; i++)
#pragma unroll
        for (int j = 0; j < 2; j++)
#pragma unroll
            for (int r = 0; r < 4; r++) acc[i][j][r] = 0.f;

    auto issue = [&](int c) {
        float* As_ = sm + (c % 3)*VG_STGF;
        float* Bs_ = As_ + 2304;
#pragma unroll
        for (int r = 0; r < 2; r++) {
            int i = t + 256*r;
            int m = i >> 3, k4 = (i & 7) << 2;
            cp_async16(&As_[m*36 + k4], pt + (size_t)m*VV + k0 + c*32 + k4);
        }
#pragma unroll
        for (int r = 0; r < 4; r++) {
            int i = t + 256*r;
            int kr = i >> 5, n4 = (i & 31) << 2;
            cp_async16(&Bs_[kr*136 + n4], We + (size_t)(k0 + c*32 + kr)*EE + n0 + n4);
        }
        cp_commit();
    };

    issue(0); issue(1);
    for (int c = 0; c < 8; c++) {
        if (c == 7) cp_wait<0>(); else cp_wait<1>();
        __syncthreads();
        if (c + 2 < 8) issue(c + 2);
        const float* As_ = sm + (c % 3)*VG_STGF;
        const float* Bs_ = As_ + 2304;
#pragma unroll
        for (int kk = 0; kk < 4; kk++) {
            uint32_t af[4][4], bf[2][2];
#pragma unroll
            for (int fm = 0; fm < 4; fm++) {
                int m0 = fm*16 + qid;
                af[fm][0] = __float_as_uint(As_[(m0    )*36 + kk*8 + tq    ]);
                af[fm][1] = __float_as_uint(As_[(m0 + 8)*36 + kk*8 + tq    ]);
                af[fm][2] = __float_as_uint(As_[(m0    )*36 + kk*8 + tq + 4]);
                af[fm][3] = __float_as_uint(As_[(m0 + 8)*36 + kk*8 + tq + 4]);
            }
#pragma unroll
            for (int fn = 0; fn < 2; fn++) {
                int nb = wid*16 + fn*8 + qid;
                bf[fn][0] = __float_as_uint(Bs_[(kk*8 + tq    )*136 + nb]);
                bf[fn][1] = __float_as_uint(Bs_[(kk*8 + tq + 4)*136 + nb]);
            }
#pragma unroll
            for (int fm = 0; fm < 4; fm++)
#pragma unroll
                for (int fn = 0; fn < 2; fn++)
                    mma_tf32(acc[fm][fn], af[fm], bf[fn]);
        }
    }

    float* outp = g_eypart + (size_t)blockIdx.y*(BZ*EE);
#pragma unroll
    for (int fm = 0; fm < 4; fm++)
#pragma unroll
        for (int fn = 0; fn < 2; fn++)
#pragma unroll
            for (int r = 0; r < 4; r++) {
                int m = fm*16 + (r >> 1)*8 + qid;
                int n = n0 + wid*16 + fn*8 + 2*tq + (r & 1);
                outp[m*EE + n] = acc[fm][fn][r];
            }
}

__global__ void ey_reduce_kernel() {
    int i = blockIdx.x * blockDim.x + threadIdx.x;
    if (i >= BZ*EE) return;
    float s = 0.f;
    for (int kc = 0; kc < EY_SPLIT; kc++) s += g_eypart[(size_t)kc*(BZ*EE) + i];
    g_Ey[i] = s;
}

// ---------------- softmax over L (sums 4 n-split partials) ----------------
__global__ void softmaxL_kernel(float* __restrict__ attn) {
    int b = blockIdx.x, t = threadIdx.x;
    __shared__ float sred[256];
    const float* p0 = g_logitpart + 0*(BZ*LL) + b*LL;
    const float* p1 = g_logitpart + 1*(BZ*LL) + b*LL;
    const float* p2 = g_logitpart + 2*(BZ*LL) + b*LL;
    const float* p3 = g_logitpart + 3*(BZ*LL) + b*LL;
    float* lg = g_logit + b*LL;

    float mx = -1e30f;
    for (int l = t; l < LL; l += 256) {
        float v = p0[l] + p1[l] + p2[l] + p3[l];
        lg[l] = v;
        mx = fmaxf(mx, v);
    }
    sred[t] = mx; __syncthreads();
    for (int s = 128; s > 0; s >>= 1) { if (t < s) sred[t] = fmaxf(sred[t], sred[t+s]); __syncthreads(); }
    mx = sred[0]; __syncthreads();
    float sum = 0.f;
    for (int l = t; l < LL; l += 256) sum += __expf(lg[l] - mx);
    sred[t] = sum; __syncthreads();
    for (int s = 128; s > 0; s >>= 1) { if (t < s) sred[t] += sred[t+s]; __syncthreads(); }
    sum = sred[0]; __syncthreads();
    float inv = 1.f / sum;
    for (int l = t; l < LL; l += 256) attn[b*LL + l] = __expf(lg[l] - mx) * inv;
}

// ---------------- context ----------------
__global__ void ctx_part_kernel(const float* __restrict__ feat, const float* __restrict__ attn) {
    int b = blockIdx.x >> 4, lc = blockIdx.x & 15;
    int d = threadIdx.x;
    const float* fb = feat + (size_t)(b*LL + lc*128) * DD;
    const float* ab = attn + b*LL + lc*128;
    float s = 0.f;
#pragma unroll 8
    for (int l = 0; l < 128; l++) s = fmaf(ab[l], fb[(size_t)l*DD + d], s);
    g_ctxpart[lc*(BZ*DD) + b*DD + d] = s;
}
__global__ void ctx_reduce_kernel() {
    int i = blockIdx.x * blockDim.x + threadIdx.x;
    if (i >= BZ*DD) return;
    float s = 0.f;
#pragma unroll
    for (int lc = 0; lc < CTX_SPLIT; lc++) s += g_ctxpart[lc*(BZ*DD) + i];
    g_context[i] = s;
}

// ---------------- softmax over V (smem-cached) ----------------
__global__ void softmaxV_kernel(float* __restrict__ out) {
    extern __shared__ float row[];
    int b = blockIdx.x, t = threadIdx.x;
    __shared__ float sred[1024];
    const float4* lg4 = (const float4*)(g_vlogits + (size_t)b*VV);

    float mx = -1e30f;
    for (int i = t; i < VV/4; i += 1024) {
        float4 v = lg4[i];
        *(float4*)&row[i*4] = v;
        mx = fmaxf(fmaxf(mx, v.x), fmaxf(v.y, fmaxf(v.z, v.w)));
    }
    sred[t] = mx; __syncthreads();
    for (int s = 512; s > 0; s >>= 1) { if (t < s) sred[t] = fmaxf(sred[t], sred[t+s]); __syncthreads(); }
    mx = sred[0]; __syncthreads();

    float sum = 0.f;
    for (int v = t; v < VV; v += 1024) sum += __expf(row[v] - mx);
    sred[t] = sum; __syncthreads();
    for (int s = 512; s > 0; s >>= 1) { if (t < s) sred[t] += sred[t+s]; __syncthreads(); }
    sum = sred[0]; __syncthreads();

    float inv = 1.f / sum;
    float4* o4 = (float4*)(out + (size_t)b*VV);
    for (int i = t; i < VV/4; i += 1024) {
        float4 v = *(float4*)&row[i*4];
        v.x = __expf(v.x - mx) * inv;
        v.y = __expf(v.y - mx) * inv;
        v.z = __expf(v.z - mx) * inv;
        v.w = __expf(v.w - mx) * inv;
        o4[i] = v;
    }
}

// ---------------- launch ----------------
extern "C" void kernel_launch(void* const* d_in, const int* in_sizes, int n_in,
                              void* d_out, int out_size)
{
    const float* prev_target = (const float*)d_in[0];
    const float* prev_hidden = (const float*)d_in[1];
    const float* features    = (const float*)d_in[2];
    const float* Bmat        = (const float*)d_in[3];
    const float* Wa          = (const float*)d_in[4];
    const float* Ua          = (const float*)d_in[5];
    const float* Va          = (const float*)d_in[6];
    const float* Uf          = (const float*)d_in[7];
    const float* Qk          = (const float*)d_in[8];
    const float* We          = (const float*)d_in[9];
    const float* Wccz        = (const float*)d_in[10];
    const float* Wyz         = (const float*)d_in[11];
    const float* Uhz         = (const float*)d_in[12];
    const float* Wyr         = (const float*)d_in[13];
    const float* Uhr         = (const float*)d_in[14];
    const float* Ccr         = (const float*)d_in[15];
    const float* Wyh         = (const float*)d_in[16];
    const float* b_wyh       = (const float*)d_in[17];
    const float* Urh         = (const float*)d_in[18];
    const float* b_urh       = (const float*)d_in[19];
    const float* Wo          = (const float*)d_in[20];
    const float* Wh          = (const float*)d_in[21];
    const float* Wc          = (const float*)d_in[22];

    float* out      = (float*)d_out;
    float* out_ht   = (float*)d_out + HT_OFF;
    float* out_attn = (float*)d_out + ATTN_OFF;

    float* pctx;  cudaGetSymbolAddress((void**)&pctx, g_context);
    float* pEy;   cudaGetSymbolAddress((void**)&pEy, g_Ey);
    float* pht;   cudaGetSymbolAddress((void**)&pht, g_ht);
    float* poute; cudaGetSymbolAddress((void**)&poute, g_oute);

    cudaFuncSetAttribute(attn_mma_kernel, cudaFuncAttributeMaxDynamicSharedMemorySize, SM_TOTF*4);
    cudaFuncSetAttribute(vgemm_mma_kernel, cudaFuncAttributeMaxDynamicSharedMemorySize, 3*VG_STGF*4);
    cudaFuncSetAttribute(ey_mma_kernel, cudaFuncAttributeMaxDynamicSharedMemorySize, 3*VG_STGF*4);
    cudaFuncSetAttribute(small3_mma_kernel, cudaFuncAttributeMaxDynamicSharedMemorySize, 3*VG_STGF*4);
    cudaFuncSetAttribute(softmaxV_kernel, cudaFuncAttributeMaxDynamicSharedMemorySize, VV*4);

    // 1. prep (Qext | Bext | ha)
    prep_all_kernel<<<64 + 16384 + 64, 256>>>(Qk, Uf, Bmat, prev_hidden, Wa);

    // 2. Ey (independent branch, tf32 mma split-K)
    { dim3 g(2, EY_SPLIT); ey_mma_kernel<<<g, 256, 3*VG_STGF*4>>>(prev_target, We); }
    ey_reduce_kernel<<<(BZ*EE + 255)/256, 256>>>();

    // 3. attention logits
    attn_mma_kernel<<<BZ*16*4, 256, SM_TOTF*4>>>(features, Ua, Va);

    // 4. softmax over L
    softmaxL_kernel<<<BZ, 256>>>(out_attn);

    // 5. context
    ctx_part_kernel<<<BZ*CTX_SPLIT, 512>>>(features, out_attn);
    ctx_reduce_kernel<<<(BZ*DD + 255)/256, 256>>>();

    // 6. zt | rt | hpart (fp32, one launch)
    { dim3 g(UU/64, 3); gates3_kernel<<<g, 256>>>(pEy, prev_hidden, pctx,
                                                  Wyz, Uhz, Wccz, Wyr, Uhr, Ccr,
                                                  Wyh, b_wyh, b_urh); }

    // 7. hcand finish + ht (fp32)
    hcand_ht_kernel<<<UU/64, 256>>>(prev_hidden, Urh, out_ht);

    // 8. oute = Ey + ht@Wh + ctx@Wc (tf32 — only affects output 0, measured safe)
    small3_mma_kernel<<<EE/128, 256, 3*VG_STGF*4>>>(
        pht, UU, Wh, EE, UU,
        pctx, DD, Wc, EE, DD,
        pEy, poute, EE);

    // 9. vlogits = oute @ Wo
    vgemm_mma_kernel<<<VV/128, 256, 3*VG_STGF*4>>>(poute, Wo);

    // 10. softmax over V
    softmaxV_kernel<<<BZ, 1024, VV*4>>>(out);
}

// round 16
// speedup vs baseline: 6.4533x; 1.0336x over previous
#include <cuda_runtime.h>
#include <cstdint>

// ---------------- shapes ----------------
#define BZ 64
#define LL 2048
#define DD 512
#define UU 512
#define AA 512
#define KK 64
#define VV 32000
#define EE 256
#define QW 7

#define HT_OFF  (BZ*VV)
#define ATTN_OFF (BZ*VV + BZ*UU)

#define EY_SPLIT 125
#define CTX_SPLIT 16

// ---------------- scratch ----------------
__device__ float g_Qext[32*512];
__device__ float g_ha[BZ*AA];
__device__ float g_logitpart[4*BZ*LL];
__device__ float g_logit[BZ*LL];
__device__ float g_ctxpart[CTX_SPLIT*BZ*DD];
__device__ float g_context[BZ*DD];
__device__ float g_eypart[EY_SPLIT*BZ*EE];
__device__ float g_Ey[BZ*EE];
__device__ float g_zt[BZ*UU];
__device__ float g_rt[BZ*UU];
__device__ float g_hpart[BZ*UU];
__device__ float g_ht[BZ*UU];
__device__ float g_oute[BZ*EE];
__device__ float g_vlogits[BZ*VV];

// ---------------- cp.async helpers ----------------
__device__ __forceinline__ void cp_async16(void* smem, const void* gmem) {
    unsigned sa = (unsigned)__cvta_generic_to_shared(smem);
    asm volatile("cp.async.cg.shared.global [%0], [%1], 16;" :: "r"(sa), "l"(gmem));
}
__device__ __forceinline__ void cp_commit() { asm volatile("cp.async.commit_group;"); }
template<int N> __device__ __forceinline__ void cp_wait() {
    asm volatile("cp.async.wait_group %0;" :: "n"(N));
}

// ---------------- merged prep: Qext | ha (Bext eliminated) ----------------
__global__ void prep_all_kernel(const float* __restrict__ Qk, const float* __restrict__ Uf,
                                const float* __restrict__ h,  const float* __restrict__ Wa)
{
    __shared__ float hs[UU];
    int bx = blockIdx.x, t = threadIdx.x;
    if (bx < 64) {
        int i = bx*256 + t;
        int w = i >> 9, a = i & 511;
        float s = 0.f;
        if (w < QW)
            for (int k = 0; k < KK; k++) s = fmaf(Qk[w*KK + k], Uf[k*AA + a], s);
        g_Qext[i] = s;
    } else {
        int b = bx - 64;
        for (int i = t; i < UU; i += 256) hs[i] = h[b*UU + i];
        __syncthreads();
        float a0 = 0.f, a1 = 0.f;
        for (int k = 0; k < UU; k++) {
            float hv = hs[k];
            a0 = fmaf(hv, Wa[k*AA + t],       a0);
            a1 = fmaf(hv, Wa[k*AA + t + 256], a1);
        }
        g_ha[b*AA + t]       = a0;
        g_ha[b*AA + t + 256] = a1;
    }
}

// ---------------- tf32 mma ----------------
__device__ __forceinline__ void mma_tf32(float* c, const uint32_t* a, const uint32_t* b) {
    asm volatile(
        "mma.sync.aligned.m16n8k8.row.col.f32.tf32.tf32.f32 "
        "{%0,%1,%2,%3}, {%4,%5,%6,%7}, {%8,%9}, {%0,%1,%2,%3};"
        : "+f"(c[0]), "+f"(c[1]), "+f"(c[2]), "+f"(c[3])
        : "r"(a[0]), "r"(a[1]), "r"(a[2]), "r"(a[3]), "r"(b[0]), "r"(b[1]));
}
__device__ __forceinline__ float fast_tanh(float x) {
    x = fminf(fmaxf(x, -15.f), 15.f);
    float e = __expf(2.f * x);
    return (e - 1.f) / (e + 1.f);
}

// ---------------- attention logits: R7-exact mainloop, 3-stage, N-split ----------------
// c==16 conv chunk is built in-smem from Bmat (no g_Bext roundtrip).
#define NCHUNK 17
#define STGF 8960            // As 128x36 + Bs 32x136
#define SM_HAS (3*STGF)
#define SM_VAS (SM_HAS+128)
#define SM_TOTF (SM_VAS+128)

__global__ __launch_bounds__(256, 2)
void attn_mma_kernel(const float* __restrict__ feat,
                     const float* __restrict__ Ua,
                     const float* __restrict__ Va,
                     const float* __restrict__ Bm)
{
    extern __shared__ float sm[];
    float* has = sm + SM_HAS;
    float* vas = sm + SM_VAS;

    int t = threadIdx.x;
    int lane = t & 31, wid = t >> 5;
    int wm = wid & 3, wn = wid >> 2;
    int qid = lane >> 2, tq = lane & 3;

    int b  = blockIdx.x >> 6;
    int l0 = ((blockIdx.x >> 2) & 15) << 7;
    int n0 = (blockIdx.x & 3) << 7;

    if (t < 128) { has[t] = g_ha[b*AA + n0 + t]; vas[t] = Va[n0 + t]; }

    const float* fb = feat + (size_t)(b*LL + l0) * DD;
    const float* Bb = Bm + b*LL;

    float acc[2][8][4];
#pragma unroll
    for (int i = 0; i < 2; i++)
#pragma unroll
        for (int j = 0; j < 8; j++)
#pragma unroll
            for (int r = 0; r < 4; r++) acc[i][j][r] = 0.f;

    auto issue = [&](int c) {
        int s = c % 3;
        float* As_ = sm + s*STGF;
        float* Bs_ = As_ + 4608;
        if (c < 16) {
            const float* Ap = fb + c*32;
            const float* Bp = Ua + (size_t)c*32*AA + n0;
#pragma unroll
            for (int r = 0; r < 4; r++) {
                int i = t + 256*r;
                int m = i >> 3, k4 = (i & 7) << 2;
                cp_async16(&As_[m*36 + k4], Ap + (size_t)m*DD + k4);
                int kr = i >> 5, n4 = (i & 31) << 2;
                cp_async16(&Bs_[kr*136 + n4], Bp + (size_t)kr*AA + n4);
            }
        } else {
            // conv chunk: As[m][k] = (k<7 && 0<=l0+m+k-3<LL) ? Bm[b, l0+m+k-3] : 0
#pragma unroll
            for (int r = 0; r < 16; r++) {
                int i = t + 256*r;
                int m = i >> 5, k = i & 31;
                float v = 0.f;
                if (k < QW) {
                    int ls = l0 + m + k - 3;
                    if (ls >= 0 && ls < LL) v = __ldg(&Bb[ls]);
                }
                As_[m*36 + k] = v;
            }
            const float* Bp = g_Qext + n0;
#pragma unroll
            for (int r = 0; r < 4; r++) {
                int i = t + 256*r;
                int kr = i >> 5, n4 = (i & 31) << 2;
                cp_async16(&Bs_[kr*136 + n4], Bp + (size_t)kr*AA + n4);
            }
        }
        cp_commit();
    };

    issue(0); issue(1);
    for (int c = 0; c < NCHUNK; c++) {
        if (c == NCHUNK-1) cp_wait<0>(); else cp_wait<1>();
        __syncthreads();
        if (c + 2 < NCHUNK) issue(c + 2);
        int s = c % 3;
        const float* As_ = sm + s*STGF;
        const float* Bs_ = As_ + 4608;
#pragma unroll
        for (int kk = 0; kk < 4; kk++) {
            uint32_t af[2][4], bf[8][2];
#pragma unroll
            for (int fm = 0; fm < 2; fm++) {
                int m0 = wm*32 + fm*16 + qid;
                af[fm][0] = __float_as_uint(As_[(m0    )*36 + kk*8 + tq    ]);
                af[fm][1] = __float_as_uint(As_[(m0 + 8)*36 + kk*8 + tq    ]);
                af[fm][2] = __float_as_uint(As_[(m0    )*36 + kk*8 + tq + 4]);
                af[fm][3] = __float_as_uint(As_[(m0 + 8)*36 + kk*8 + tq + 4]);
            }
#pragma unroll
            for (int fn = 0; fn < 8; fn++) {
                int nb = wn*64 + fn*8 + qid;
                bf[fn][0] = __float_as_uint(Bs_[(kk*8 + tq    )*136 + nb]);
                bf[fn][1] = __float_as_uint(Bs_[(kk*8 + tq + 4)*136 + nb]);
            }
#pragma unroll
            for (int fm = 0; fm < 2; fm++)
#pragma unroll
                for (int fn = 0; fn < 8; fn++)
                    mma_tf32(acc[fm][fn], af[fm], bf[fn]);
        }
    }

    float part[4] = {0.f, 0.f, 0.f, 0.f};
#pragma unroll
    for (int fm = 0; fm < 2; fm++)
#pragma unroll
        for (int fn = 0; fn < 8; fn++)
#pragma unroll
            for (int r = 0; r < 4; r++) {
                int half = r >> 1, j = r & 1;
                int nl = wn*64 + fn*8 + 2*tq + j;
                part[fm*2 + half] += fast_tanh(acc[fm][fn][r] + has[nl]) * vas[nl];
            }

    float* red = sm;
    __syncthreads();
#pragma unroll
    for (int p = 0; p < 4; p++) {
        int fm = p >> 1, half = p & 1;
        int rl = wm*32 + fm*16 + half*8 + qid;
        red[rl*9 + wn*4 + tq] = part[p];
    }
    __syncthreads();
    if (t < 128) {
        float s = 0.f;
#pragma unroll
        for (int x = 0; x < 8; x++) s += red[t*9 + x];
        g_logitpart[(size_t)(blockIdx.x & 3)*(BZ*LL) + b*LL + l0 + t] = s;
    }
}

// ---------------- gates3: zt | rt | hpart in one launch, grid (8, 3), fp32 ----------------
__global__ void gates3_kernel(const float* __restrict__ Ey, const float* __restrict__ h,
                              const float* __restrict__ ctx,
                              const float* __restrict__ Wyz, const float* __restrict__ Uhz,
                              const float* __restrict__ Wccz,
                              const float* __restrict__ Wyr, const float* __restrict__ Uhr,
                              const float* __restrict__ Ccr,
                              const float* __restrict__ Wyh,
                              const float* __restrict__ b_wyh, const float* __restrict__ b_urh)
{
    __shared__ float As[64][33];
    __shared__ float Bs[32][64];
    int t = threadIdx.x;
    int tx = t & 15, ty = t >> 4;
    int n0 = blockIdx.x * 64;
    int gate = blockIdx.y;

    const float* Aps[3];
    const float* Bps[3];
    int Ks[3];
    float* C;
    if (gate == 0) {
        Aps[0]=Ey; Bps[0]=Wyz; Ks[0]=EE;
        Aps[1]=h;  Bps[1]=Uhz; Ks[1]=UU;
        Aps[2]=ctx;Bps[2]=Wccz;Ks[2]=DD;
        C = g_zt;
    } else if (gate == 1) {
        Aps[0]=Ey; Bps[0]=Wyr; Ks[0]=EE;
        Aps[1]=h;  Bps[1]=Uhr; Ks[1]=UU;
        Aps[2]=ctx;Bps[2]=Ccr; Ks[2]=DD;
        C = g_rt;
    } else {
        Aps[0]=Ey; Bps[0]=Wyh; Ks[0]=EE;
        Aps[1]=ctx;Bps[1]=Wccz;Ks[1]=DD;
        Aps[2]=nullptr; Bps[2]=nullptr; Ks[2]=0;
        C = g_hpart;
    }

    float acc[4][4];
#pragma unroll
    for (int i = 0; i < 4; i++)
#pragma unroll
        for (int j = 0; j < 4; j++) acc[i][j] = 0.f;

    for (int p = 0; p < 3; p++) {
        const float* A = Aps[p];
        if (A == nullptr) continue;
        const float* Bm = Bps[p];
        int K = Ks[p];
        float ar[8], br[8];
#pragma unroll
        for (int r = 0; r < 8; r++) {
            int e = t + 256*r;
            ar[r] = A[(e >> 5)*K + (e & 31)];
            br[r] = Bm[(size_t)(e >> 6)*UU + n0 + (e & 63)];
        }
        for (int kc = 0; kc < K; kc += 32) {
            __syncthreads();
#pragma unroll
            for (int r = 0; r < 8; r++) {
                int e = t + 256*r;
                As[e >> 5][e & 31] = ar[r];
                Bs[e >> 6][e & 63] = br[r];
            }
            __syncthreads();
            if (kc + 32 < K) {
#pragma unroll
                for (int r = 0; r < 8; r++) {
                    int e = t + 256*r;
                    ar[r] = A[(e >> 5)*K + kc + 32 + (e & 31)];
                    br[r] = Bm[(size_t)(kc + 32 + (e >> 6))*UU + n0 + (e & 63)];
                }
            }
#pragma unroll
            for (int k = 0; k < 32; k++) {
                float a[4];
#pragma unroll
                for (int i = 0; i < 4; i++) a[i] = As[ty*4 + i][k];
                float4 bv = *(const float4*)&Bs[k][tx*4];
                float bj[4] = {bv.x, bv.y, bv.z, bv.w};
#pragma unroll
                for (int i = 0; i < 4; i++)
#pragma unroll
                    for (int j = 0; j < 4; j++) acc[i][j] = fmaf(a[i], bj[j], acc[i][j]);
            }
        }
    }
#pragma unroll
    for (int i = 0; i < 4; i++) {
        int m = ty*4 + i;
#pragma unroll
        for (int j = 0; j < 4; j++) {
            int n = n0 + tx*4 + j;
            float v = acc[i][j];
            if (gate < 2) v = 1.f / (1.f + __expf(-v));
            else          v += b_wyh[n] + b_urh[n];
            C[m*UU + n] = v;
        }
    }
}

// ---------------- hcand finish + ht (fp32): (rt*h)@Urh + hpart, blend ----------------
__global__ void hcand_ht_kernel(const float* __restrict__ h,
                                const float* __restrict__ Urh,
                                float* __restrict__ out_ht)
{
    __shared__ float As[64][33];
    __shared__ float Bs[32][64];
    int t = threadIdx.x;
    int tx = t & 15, ty = t >> 4;
    int n0 = blockIdx.x * 64;

    float acc[4][4];
#pragma unroll
    for (int i = 0; i < 4; i++)
#pragma unroll
        for (int j = 0; j < 4; j++) acc[i][j] = 0.f;

    float ar[8], br[8];
#pragma unroll
    for (int r = 0; r < 8; r++) {
        int e = t + 256*r;
        int m = e >> 5, k = e & 31;
        ar[r] = h[m*UU + k] * g_rt[m*UU + k];
        br[r] = Urh[(size_t)(e >> 6)*UU + n0 + (e & 63)];
    }
    for (int kc = 0; kc < UU; kc += 32) {
        __syncthreads();
#pragma unroll
        for (int r = 0; r < 8; r++) {
            int e = t + 256*r;
            As[e >> 5][e & 31] = ar[r];
            Bs[e >> 6][e & 63] = br[r];
        }
        __syncthreads();
        if (kc + 32 < UU) {
#pragma unroll
            for (int r = 0; r < 8; r++) {
                int e = t + 256*r;
                int m = e >> 5, k = kc + 32 + (e & 31);
                ar[r] = h[m*UU + k] * g_rt[m*UU + k];
                br[r] = Urh[(size_t)(kc + 32 + (e >> 6))*UU + n0 + (e & 63)];
            }
        }
#pragma unroll
        for (int k = 0; k < 32; k++) {
            float a[4];
#pragma unroll
            for (int i = 0; i < 4; i++) a[i] = As[ty*4 + i][k];
            float4 bv = *(const float4*)&Bs[k][tx*4];
            float bj[4] = {bv.x, bv.y, bv.z, bv.w};
#pragma unroll
            for (int i = 0; i < 4; i++)
#pragma unroll
                for (int j = 0; j < 4; j++) acc[i][j] = fmaf(a[i], bj[j], acc[i][j]);
        }
    }
#pragma unroll
    for (int i = 0; i < 4; i++) {
        int m = ty*4 + i;
#pragma unroll
        for (int j = 0; j < 4; j++) {
            int n = n0 + tx*4 + j;
            float hc = tanhf(acc[i][j] + g_hpart[m*UU + n]);
            float z  = g_zt[m*UU + n];
            float v  = (1.f - z) * h[m*UU + n] + z * hc;
            g_ht[m*UU + n] = v;
            out_ht[m*UU + n] = v;
        }
    }
}

// ---------------- generic small tf32 GEMM (oute only) ----------------
#define VG_STGF (2304 + 4352)
__global__ __launch_bounds__(256)
void small3_mma_kernel(const float* __restrict__ A0, int lda0, const float* __restrict__ B0, int ldb0, int K0,
                       const float* __restrict__ A1, int lda1, const float* __restrict__ B1, int ldb1, int K1,
                       const float* __restrict__ addm,
                       float* __restrict__ C, int ldc)
{
    extern __shared__ float sm[];
    int t = threadIdx.x;
    int lane = t & 31, wid = t >> 5;
    int qid = lane >> 2, tq = lane & 3;
    int n0 = blockIdx.x << 7;

    int c0 = K0 >> 5, c1 = K1 >> 5;
    int nchunk = c0 + c1;

    float acc[4][2][4];
#pragma unroll
    for (int i = 0; i < 4; i++)
#pragma unroll
        for (int j = 0; j < 2; j++)
#pragma unroll
            for (int r = 0; r < 4; r++) acc[i][j][r] = 0.f;

    auto issue = [&](int c) {
        float* As_ = sm + (c % 3)*VG_STGF;
        float* Bs_ = As_ + 2304;
        const float* Ap; int lda; const float* Bp; int ldb;
        int koff;
        if (c < c0) { Ap = A0; lda = lda0; Bp = B0; ldb = ldb0; koff = c*32; }
        else        { Ap = A1; lda = lda1; Bp = B1; ldb = ldb1; koff = (c - c0)*32; }
#pragma unroll
        for (int r = 0; r < 2; r++) {
            int i = t + 256*r;
            int m = i >> 3, k4 = (i & 7) << 2;
            cp_async16(&As_[m*36 + k4], Ap + (size_t)m*lda + koff + k4);
        }
#pragma unroll
        for (int r = 0; r < 4; r++) {
            int i = t + 256*r;
            int kr = i >> 5, n4 = (i & 31) << 2;
            cp_async16(&Bs_[kr*136 + n4], Bp + (size_t)(koff + kr)*ldb + n0 + n4);
        }
        cp_commit();
    };

    issue(0);
    if (nchunk > 1) issue(1);
    for (int c = 0; c < nchunk; c++) {
        if (c == nchunk-1) cp_wait<0>(); else cp_wait<1>();
        __syncthreads();
        if (c + 2 < nchunk) issue(c + 2);
        const float* As_ = sm + (c % 3)*VG_STGF;
        const float* Bs_ = As_ + 2304;
#pragma unroll
        for (int kk = 0; kk < 4; kk++) {
            uint32_t af[4][4], bf[2][2];
#pragma unroll
            for (int fm = 0; fm < 4; fm++) {
                int m0 = fm*16 + qid;
                af[fm][0] = __float_as_uint(As_[(m0    )*36 + kk*8 + tq    ]);
                af[fm][1] = __float_as_uint(As_[(m0 + 8)*36 + kk*8 + tq    ]);
                af[fm][2] = __float_as_uint(As_[(m0    )*36 + kk*8 + tq + 4]);
                af[fm][3] = __float_as_uint(As_[(m0 + 8)*36 + kk*8 + tq + 4]);
            }
#pragma unroll
            for (int fn = 0; fn < 2; fn++) {
                int nb = wid*16 + fn*8 + qid;
                bf[fn][0] = __float_as_uint(Bs_[(kk*8 + tq    )*136 + nb]);
                bf[fn][1] = __float_as_uint(Bs_[(kk*8 + tq + 4)*136 + nb]);
            }
#pragma unroll
            for (int fm = 0; fm < 4; fm++)
#pragma unroll
                for (int fn = 0; fn < 2; fn++)
                    mma_tf32(acc[fm][fn], af[fm], bf[fn]);
        }
        __syncthreads();
    }

#pragma unroll
    for (int fm = 0; fm < 4; fm++)
#pragma unroll
        for (int fn = 0; fn < 2; fn++)
#pragma unroll
            for (int r = 0; r < 4; r++) {
                int m = fm*16 + (r >> 1)*8 + qid;
                int n = n0 + wid*16 + fn*8 + 2*tq + (r & 1);
                C[m*ldc + n] = acc[fm][fn][r] + addm[m*ldc + n];
            }
}

// ---------------- vlogits: tf32 MMA, 3-stage ----------------
__global__ __launch_bounds__(256)
void vgemm_mma_kernel(const float* __restrict__ Aee, const float* __restrict__ Wo)
{
    extern __shared__ float sm[];
    int t = threadIdx.x;
    int lane = t & 31, wid = t >> 5;
    int qid = lane >> 2, tq = lane & 3;
    int n0 = blockIdx.x << 7;

    float acc[4][2][4];
#pragma unroll
    for (int i = 0; i < 4; i++)
#pragma unroll
        for (int j = 0; j < 2; j++)
#pragma unroll
            for (int r = 0; r < 4; r++) acc[i][j][r] = 0.f;

    auto issue = [&](int c) {
        float* As_ = sm + (c % 3)*VG_STGF;
        float* Bs_ = As_ + 2304;
#pragma unroll
        for (int r = 0; r < 2; r++) {
            int i = t + 256*r;
            int m = i >> 3, k4 = (i & 7) << 2;
            cp_async16(&As_[m*36 + k4], Aee + (size_t)m*EE + c*32 + k4);
        }
#pragma unroll
        for (int r = 0; r < 4; r++) {
            int i = t + 256*r;
            int kr = i >> 5, n4 = (i & 31) << 2;
            cp_async16(&Bs_[kr*136 + n4], Wo + (size_t)(c*32 + kr)*VV + n0 + n4);
        }
        cp_commit();
    };

    issue(0); issue(1);
    for (int c = 0; c < 8; c++) {
        if (c == 7) cp_wait<0>(); else cp_wait<1>();
        __syncthreads();
        if (c + 2 < 8) issue(c + 2);
        const float* As_ = sm + (c % 3)*VG_STGF;
        const float* Bs_ = As_ + 2304;
#pragma unroll
        for (int kk = 0; kk < 4; kk++) {
            uint32_t af[4][4], bf[2][2];
#pragma unroll
            for (int fm = 0; fm < 4; fm++) {
                int m0 = fm*16 + qid;
                af[fm][0] = __float_as_uint(As_[(m0    )*36 + kk*8 + tq    ]);
                af[fm][1] = __float_as_uint(As_[(m0 + 8)*36 + kk*8 + tq    ]);
                af[fm][2] = __float_as_uint(As_[(m0    )*36 + kk*8 + tq + 4]);
                af[fm][3] = __float_as_uint(As_[(m0 + 8)*36 + kk*8 + tq + 4]);
            }
#pragma unroll
            for (int fn = 0; fn < 2; fn++) {
                int nb = wid*16 + fn*8 + qid;
                bf[fn][0] = __float_as_uint(Bs_[(kk*8 + tq    )*136 + nb]);
                bf[fn][1] = __float_as_uint(Bs_[(kk*8 + tq + 4)*136 + nb]);
            }
#pragma unroll
            for (int fm = 0; fm < 4; fm++)
#pragma unroll
                for (int fn = 0; fn < 2; fn++)
                    mma_tf32(acc[fm][fn], af[fm], bf[fn]);
        }
    }

#pragma unroll
    for (int fm = 0; fm < 4; fm++)
#pragma unroll
        for (int fn = 0; fn < 2; fn++)
#pragma unroll
            for (int r = 0; r < 4; r++) {
                int m = fm*16 + (r >> 1)*8 + qid;
                int n = n0 + wid*16 + fn*8 + 2*tq + (r & 1);
                g_vlogits[(size_t)m*VV + n] = acc[fm][fn][r];
            }
}

// ---------------- Ey: tf32 MMA split-K, grid (2 n-tiles, 125 k-chunks) ----------------
__global__ __launch_bounds__(256)
void ey_mma_kernel(const float* __restrict__ pt, const float* __restrict__ We)
{
    extern __shared__ float sm[];
    int t = threadIdx.x;
    int lane = t & 31, wid = t >> 5;
    int qid = lane >> 2, tq = lane & 3;
    int n0 = blockIdx.x << 7;
    int k0 = blockIdx.y << 8;

    float acc[4][2][4];
#pragma unroll
    for (int i = 0; i < 4; i++)
#pragma unroll
        for (int j = 0; j < 2; j++)
#pragma unroll
            for (int r = 0; r < 4; r++) acc[i][j][r] = 0.f;

    auto issue = [&](int c) {
        float* As_ = sm + (c % 3)*VG_STGF;
        float* Bs_ = As_ + 2304;
#pragma unroll
        for (int r = 0; r < 2; r++) {
            int i = t + 256*r;
            int m = i >> 3, k4 = (i & 7) << 2;
            cp_async16(&As_[m*36 + k4], pt + (size_t)m*VV + k0 + c*32 + k4);
        }
#pragma unroll
        for (int r = 0; r < 4; r++) {
            int i = t + 256*r;
            int kr = i >> 5, n4 = (i & 31) << 2;
            cp_async16(&Bs_[kr*136 + n4], We + (size_t)(k0 + c*32 + kr)*EE + n0 + n4);
        }
        cp_commit();
    };

    issue(0); issue(1);
    for (int c = 0; c < 8; c++) {
        if (c == 7) cp_wait<0>(); else cp_wait<1>();
        __syncthreads();
        if (c + 2 < 8) issue(c + 2);
        const float* As_ = sm + (c % 3)*VG_STGF;
        const float* Bs_ = As_ + 2304;
#pragma unroll
        for (int kk = 0; kk < 4; kk++) {
            uint32_t af[4][4], bf[2][2];
#pragma unroll
            for (int fm = 0; fm < 4; fm++) {
                int m0 = fm*16 + qid;
                af[fm][0] = __float_as_uint(As_[(m0    )*36 + kk*8 + tq    ]);
                af[fm][1] = __float_as_uint(As_[(m0 + 8)*36 + kk*8 + tq    ]);
                af[fm][2] = __float_as_uint(As_[(m0    )*36 + kk*8 + tq + 4]);
                af[fm][3] = __float_as_uint(As_[(m0 + 8)*36 + kk*8 + tq + 4]);
            }
#pragma unroll
            for (int fn = 0; fn < 2; fn++) {
                int nb = wid*16 + fn*8 + qid;
                bf[fn][0] = __float_as_uint(Bs_[(kk*8 + tq    )*136 + nb]);
                bf[fn][1] = __float_as_uint(Bs_[(kk*8 + tq + 4)*136 + nb]);
            }
#pragma unroll
            for (int fm = 0; fm < 4; fm++)
#pragma unroll
                for (int fn = 0; fn < 2; fn++)
                    mma_tf32(acc[fm][fn], af[fm], bf[fn]);
        }
    }

    float* outp = g_eypart + (size_t)blockIdx.y*(BZ*EE);
#pragma unroll
    for (int fm = 0; fm < 4; fm++)
#pragma unroll
        for (int fn = 0; fn < 2; fn++)
#pragma unroll
            for (int r = 0; r < 4; r++) {
                int m = fm*16 + (r >> 1)*8 + qid;
                int n = n0 + wid*16 + fn*8 + 2*tq + (r & 1);
                outp[m*EE + n] = acc[fm][fn][r];
            }
}

__global__ void ey_reduce_kernel() {
    int i = blockIdx.x * blockDim.x + threadIdx.x;
    if (i >= BZ*EE) return;
    float s = 0.f;
    for (int kc = 0; kc < EY_SPLIT; kc++) s += g_eypart[(size_t)kc*(BZ*EE) + i];
    g_Ey[i] = s;
}

// ---------------- softmax over L (sums 4 n-split partials) ----------------
__global__ void softmaxL_kernel(float* __restrict__ attn) {
    int b = blockIdx.x, t = threadIdx.x;
    __shared__ float sred[256];
    const float* p0 = g_logitpart + 0*(BZ*LL) + b*LL;
    const float* p1 = g_logitpart + 1*(BZ*LL) + b*LL;
    const float* p2 = g_logitpart + 2*(BZ*LL) + b*LL;
    const float* p3 = g_logitpart + 3*(BZ*LL) + b*LL;
    float* lg = g_logit + b*LL;

    float mx = -1e30f;
    for (int l = t; l < LL; l += 256) {
        float v = p0[l] + p1[l] + p2[l] + p3[l];
        lg[l] = v;
        mx = fmaxf(mx, v);
    }
    sred[t] = mx; __syncthreads();
    for (int s = 128; s > 0; s >>= 1) { if (t < s) sred[t] = fmaxf(sred[t], sred[t+s]); __syncthreads(); }
    mx = sred[0]; __syncthreads();
    float sum = 0.f;
    for (int l = t; l < LL; l += 256) sum += __expf(lg[l] - mx);
    sred[t] = sum; __syncthreads();
    for (int s = 128; s > 0; s >>= 1) { if (t < s) sred[t] += sred[t+s]; __syncthreads(); }
    sum = sred[0]; __syncthreads();
    float inv = 1.f / sum;
    for (int l = t; l < LL; l += 256) attn[b*LL + l] = __expf(lg[l] - mx) * inv;
}

// ---------------- context (float4 loads) ----------------
__global__ void ctx_part_kernel(const float* __restrict__ feat, const float* __restrict__ attn) {
    int b = blockIdx.x >> 4, lc = blockIdx.x & 15;
    int t = threadIdx.x;           // 128 threads, each owns 4 consecutive d
    int d4 = t << 2;
    const float* fb = feat + (size_t)(b*LL + lc*128) * DD;
    const float* ab = attn + b*LL + lc*128;
    float4 acc = make_float4(0.f, 0.f, 0.f, 0.f);
#pragma unroll 8
    for (int l = 0; l < 128; l++) {
        float w = ab[l];
        float4 f = *(const float4*)&fb[(size_t)l*DD + d4];
        acc.x = fmaf(w, f.x, acc.x);
        acc.y = fmaf(w, f.y, acc.y);
        acc.z = fmaf(w, f.z, acc.z);
        acc.w = fmaf(w, f.w, acc.w);
    }
    *(float4*)&g_ctxpart[lc*(BZ*DD) + b*DD + d4] = acc;
}
__global__ void ctx_reduce_kernel() {
    int i = blockIdx.x * blockDim.x + threadIdx.x;
    if (i >= BZ*DD) return;
    float s = 0.f;
#pragma unroll
    for (int lc = 0; lc < CTX_SPLIT; lc++) s += g_ctxpart[lc*(BZ*DD) + i];
    g_context[i] = s;
}

// ---------------- softmax over V (smem-cached) ----------------
__global__ void softmaxV_kernel(float* __restrict__ out) {
    extern __shared__ float row[];
    int b = blockIdx.x, t = threadIdx.x;
    __shared__ float sred[1024];
    const float4* lg4 = (const float4*)(g_vlogits + (size_t)b*VV);

    float mx = -1e30f;
    for (int i = t; i < VV/4; i += 1024) {
        float4 v = lg4[i];
        *(float4*)&row[i*4] = v;
        mx = fmaxf(fmaxf(mx, v.x), fmaxf(v.y, fmaxf(v.z, v.w)));
    }
    sred[t] = mx; __syncthreads();
    for (int s = 512; s > 0; s >>= 1) { if (t < s) sred[t] = fmaxf(sred[t], sred[t+s]); __syncthreads(); }
    mx = sred[0]; __syncthreads();

    float sum = 0.f;
    for (int v = t; v < VV; v += 1024) sum += __expf(row[v] - mx);
    sred[t] = sum; __syncthreads();
    for (int s = 512; s > 0; s >>= 1) { if (t < s) sred[t] += sred[t+s]; __syncthreads(); }
    sum = sred[0]; __syncthreads();

    float inv = 1.f / sum;
    float4* o4 = (float4*)(out + (size_t)b*VV);
    for (int i = t; i < VV/4; i += 1024) {
        float4 v = *(float4*)&row[i*4];
        v.x = __expf(v.x - mx) * inv;
        v.y = __expf(v.y - mx) * inv;
        v.z = __expf(v.z - mx) * inv;
        v.w = __expf(v.w - mx) * inv;
        o4[i] = v;
    }
}

// ---------------- launch ----------------
extern "C" void kernel_launch(void* const* d_in, const int* in_sizes, int n_in,
                              void* d_out, int out_size)
{
    const float* prev_target = (const float*)d_in[0];
    const float* prev_hidden = (const float*)d_in[1];
    const float* features    = (const float*)d_in[2];
    const float* Bmat        = (const float*)d_in[3];
    const float* Wa          = (const float*)d_in[4];
    const float* Ua          = (const float*)d_in[5];
    const float* Va          = (const float*)d_in[6];
    const float* Uf          = (const float*)d_in[7];
    const float* Qk          = (const float*)d_in[8];
    const float* We          = (const float*)d_in[9];
    const float* Wccz        = (const float*)d_in[10];
    const float* Wyz         = (const float*)d_in[11];
    const float* Uhz         = (const float*)d_in[12];
    const float* Wyr         = (const float*)d_in[13];
    const float* Uhr         = (const float*)d_in[14];
    const float* Ccr         = (const float*)d_in[15];
    const float* Wyh         = (const float*)d_in[16];
    const float* b_wyh       = (const float*)d_in[17];
    const float* Urh         = (const float*)d_in[18];
    const float* b_urh       = (const float*)d_in[19];
    const float* Wo          = (const float*)d_in[20];
    const float* Wh          = (const float*)d_in[21];
    const float* Wc          = (const float*)d_in[22];

    float* out      = (float*)d_out;
    float* out_ht   = (float*)d_out + HT_OFF;
    float* out_attn = (float*)d_out + ATTN_OFF;

    float* pctx;  cudaGetSymbolAddress((void**)&pctx, g_context);
    float* pEy;   cudaGetSymbolAddress((void**)&pEy, g_Ey);
    float* pht;   cudaGetSymbolAddress((void**)&pht, g_ht);
    float* poute; cudaGetSymbolAddress((void**)&poute, g_oute);

    cudaFuncSetAttribute(attn_mma_kernel, cudaFuncAttributeMaxDynamicSharedMemorySize, SM_TOTF*4);
    cudaFuncSetAttribute(vgemm_mma_kernel, cudaFuncAttributeMaxDynamicSharedMemorySize, 3*VG_STGF*4);
    cudaFuncSetAttribute(ey_mma_kernel, cudaFuncAttributeMaxDynamicSharedMemorySize, 3*VG_STGF*4);
    cudaFuncSetAttribute(small3_mma_kernel, cudaFuncAttributeMaxDynamicSharedMemorySize, 3*VG_STGF*4);
    cudaFuncSetAttribute(softmaxV_kernel, cudaFuncAttributeMaxDynamicSharedMemorySize, VV*4);

    // 1. prep (Qext | ha) — Bext eliminated
    prep_all_kernel<<<128, 256>>>(Qk, Uf, prev_hidden, Wa);

    // 2. Ey (independent branch, tf32 mma split-K)
    { dim3 g(2, EY_SPLIT); ey_mma_kernel<<<g, 256, 3*VG_STGF*4>>>(prev_target, We); }
    ey_reduce_kernel<<<(BZ*EE + 255)/256, 256>>>();

    // 3. attention logits (conv chunk built in-smem from Bmat)
    attn_mma_kernel<<<BZ*16*4, 256, SM_TOTF*4>>>(features, Ua, Va, Bmat);

    // 4. softmax over L
    softmaxL_kernel<<<BZ, 256>>>(out_attn);

    // 5. context
    ctx_part_kernel<<<BZ*CTX_SPLIT, 128>>>(features, out_attn);
    ctx_reduce_kernel<<<(BZ*DD + 255)/256, 256>>>();

    // 6. zt | rt | hpart (fp32)
    { dim3 g(UU/64, 3); gates3_kernel<<<g, 256>>>(pEy, prev_hidden, pctx,
                                                  Wyz, Uhz, Wccz, Wyr, Uhr, Ccr,
                                                  Wyh, b_wyh, b_urh); }

    // 7. hcand finish + ht (fp32)
    hcand_ht_kernel<<<UU/64, 256>>>(prev_hidden, Urh, out_ht);

    // 8. oute = Ey + ht@Wh + ctx@Wc (tf32)
    small3_mma_kernel<<<EE/128, 256, 3*VG_STGF*4>>>(
        pht, UU, Wh, EE, UU,
        pctx, DD, Wc, EE, DD,
        pEy, poute, EE);

    // 9. vlogits = oute @ Wo
    vgemm_mma_kernel<<<VV/128, 256, 3*VG_STGF*4>>>(poute, Wo);

    // 10. softmax over V
    softmaxV_kernel<<<BZ, 1024, VV*4>>>(out);
}